// round 1
// baseline (speedup 1.0000x reference)
#include <cuda_runtime.h>
#include <math.h>

// Problem constants
#define Bq   4
#define Sq   2048
#define Hq   512
#define NHq  4
#define HDq  128
#define FFNq 2048
#define Lq   3
#define BSq  (Bq*Sq)        // 8192
#define CHq  128            // retention chunk
#define NCq  (Sq/CHq)       // 16 chunks
#define EPSq 1e-5f

// ---------------- scratch (static __device__, no allocations) ----------------
__device__ float g_Xn[BSq*Hq];
__device__ float g_Q[BSq*Hq];
__device__ float g_K[BSq*Hq];
__device__ float g_V[BSq*Hq];
__device__ float g_G[BSq*Hq];
__device__ float g_Gated[BSq*Hq];
__device__ float g_Y[BSq*Hq];
__device__ float g_Hn[BSq*Hq];
__device__ float g_X[BSq*Hq];
__device__ float g_Yattn[BSq*Hq];          // (b,n,s,d)
__device__ float g_M[Bq*NHq*NCq*HDq*HDq];  // per-chunk decayed KV sums
__device__ float g_St[Bq*NHq*NCq*HDq*HDq]; // per-chunk input states
__device__ float g_Hf[BSq*FFNq];

// gamma_n = 1 - exp(linspace(log(1/32), log(1/512), 4))  (computed in double like numpy)
__device__ __forceinline__ float gamma_of(int n) {
    double lg = -3.4657359027997265 + (double)n * (-0.9241962407465937);
    return (float)(1.0 - exp(lg));
}

__device__ __forceinline__ float blockReduceSum(float v, volatile float* red) {
    int tid = threadIdx.x;
#pragma unroll
    for (int o = 16; o > 0; o >>= 1) v += __shfl_xor_sync(0xffffffffu, v, o);
    if ((tid & 31) == 0) red[tid >> 5] = v;
    __syncthreads();
    if (tid == 0) {
        float s = 0.f;
        int nw = blockDim.x >> 5;
        for (int i = 0; i < nw; i++) s += red[i];
        red[0] = s;
    }
    __syncthreads();
    float r = red[0];
    __syncthreads();
    return r;
}

// ---------------- LayerNorm over H=512, one row per block (256 thr) ----------
__global__ __launch_bounds__(256) void ln_kernel(const float* __restrict__ X,
                                                 const float* __restrict__ w,
                                                 const float* __restrict__ b,
                                                 float* __restrict__ out) {
    long row = blockIdx.x;
    const float* x = X + row * Hq;
    __shared__ float red[8];
    int tid = threadIdx.x;
    float v0 = x[tid], v1 = x[tid + 256];
    float m = blockReduceSum(v0 + v1, red) * (1.f / Hq);
    float d0 = v0 - m, d1 = v1 - m;
    float var = blockReduceSum(d0 * d0 + d1 * d1, red) * (1.f / Hq);
    float inv = rsqrtf(var + EPSq);
    out[row * Hq + tid]       = d0 * inv * w[tid]       + b[tid];
    out[row * Hq + tid + 256] = d1 * inv * w[tid + 256] + b[tid + 256];
}

// ---------------- generic 128x128x16 SGEMM, NN or NT, fused epilogue --------
// C = A(MxK) * B + [bias] -> [gelu] -> + [res];  all dims multiples of 128/16.
__global__ __launch_bounds__(256) void sgemm_kernel(
    const float* __restrict__ A, const float* __restrict__ Bm, float* __restrict__ C,
    int M, int N, int K, int lda, int ldb, int ldc,
    long aStride, long bStride, long cStride,
    const float* __restrict__ bias, const float* __restrict__ res,
    int act, int bT)
{
    __shared__ float As[16][128];
    __shared__ float Bs[16][128];
    int z = blockIdx.z;
    A  += z * aStride;
    Bm += z * bStride;
    C  += z * cStride;
    if (res) res += z * cStride;
    int bm = blockIdx.y * 128, bn = blockIdx.x * 128;
    int tid = threadIdx.x;
    int ty = tid >> 4, tx = tid & 15;
    float acc[8][8];
#pragma unroll
    for (int i = 0; i < 8; i++)
#pragma unroll
        for (int j = 0; j < 8; j++) acc[i][j] = 0.f;
    float af[8], bf[8];

    for (int k0 = 0; k0 < K; k0 += 16) {
        {   // A tile 128x16 -> As[k][m] (transposed)
            int r = tid >> 2, c = (tid & 3) * 4;
#pragma unroll
            for (int i = 0; i < 2; i++) {
                int row = bm + r + i * 64;
                float4 v = *(const float4*)(A + (long)row * lda + k0 + c);
                As[c + 0][r + i * 64] = v.x; As[c + 1][r + i * 64] = v.y;
                As[c + 2][r + i * 64] = v.z; As[c + 3][r + i * 64] = v.w;
            }
        }
        if (!bT) {   // B tile 16x128 row-major
            int r = tid >> 5, c = (tid & 31) * 4;
#pragma unroll
            for (int i = 0; i < 2; i++) {
                int row = k0 + r + i * 8;
                float4 v = *(const float4*)(Bm + (long)row * ldb + bn + c);
                *(float4*)&Bs[r + i * 8][c] = v;
            }
        } else {     // B is NxK row-major: Bs[k][n] = B[n][k]
            int r = tid >> 2, c = (tid & 3) * 4;
#pragma unroll
            for (int i = 0; i < 2; i++) {
                int row = bn + r + i * 64;
                float4 v = *(const float4*)(Bm + (long)row * ldb + k0 + c);
                Bs[c + 0][r + i * 64] = v.x; Bs[c + 1][r + i * 64] = v.y;
                Bs[c + 2][r + i * 64] = v.z; Bs[c + 3][r + i * 64] = v.w;
            }
        }
        __syncthreads();
#pragma unroll
        for (int kk = 0; kk < 16; kk++) {
#pragma unroll
            for (int i = 0; i < 8; i++) af[i] = As[kk][ty * 8 + i];
#pragma unroll
            for (int j = 0; j < 8; j++) bf[j] = Bs[kk][tx * 8 + j];
#pragma unroll
            for (int i = 0; i < 8; i++)
#pragma unroll
                for (int j = 0; j < 8; j++) acc[i][j] += af[i] * bf[j];
        }
        __syncthreads();
    }
#pragma unroll
    for (int i = 0; i < 8; i++) {
        long row = bm + ty * 8 + i;
#pragma unroll
        for (int j = 0; j < 8; j++) {
            int col = bn + tx * 8 + j;
            float v = acc[i][j];
            if (bias) v += bias[col];
            if (act == 1) v = 0.5f * v * (1.f + erff(v * 0.70710678118654752f));
            if (res) v += res[row * ldc + col];
            C[row * ldc + col] = v;
        }
    }
}

// ---------------- xpos rotary (pair-wise), in place ------------------------
__global__ __launch_bounds__(256) void xpos_kernel(float* __restrict__ Qm, int downscale) {
    long idx = (long)blockIdx.x * blockDim.x + threadIdx.x;  // pair index
    if (idx >= (long)BSq * Hq / 2) return;
    int pairInRow = (int)(idx % (Hq / 2));
    long row = idx / (Hq / 2);
    int pos = (int)(row % Sq);
    int i = pairInRow % (HDq / 2);   // 0..63 within head
    float fi = (float)i;
    float sbase = (fi + 0.4f * HDq) / (1.4f * HDq);
    float p = (float)pos;
    float scale = powf(sbase, p * (1.f / 512.f));
    if (downscale) scale = 1.f / scale;
    float invf = powf(10000.f, -fi * (1.f / 64.f));
    float ang = p * invf;
    float c = cosf(ang) * scale, s = sinf(ang) * scale;
    float* ptr = Qm + row * Hq + pairInRow * 2;
    float x0 = ptr[0], x1 = ptr[1];
    ptr[0] = x0 * c - x1 * s;
    ptr[1] = x1 * c + x0 * s;
}

// ---------------- retention pass A: per-chunk decayed KV -------------------
// M_c[d1][d2] = sum_j gamma^{127-j} K[j][d1] V[j][d2]
__global__ __launch_bounds__(256) void chunk_kv_kernel(const float* __restrict__ Kd,
                                                       const float* __restrict__ Vd,
                                                       float* __restrict__ Mout) {
    int bid = blockIdx.x;                 // bn*NC + c
    int bn = bid / NCq, c = bid % NCq;
    int b = bn >> 2, n = bn & 3;
    float gamma = gamma_of(n);
    float lgam = logf(gamma);
    const float* Kb = Kd + ((long)(b * Sq + c * CHq)) * Hq + n * HDq;
    const float* Vb = Vd + ((long)(b * Sq + c * CHq)) * Hq + n * HDq;
    __shared__ float Ks[16][128], Vs[16][128];
    int tid = threadIdx.x;
    int ty = tid >> 4, tx = tid & 15;
    float acc[8][8];
#pragma unroll
    for (int i = 0; i < 8; i++)
#pragma unroll
        for (int j = 0; j < 8; j++) acc[i][j] = 0.f;
    float af[8], bf[8];
    for (int j0 = 0; j0 < CHq; j0 += 16) {
        int r = tid >> 4, cc = (tid & 15) * 8;
        float w = expf((float)(127 - (j0 + r)) * lgam);
        float4 a0 = *(const float4*)(Kb + (long)(j0 + r) * Hq + cc);
        float4 a1 = *(const float4*)(Kb + (long)(j0 + r) * Hq + cc + 4);
        Ks[r][cc + 0] = a0.x * w; Ks[r][cc + 1] = a0.y * w; Ks[r][cc + 2] = a0.z * w; Ks[r][cc + 3] = a0.w * w;
        Ks[r][cc + 4] = a1.x * w; Ks[r][cc + 5] = a1.y * w; Ks[r][cc + 6] = a1.z * w; Ks[r][cc + 7] = a1.w * w;
        float4 v0 = *(const float4*)(Vb + (long)(j0 + r) * Hq + cc);
        float4 v1 = *(const float4*)(Vb + (long)(j0 + r) * Hq + cc + 4);
        *(float4*)&Vs[r][cc] = v0; *(float4*)&Vs[r][cc + 4] = v1;
        __syncthreads();
#pragma unroll
        for (int kk = 0; kk < 16; kk++) {
#pragma unroll
            for (int i = 0; i < 8; i++) af[i] = Ks[kk][ty * 8 + i];
#pragma unroll
            for (int j = 0; j < 8; j++) bf[j] = Vs[kk][tx * 8 + j];
#pragma unroll
            for (int i = 0; i < 8; i++)
#pragma unroll
                for (int j = 0; j < 8; j++) acc[i][j] += af[i] * bf[j];
        }
        __syncthreads();
    }
    float* Mo = Mout + (long)bid * (HDq * HDq);
#pragma unroll
    for (int i = 0; i < 8; i++)
#pragma unroll
        for (int j = 0; j < 8; j++)
            Mo[(ty * 8 + i) * HDq + tx * 8 + j] = acc[i][j];
}

// ---------------- retention pass B: decayed prefix scan over chunks --------
__global__ __launch_bounds__(256) void scan_kernel(const float* __restrict__ M,
                                                   float* __restrict__ St) {
    long idx = (long)blockIdx.x * blockDim.x + threadIdx.x;  // bn*16384 + e
    int bn = (int)(idx >> 14);
    int n = bn & 3;
    float gamma = gamma_of(n);
    float gC = expf(128.f * logf(gamma));
    long e = idx & 16383;
    float s = 0.f;
    for (int c = 0; c < NCq; c++) {
        long off = ((long)bn * NCq + c) * 16384 + e;
        St[off] = s;
        s = s * gC + M[off];
    }
}

// ---------------- retention pass C: chunk output ---------------------------
// Y = (tril-decay(Q K^T)) V + diag(gamma^{j+1}) Q State
__global__ __launch_bounds__(256) void chunk_out_kernel(const float* __restrict__ Qd,
                                                        const float* __restrict__ Kd,
                                                        const float* __restrict__ Vd,
                                                        const float* __restrict__ States,
                                                        float* __restrict__ Yattn) {
    extern __shared__ float sm[];
    float* Asm = sm;                    // 128 x 130 (padded)
    float* S1  = sm + 128 * 130;        // 16 x 128
    float* S2  = S1 + 16 * 128;         // 16 x 128

    int bid = blockIdx.x;
    int bn = bid / NCq, c = bid % NCq;
    int b = bn >> 2, n = bn & 3;
    float gamma = gamma_of(n);
    float lgam = logf(gamma);
    const float* Qb = Qd + ((long)(b * Sq + c * CHq)) * Hq + n * HDq;
    const float* Kb = Kd + ((long)(b * Sq + c * CHq)) * Hq + n * HDq;
    const float* Vb = Vd + ((long)(b * Sq + c * CHq)) * Hq + n * HDq;
    const float* Sb = States + ((long)bn * NCq + c) * 16384;

    int tid = threadIdx.x;
    int ty = tid >> 4, tx = tid & 15;
    float acc[8][8];
    float af[8], bf[8];

    // --- phase 1: A = Q K^T (contract over d), masked+decayed into Asm -----
#pragma unroll
    for (int i = 0; i < 8; i++)
#pragma unroll
        for (int j = 0; j < 8; j++) acc[i][j] = 0.f;
    for (int d0 = 0; d0 < HDq; d0 += 16) {
        int r = tid >> 2, c4 = (tid & 3) * 4;
#pragma unroll
        for (int it = 0; it < 2; it++) {
            int rowj = r + it * 64;
            float4 q4 = *(const float4*)(Qb + (long)rowj * Hq + d0 + c4);
            S1[(c4 + 0) * 128 + rowj] = q4.x; S1[(c4 + 1) * 128 + rowj] = q4.y;
            S1[(c4 + 2) * 128 + rowj] = q4.z; S1[(c4 + 3) * 128 + rowj] = q4.w;
            float4 k4 = *(const float4*)(Kb + (long)rowj * Hq + d0 + c4);
            S2[(c4 + 0) * 128 + rowj] = k4.x; S2[(c4 + 1) * 128 + rowj] = k4.y;
            S2[(c4 + 2) * 128 + rowj] = k4.z; S2[(c4 + 3) * 128 + rowj] = k4.w;
        }
        __syncthreads();
#pragma unroll
        for (int kk = 0; kk < 16; kk++) {
#pragma unroll
            for (int i = 0; i < 8; i++) af[i] = S1[kk * 128 + ty * 8 + i];
#pragma unroll
            for (int j = 0; j < 8; j++) bf[j] = S2[kk * 128 + tx * 8 + j];
#pragma unroll
            for (int i = 0; i < 8; i++)
#pragma unroll
                for (int j = 0; j < 8; j++) acc[i][j] += af[i] * bf[j];
        }
        __syncthreads();
    }
#pragma unroll
    for (int i = 0; i < 8; i++) {
        int jq = ty * 8 + i;
#pragma unroll
        for (int j = 0; j < 8; j++) {
            int jk = tx * 8 + j;
            int diff = jq - jk;
            Asm[jq * 130 + jk] = (diff < 0) ? 0.f : acc[i][j] * expf((float)diff * lgam);
        }
    }
    __syncthreads();

    // --- phase 2: Y = A V  (contract over j') -------------------------------
#pragma unroll
    for (int i = 0; i < 8; i++)
#pragma unroll
        for (int j = 0; j < 8; j++) acc[i][j] = 0.f;
    for (int j0 = 0; j0 < CHq; j0 += 16) {
        int r = tid >> 4, cc = (tid & 15) * 8;
        float4 v0 = *(const float4*)(Vb + (long)(j0 + r) * Hq + cc);
        float4 v1 = *(const float4*)(Vb + (long)(j0 + r) * Hq + cc + 4);
        *(float4*)&S2[r * 128 + cc] = v0; *(float4*)&S2[r * 128 + cc + 4] = v1;
        __syncthreads();
#pragma unroll
        for (int kk = 0; kk < 16; kk++) {
#pragma unroll
            for (int i = 0; i < 8; i++) af[i] = Asm[(ty * 8 + i) * 130 + j0 + kk];
#pragma unroll
            for (int j = 0; j < 8; j++) bf[j] = S2[kk * 128 + tx * 8 + j];
#pragma unroll
            for (int i = 0; i < 8; i++)
#pragma unroll
                for (int j = 0; j < 8; j++) acc[i][j] += af[i] * bf[j];
        }
        __syncthreads();
    }

    // --- phase 3: Y += diag(gamma^{j+1}) Q State (contract over e) ----------
    for (int e0 = 0; e0 < HDq; e0 += 16) {
        int r = tid >> 2, c4 = (tid & 3) * 4;
#pragma unroll
        for (int it = 0; it < 2; it++) {
            int rowj = r + it * 64;
            float w = expf((float)(rowj + 1) * lgam);
            float4 q4 = *(const float4*)(Qb + (long)rowj * Hq + e0 + c4);
            S1[(c4 + 0) * 128 + rowj] = q4.x * w; S1[(c4 + 1) * 128 + rowj] = q4.y * w;
            S1[(c4 + 2) * 128 + rowj] = q4.z * w; S1[(c4 + 3) * 128 + rowj] = q4.w * w;
        }
        {
            int r2 = tid >> 4, cc = (tid & 15) * 8;
            float4 s0 = *(const float4*)(Sb + (long)(e0 + r2) * 128 + cc);
            float4 s1 = *(const float4*)(Sb + (long)(e0 + r2) * 128 + cc + 4);
            *(float4*)&S2[r2 * 128 + cc] = s0; *(float4*)&S2[r2 * 128 + cc + 4] = s1;
        }
        __syncthreads();
#pragma unroll
        for (int kk = 0; kk < 16; kk++) {
#pragma unroll
            for (int i = 0; i < 8; i++) af[i] = S1[kk * 128 + ty * 8 + i];
#pragma unroll
            for (int j = 0; j < 8; j++) bf[j] = S2[kk * 128 + tx * 8 + j];
#pragma unroll
            for (int i = 0; i < 8; i++)
#pragma unroll
                for (int j = 0; j < 8; j++) acc[i][j] += af[i] * bf[j];
        }
        __syncthreads();
    }

    float* Yb = Yattn + ((long)bn * Sq + c * CHq) * HDq;
#pragma unroll
    for (int i = 0; i < 8; i++)
#pragma unroll
        for (int j = 0; j < 8; j++)
            Yb[(ty * 8 + i) * HDq + tx * 8 + j] = acc[i][j];
}

// ---------------- group norm over HD per head + swish gate -----------------
__global__ __launch_bounds__(128) void gnorm_gate_kernel(const float* __restrict__ Yattn,
                                                         const float* __restrict__ G,
                                                         const float* __restrict__ gnw,
                                                         const float* __restrict__ gnb,
                                                         float* __restrict__ out) {
    int bid = blockIdx.x;          // (b*S+s)*NH + n
    int n = bid % NHq;
    long bs = bid / NHq;           // b*S + s
    long b = bs / Sq, s = bs % Sq;
    int d = threadIdx.x;
    __shared__ float red[4];
    float y = Yattn[(((long)(b * NHq + n)) * Sq + s) * HDq + d];
    float m = blockReduceSum(y, red) * (1.f / HDq);
    float dd = y - m;
    float var = blockReduceSum(dd * dd, red) * (1.f / HDq);
    float yn = dd * rsqrtf(var + EPSq) * gnw[n * HDq + d] + gnb[n * HDq + d];
    float g = G[bs * Hq + n * HDq + d];
    float sw = g / (1.f + expf(-g));
    out[bs * Hq + n * HDq + d] = sw * yn;
}

// ---------------- plain copy -----------------------------------------------
__global__ void copy_kernel(const float* __restrict__ src, float* __restrict__ dst, long nTot) {
    long i = (long)blockIdx.x * blockDim.x + threadIdx.x;
    if (i < nTot) dst[i] = src[i];
}

// ============================================================================
extern "C" void kernel_launch(void* const* d_in, const int* in_sizes, int n_in,
                              void* d_out, int out_size) {
    const float* Xin  = (const float*)d_in[0];
    const float* WQ   = (const float*)d_in[1];
    const float* WK   = (const float*)d_in[2];
    const float* WV   = (const float*)d_in[3];
    const float* WG   = (const float*)d_in[4];
    const float* WO   = (const float*)d_in[5];
    const float* gn_w = (const float*)d_in[6];
    const float* gn_b = (const float*)d_in[7];
    const float* ln1w = (const float*)d_in[8];
    const float* ln1b = (const float*)d_in[9];
    const float* ln2w = (const float*)d_in[10];
    const float* ln2b = (const float*)d_in[11];
    const float* fw1  = (const float*)d_in[12];
    const float* fb1  = (const float*)d_in[13];
    const float* fw2  = (const float*)d_in[14];
    const float* fb2  = (const float*)d_in[15];
    float* out = (float*)d_out;

    float *pXn, *pQ, *pK, *pV, *pG, *pGated, *pY, *pHn, *pX, *pYa, *pM, *pSt, *pHf;
    cudaGetSymbolAddress((void**)&pXn, g_Xn);
    cudaGetSymbolAddress((void**)&pQ, g_Q);
    cudaGetSymbolAddress((void**)&pK, g_K);
    cudaGetSymbolAddress((void**)&pV, g_V);
    cudaGetSymbolAddress((void**)&pG, g_G);
    cudaGetSymbolAddress((void**)&pGated, g_Gated);
    cudaGetSymbolAddress((void**)&pY, g_Y);
    cudaGetSymbolAddress((void**)&pHn, g_Hn);
    cudaGetSymbolAddress((void**)&pX, g_X);
    cudaGetSymbolAddress((void**)&pYa, g_Yattn);
    cudaGetSymbolAddress((void**)&pM, g_M);
    cudaGetSymbolAddress((void**)&pSt, g_St);
    cudaGetSymbolAddress((void**)&pHf, g_Hf);

    cudaFuncSetAttribute(chunk_out_kernel, cudaFuncAttributeMaxDynamicSharedMemorySize, 84992);
    const int smemCO = (128 * 130 + 2 * 16 * 128) * 4;  // 82944 B

    const float* cur = Xin;  // residual stream input of current layer
    for (int l = 0; l < Lq; l++) {
        // 1. LN1
        ln_kernel<<<BSq, 256>>>(cur, ln1w + (long)l * Hq, ln1b + (long)l * Hq, pXn);
        // 2. Q,K,V per-head GEMMs (grid.z = heads), G GEMM
        sgemm_kernel<<<dim3(1, BSq / 128, NHq), 256>>>(pXn, WQ + (long)l * NHq * Hq * HDq, pQ,
            BSq, HDq, Hq, Hq, HDq, Hq, 0, (long)Hq * HDq, HDq, nullptr, nullptr, 0, 0);
        sgemm_kernel<<<dim3(1, BSq / 128, NHq), 256>>>(pXn, WK + (long)l * NHq * Hq * HDq, pK,
            BSq, HDq, Hq, Hq, HDq, Hq, 0, (long)Hq * HDq, HDq, nullptr, nullptr, 0, 0);
        sgemm_kernel<<<dim3(1, BSq / 128, NHq), 256>>>(pXn, WV + (long)l * NHq * Hq * HDq, pV,
            BSq, HDq, Hq, Hq, HDq, Hq, 0, (long)Hq * HDq, HDq, nullptr, nullptr, 0, 0);
        sgemm_kernel<<<dim3(Hq / 128, BSq / 128, 1), 256>>>(pXn, WG + (long)l * Hq * Hq, pG,
            BSq, Hq, Hq, Hq, Hq, Hq, 0, 0, 0, nullptr, nullptr, 0, 0);
        // 3. xpos
        long pairs = (long)BSq * Hq / 2;
        xpos_kernel<<<(int)((pairs + 255) / 256), 256>>>(pQ, 0);
        xpos_kernel<<<(int)((pairs + 255) / 256), 256>>>(pK, 1);
        // 4. retention (exact chunked linear form)
        chunk_kv_kernel<<<Bq * NHq * NCq, 256>>>(pK, pV, pM);
        scan_kernel<<<(Bq * NHq * HDq * HDq) / 256, 256>>>(pM, pSt);
        chunk_out_kernel<<<Bq * NHq * NCq, 256, smemCO>>>(pQ, pK, pV, pSt, pYa);
        // 5. group norm + swish gate
        gnorm_gate_kernel<<<BSq * NHq, 128>>>(pYa, pG, gn_w + (long)l * Hq, gn_b + (long)l * Hq, pGated);
        // 6. O-proj + residual
        sgemm_kernel<<<dim3(Hq / 128, BSq / 128, 1), 256>>>(pGated, WO + (long)l * Hq * Hq, pY,
            BSq, Hq, Hq, Hq, Hq, Hq, 0, 0, 0, nullptr, cur, 0, 0);
        // 7. LN2
        ln_kernel<<<BSq, 256>>>(pY, ln2w + (long)l * Hq, ln2b + (long)l * Hq, pHn);
        // 8. FFN1 (+bias, exact gelu)
        sgemm_kernel<<<dim3(FFNq / 128, BSq / 128, 1), 256>>>(pHn, fw1 + (long)l * Hq * FFNq, pHf,
            BSq, FFNq, Hq, Hq, FFNq, FFNq, 0, 0, 0, fb1 + (long)l * FFNq, nullptr, 1, 0);
        // 9. FFN2 (+bias, +residual Y)
        sgemm_kernel<<<dim3(Hq / 128, BSq / 128, 1), 256>>>(pHf, fw2 + (long)l * FFNq * Hq, pX,
            BSq, Hq, FFNq, FFNq, Hq, Hq, 0, 0, 0, fb2 + (long)l * Hq, pY, 0, 0);
        cur = pX;
    }

    // output 0: X
    long nX = (long)BSq * Hq;
    copy_kernel<<<(int)((nX + 255) / 256), 256>>>(pX, out, nX);
    // output 1: per-batch X @ X^T (NT GEMM)
    sgemm_kernel<<<dim3(Sq / 128, Sq / 128, Bq), 256>>>(pX, pX, out + nX,
        Sq, Sq, Hq, Hq, Hq, Sq,
        (long)Sq * Hq, (long)Sq * Hq, (long)Sq * Sq,
        nullptr, nullptr, 0, 1);
}

// round 2
// speedup vs baseline: 1.9829x; 1.9829x over previous
#include <cuda_runtime.h>
#include <math.h>
#include <stdint.h>

// Problem constants
#define Bq   4
#define Sq   2048
#define Hq   512
#define NHq  4
#define HDq  128
#define FFNq 2048
#define Lq   3
#define BSq  (Bq*Sq)        // 8192
#define CHq  128            // retention chunk
#define NCq  (Sq/CHq)       // 16 chunks
#define EPSq 1e-5f

// ---------------- scratch (static __device__, no allocations) ----------------
__device__ float g_Xn[BSq*Hq];
__device__ float g_Q[BSq*Hq];
__device__ float g_K[BSq*Hq];
__device__ float g_V[BSq*Hq];
__device__ float g_G[BSq*Hq];
__device__ float g_Gated[BSq*Hq];
__device__ float g_Y[BSq*Hq];
__device__ float g_Hn[BSq*Hq];
__device__ float g_X[BSq*Hq];
__device__ float g_Yattn[BSq*Hq];          // (b,n,s,d)
__device__ float g_M[Bq*NHq*NCq*HDq*HDq];  // per-chunk decayed KV sums
__device__ float g_St[Bq*NHq*NCq*HDq*HDq]; // per-chunk input states
__device__ float g_Hf[BSq*FFNq];

// gamma_n = 1 - exp(linspace(log(1/32), log(1/512), 4))  (double, matching numpy)
__device__ __forceinline__ float gamma_of(int n) {
    double lg = -3.4657359027997265 + (double)n * (-0.9241962407465937);
    return (float)(1.0 - exp(lg));
}

__device__ __forceinline__ uint32_t f2tf(float x) {
    uint32_t y;
    asm("cvt.rna.tf32.f32 %0, %1;" : "=r"(y) : "f"(x));
    return y;
}

__device__ __forceinline__ float blockReduceSum(float v, volatile float* red) {
    int tid = threadIdx.x;
#pragma unroll
    for (int o = 16; o > 0; o >>= 1) v += __shfl_xor_sync(0xffffffffu, v, o);
    if ((tid & 31) == 0) red[tid >> 5] = v;
    __syncthreads();
    if (tid == 0) {
        float s = 0.f;
        int nw = blockDim.x >> 5;
        for (int i = 0; i < nw; i++) s += red[i];
        red[0] = s;
    }
    __syncthreads();
    float r = red[0];
    __syncthreads();
    return r;
}

// ---------------- LayerNorm over H=512, one row per block (256 thr) ----------
__global__ __launch_bounds__(256) void ln_kernel(const float* __restrict__ X,
                                                 const float* __restrict__ w,
                                                 const float* __restrict__ b,
                                                 float* __restrict__ out) {
    long row = blockIdx.x;
    const float* x = X + row * Hq;
    __shared__ float red[8];
    int tid = threadIdx.x;
    float v0 = x[tid], v1 = x[tid + 256];
    float m = blockReduceSum(v0 + v1, red) * (1.f / Hq);
    float d0 = v0 - m, d1 = v1 - m;
    float var = blockReduceSum(d0 * d0 + d1 * d1, red) * (1.f / Hq);
    float inv = rsqrtf(var + EPSq);
    out[row * Hq + tid]       = d0 * inv * w[tid]       + b[tid];
    out[row * Hq + tid + 256] = d1 * inv * w[tid + 256] + b[tid + 256];
}

// =============== tensor-core (tf32 mma.sync) 128x128x16 GEMM ===============
// C = A(MxK) * B + [bias] -> [gelu] -> + [res]; NN or NT; batched via z.
// 8 warps (2x4), warp tile 64x32, mma m16n8k8, fp32 accumulate.
#define PA 20    // smA pitch: 16 k + 4 pad (conflict-free frag loads)
#define PB 136   // smB pitch: 128 n + 8 pad

__global__ __launch_bounds__(256, 2) void mma_gemm_kernel(
    const float* __restrict__ A, const float* __restrict__ Bm, float* __restrict__ C,
    int M, int N, int K, int lda, int ldb, int ldc,
    long aStride, long bStride, long cStride,
    const float* __restrict__ bias, const float* __restrict__ res,
    int act, int bT)
{
    __shared__ uint32_t smA[128 * PA];
    __shared__ uint32_t smB[16 * PB];
    int z = blockIdx.z;
    A  += z * aStride;
    Bm += z * bStride;
    C  += z * cStride;
    if (res) res += z * cStride;
    int bm = blockIdx.y * 128, bn = blockIdx.x * 128;
    int tid = threadIdx.x;
    int lane = tid & 31, warp = tid >> 5;
    int gid = lane >> 2, tig = lane & 3;
    int wy = warp >> 2, wx = warp & 3;   // 2 x 4 warp grid

    float acc[4][4][4];
#pragma unroll
    for (int i = 0; i < 4; i++)
#pragma unroll
        for (int j = 0; j < 4; j++)
#pragma unroll
            for (int k = 0; k < 4; k++) acc[i][j][k] = 0.f;

    // global load coords
    int ar = tid >> 1, ac = (tid & 1) * 8;     // A: 128 rows x 16 cols
    int br = tid >> 4, bc = (tid & 15) * 8;    // B NN: 16 rows x 128 cols

    uint32_t ra[8], rb[8];

    // ---- prefetch tile 0 ----
    {
        const float* ap = A + (long)(bm + ar) * lda + ac;
        float4 a0 = *(const float4*)(ap);
        float4 a1 = *(const float4*)(ap + 4);
        ra[0]=f2tf(a0.x); ra[1]=f2tf(a0.y); ra[2]=f2tf(a0.z); ra[3]=f2tf(a0.w);
        ra[4]=f2tf(a1.x); ra[5]=f2tf(a1.y); ra[6]=f2tf(a1.z); ra[7]=f2tf(a1.w);
        if (!bT) {
            const float* bp = Bm + (long)br * ldb + bn + bc;
            float4 b0 = *(const float4*)(bp);
            float4 b1 = *(const float4*)(bp + 4);
            rb[0]=f2tf(b0.x); rb[1]=f2tf(b0.y); rb[2]=f2tf(b0.z); rb[3]=f2tf(b0.w);
            rb[4]=f2tf(b1.x); rb[5]=f2tf(b1.y); rb[6]=f2tf(b1.z); rb[7]=f2tf(b1.w);
        } else {
            const float* bp = Bm + (long)(bn + ar) * ldb + ac;
            float4 b0 = *(const float4*)(bp);
            float4 b1 = *(const float4*)(bp + 4);
            rb[0]=f2tf(b0.x); rb[1]=f2tf(b0.y); rb[2]=f2tf(b0.z); rb[3]=f2tf(b0.w);
            rb[4]=f2tf(b1.x); rb[5]=f2tf(b1.y); rb[6]=f2tf(b1.z); rb[7]=f2tf(b1.w);
        }
    }
    // store tile 0
    {
#pragma unroll
        for (int i = 0; i < 8; i++) smA[ar * PA + ac + i] = ra[i];
        if (!bT) {
#pragma unroll
            for (int i = 0; i < 8; i++) smB[br * PB + bc + i] = rb[i];
        } else {
#pragma unroll
            for (int i = 0; i < 8; i++) smB[(ac + i) * PB + ar] = rb[i];
        }
    }
    __syncthreads();

    for (int k0 = 16; k0 <= K; k0 += 16) {
        bool more = (k0 < K);
        if (more) {
            const float* ap = A + (long)(bm + ar) * lda + k0 + ac;
            float4 a0 = *(const float4*)(ap);
            float4 a1 = *(const float4*)(ap + 4);
            ra[0]=f2tf(a0.x); ra[1]=f2tf(a0.y); ra[2]=f2tf(a0.z); ra[3]=f2tf(a0.w);
            ra[4]=f2tf(a1.x); ra[5]=f2tf(a1.y); ra[6]=f2tf(a1.z); ra[7]=f2tf(a1.w);
            if (!bT) {
                const float* bp = Bm + (long)(k0 + br) * ldb + bn + bc;
                float4 b0 = *(const float4*)(bp);
                float4 b1 = *(const float4*)(bp + 4);
                rb[0]=f2tf(b0.x); rb[1]=f2tf(b0.y); rb[2]=f2tf(b0.z); rb[3]=f2tf(b0.w);
                rb[4]=f2tf(b1.x); rb[5]=f2tf(b1.y); rb[6]=f2tf(b1.z); rb[7]=f2tf(b1.w);
            } else {
                const float* bp = Bm + (long)(bn + ar) * ldb + k0 + ac;
                float4 b0 = *(const float4*)(bp);
                float4 b1 = *(const float4*)(bp + 4);
                rb[0]=f2tf(b0.x); rb[1]=f2tf(b0.y); rb[2]=f2tf(b0.z); rb[3]=f2tf(b0.w);
                rb[4]=f2tf(b1.x); rb[5]=f2tf(b1.y); rb[6]=f2tf(b1.z); rb[7]=f2tf(b1.w);
            }
        }
        // compute current tile from smem
#pragma unroll
        for (int kk = 0; kk < 16; kk += 8) {
            uint32_t af[4][4], bf[4][2];
#pragma unroll
            for (int mi = 0; mi < 4; mi++) {
                int mb = (wy * 64 + mi * 16 + gid) * PA + kk + tig;
                af[mi][0] = smA[mb];
                af[mi][1] = smA[mb + 8 * PA];
                af[mi][2] = smA[mb + 4];
                af[mi][3] = smA[mb + 8 * PA + 4];
            }
#pragma unroll
            for (int ni = 0; ni < 4; ni++) {
                int nb = wx * 32 + ni * 8 + gid;
                bf[ni][0] = smB[(kk + tig) * PB + nb];
                bf[ni][1] = smB[(kk + tig + 4) * PB + nb];
            }
#pragma unroll
            for (int mi = 0; mi < 4; mi++)
#pragma unroll
                for (int ni = 0; ni < 4; ni++) {
                    asm volatile(
                        "mma.sync.aligned.m16n8k8.row.col.f32.tf32.tf32.f32 "
                        "{%0,%1,%2,%3}, {%4,%5,%6,%7}, {%8,%9}, {%0,%1,%2,%3};"
                        : "+f"(acc[mi][ni][0]), "+f"(acc[mi][ni][1]),
                          "+f"(acc[mi][ni][2]), "+f"(acc[mi][ni][3])
                        : "r"(af[mi][0]), "r"(af[mi][1]), "r"(af[mi][2]), "r"(af[mi][3]),
                          "r"(bf[ni][0]), "r"(bf[ni][1]));
                }
        }
        if (more) {
            __syncthreads();
#pragma unroll
            for (int i = 0; i < 8; i++) smA[ar * PA + ac + i] = ra[i];
            if (!bT) {
#pragma unroll
                for (int i = 0; i < 8; i++) smB[br * PB + bc + i] = rb[i];
            } else {
#pragma unroll
                for (int i = 0; i < 8; i++) smB[(ac + i) * PB + ar] = rb[i];
            }
            __syncthreads();
        }
    }

    // epilogue
#pragma unroll
    for (int mi = 0; mi < 4; mi++) {
        long r0 = bm + wy * 64 + mi * 16 + gid;
        long r1 = r0 + 8;
#pragma unroll
        for (int ni = 0; ni < 4; ni++) {
            int c0 = bn + wx * 32 + ni * 8 + tig * 2;
            float v00 = acc[mi][ni][0], v01 = acc[mi][ni][1];
            float v10 = acc[mi][ni][2], v11 = acc[mi][ni][3];
            if (bias) {
                float b0 = bias[c0], b1 = bias[c0 + 1];
                v00 += b0; v01 += b1; v10 += b0; v11 += b1;
            }
            if (act == 1) {
                v00 = 0.5f * v00 * (1.f + erff(v00 * 0.70710678118654752f));
                v01 = 0.5f * v01 * (1.f + erff(v01 * 0.70710678118654752f));
                v10 = 0.5f * v10 * (1.f + erff(v10 * 0.70710678118654752f));
                v11 = 0.5f * v11 * (1.f + erff(v11 * 0.70710678118654752f));
            }
            if (res) {
                v00 += res[r0 * ldc + c0]; v01 += res[r0 * ldc + c0 + 1];
                v10 += res[r1 * ldc + c0]; v11 += res[r1 * ldc + c0 + 1];
            }
            float2 o0 = make_float2(v00, v01);
            float2 o1 = make_float2(v10, v11);
            *(float2*)(C + r0 * ldc + c0) = o0;
            *(float2*)(C + r1 * ldc + c0) = o1;
        }
    }
}

// ---------------- xpos rotary (pair-wise), in place ------------------------
__global__ __launch_bounds__(256) void xpos_kernel(float* __restrict__ Qm, int downscale) {
    long idx = (long)blockIdx.x * blockDim.x + threadIdx.x;  // pair index
    if (idx >= (long)BSq * Hq / 2) return;
    int pairInRow = (int)(idx % (Hq / 2));
    long row = idx / (Hq / 2);
    int pos = (int)(row % Sq);
    int i = pairInRow % (HDq / 2);   // 0..63 within head
    float fi = (float)i;
    float sbase = (fi + 0.4f * HDq) / (1.4f * HDq);
    float p = (float)pos;
    float scale = powf(sbase, p * (1.f / 512.f));
    if (downscale) scale = 1.f / scale;
    float invf = powf(10000.f, -fi * (1.f / 64.f));
    float ang = p * invf;
    float c = cosf(ang) * scale, s = sinf(ang) * scale;
    float* ptr = Qm + row * Hq + pairInRow * 2;
    float x0 = ptr[0], x1 = ptr[1];
    ptr[0] = x0 * c - x1 * s;
    ptr[1] = x1 * c + x0 * s;
}

// ---------------- retention pass A: per-chunk decayed KV -------------------
__global__ __launch_bounds__(256) void chunk_kv_kernel(const float* __restrict__ Kd,
                                                       const float* __restrict__ Vd,
                                                       float* __restrict__ Mout) {
    int bid = blockIdx.x;                 // bn*NC + c
    int bn = bid / NCq, c = bid % NCq;
    int b = bn >> 2, n = bn & 3;
    float gamma = gamma_of(n);
    float lgam = logf(gamma);
    const float* Kb = Kd + ((long)(b * Sq + c * CHq)) * Hq + n * HDq;
    const float* Vb = Vd + ((long)(b * Sq + c * CHq)) * Hq + n * HDq;
    __shared__ float Ks[16][128], Vs[16][128];
    int tid = threadIdx.x;
    int ty = tid >> 4, tx = tid & 15;
    float acc[8][8];
#pragma unroll
    for (int i = 0; i < 8; i++)
#pragma unroll
        for (int j = 0; j < 8; j++) acc[i][j] = 0.f;
    float af[8], bf[8];
    for (int j0 = 0; j0 < CHq; j0 += 16) {
        int r = tid >> 4, cc = (tid & 15) * 8;
        float w = expf((float)(127 - (j0 + r)) * lgam);
        float4 a0 = *(const float4*)(Kb + (long)(j0 + r) * Hq + cc);
        float4 a1 = *(const float4*)(Kb + (long)(j0 + r) * Hq + cc + 4);
        Ks[r][cc + 0] = a0.x * w; Ks[r][cc + 1] = a0.y * w; Ks[r][cc + 2] = a0.z * w; Ks[r][cc + 3] = a0.w * w;
        Ks[r][cc + 4] = a1.x * w; Ks[r][cc + 5] = a1.y * w; Ks[r][cc + 6] = a1.z * w; Ks[r][cc + 7] = a1.w * w;
        float4 v0 = *(const float4*)(Vb + (long)(j0 + r) * Hq + cc);
        float4 v1 = *(const float4*)(Vb + (long)(j0 + r) * Hq + cc + 4);
        *(float4*)&Vs[r][cc] = v0; *(float4*)&Vs[r][cc + 4] = v1;
        __syncthreads();
#pragma unroll
        for (int kk = 0; kk < 16; kk++) {
#pragma unroll
            for (int i = 0; i < 8; i++) af[i] = Ks[kk][ty * 8 + i];
#pragma unroll
            for (int j = 0; j < 8; j++) bf[j] = Vs[kk][tx * 8 + j];
#pragma unroll
            for (int i = 0; i < 8; i++)
#pragma unroll
                for (int j = 0; j < 8; j++) acc[i][j] += af[i] * bf[j];
        }
        __syncthreads();
    }
    float* Mo = Mout + (long)bid * (HDq * HDq);
#pragma unroll
    for (int i = 0; i < 8; i++)
#pragma unroll
        for (int j = 0; j < 8; j++)
            Mo[(ty * 8 + i) * HDq + tx * 8 + j] = acc[i][j];
}

// ---------------- retention pass B: decayed prefix scan over chunks --------
__global__ __launch_bounds__(256) void scan_kernel(const float* __restrict__ M,
                                                   float* __restrict__ St) {
    long idx = (long)blockIdx.x * blockDim.x + threadIdx.x;  // bn*16384 + e
    int bn = (int)(idx >> 14);
    int n = bn & 3;
    float gamma = gamma_of(n);
    float gC = expf(128.f * logf(gamma));
    long e = idx & 16383;
    float s = 0.f;
    for (int c = 0; c < NCq; c++) {
        long off = ((long)bn * NCq + c) * 16384 + e;
        St[off] = s;
        s = s * gC + M[off];
    }
}

// ---------------- retention pass C: chunk output ---------------------------
__global__ __launch_bounds__(256) void chunk_out_kernel(const float* __restrict__ Qd,
                                                        const float* __restrict__ Kd,
                                                        const float* __restrict__ Vd,
                                                        const float* __restrict__ States,
                                                        float* __restrict__ Yattn) {
    extern __shared__ float sm[];
    float* Asm = sm;                    // 128 x 130 (padded)
    float* S1  = sm + 128 * 130;        // 16 x 128
    float* S2  = S1 + 16 * 128;         // 16 x 128

    int bid = blockIdx.x;
    int bn = bid / NCq, c = bid % NCq;
    int b = bn >> 2, n = bn & 3;
    float gamma = gamma_of(n);
    float lgam = logf(gamma);
    const float* Qb = Qd + ((long)(b * Sq + c * CHq)) * Hq + n * HDq;
    const float* Kb = Kd + ((long)(b * Sq + c * CHq)) * Hq + n * HDq;
    const float* Vb = Vd + ((long)(b * Sq + c * CHq)) * Hq + n * HDq;
    const float* Sb = States + ((long)bn * NCq + c) * 16384;

    int tid = threadIdx.x;
    int ty = tid >> 4, tx = tid & 15;
    float acc[8][8];
    float af[8], bf[8];

    // --- phase 1: A = Q K^T, masked+decayed into Asm ------------------------
#pragma unroll
    for (int i = 0; i < 8; i++)
#pragma unroll
        for (int j = 0; j < 8; j++) acc[i][j] = 0.f;
    for (int d0 = 0; d0 < HDq; d0 += 16) {
        int r = tid >> 2, c4 = (tid & 3) * 4;
#pragma unroll
        for (int it = 0; it < 2; it++) {
            int rowj = r + it * 64;
            float4 q4 = *(const float4*)(Qb + (long)rowj * Hq + d0 + c4);
            S1[(c4 + 0) * 128 + rowj] = q4.x; S1[(c4 + 1) * 128 + rowj] = q4.y;
            S1[(c4 + 2) * 128 + rowj] = q4.z; S1[(c4 + 3) * 128 + rowj] = q4.w;
            float4 k4 = *(const float4*)(Kb + (long)rowj * Hq + d0 + c4);
            S2[(c4 + 0) * 128 + rowj] = k4.x; S2[(c4 + 1) * 128 + rowj] = k4.y;
            S2[(c4 + 2) * 128 + rowj] = k4.z; S2[(c4 + 3) * 128 + rowj] = k4.w;
        }
        __syncthreads();
#pragma unroll
        for (int kk = 0; kk < 16; kk++) {
#pragma unroll
            for (int i = 0; i < 8; i++) af[i] = S1[kk * 128 + ty * 8 + i];
#pragma unroll
            for (int j = 0; j < 8; j++) bf[j] = S2[kk * 128 + tx * 8 + j];
#pragma unroll
            for (int i = 0; i < 8; i++)
#pragma unroll
                for (int j = 0; j < 8; j++) acc[i][j] += af[i] * bf[j];
        }
        __syncthreads();
    }
#pragma unroll
    for (int i = 0; i < 8; i++) {
        int jq = ty * 8 + i;
#pragma unroll
        for (int j = 0; j < 8; j++) {
            int jk = tx * 8 + j;
            int diff = jq - jk;
            Asm[jq * 130 + jk] = (diff < 0) ? 0.f : acc[i][j] * expf((float)diff * lgam);
        }
    }
    __syncthreads();

    // --- phase 2: Y = A V ----------------------------------------------------
#pragma unroll
    for (int i = 0; i < 8; i++)
#pragma unroll
        for (int j = 0; j < 8; j++) acc[i][j] = 0.f;
    for (int j0 = 0; j0 < CHq; j0 += 16) {
        int r = tid >> 4, cc = (tid & 15) * 8;
        float4 v0 = *(const float4*)(Vb + (long)(j0 + r) * Hq + cc);
        float4 v1 = *(const float4*)(Vb + (long)(j0 + r) * Hq + cc + 4);
        *(float4*)&S2[r * 128 + cc] = v0; *(float4*)&S2[r * 128 + cc + 4] = v1;
        __syncthreads();
#pragma unroll
        for (int kk = 0; kk < 16; kk++) {
#pragma unroll
            for (int i = 0; i < 8; i++) af[i] = Asm[(ty * 8 + i) * 130 + j0 + kk];
#pragma unroll
            for (int j = 0; j < 8; j++) bf[j] = S2[kk * 128 + tx * 8 + j];
#pragma unroll
            for (int i = 0; i < 8; i++)
#pragma unroll
                for (int j = 0; j < 8; j++) acc[i][j] += af[i] * bf[j];
        }
        __syncthreads();
    }

    // --- phase 3: Y += diag(gamma^{j+1}) Q State -----------------------------
    for (int e0 = 0; e0 < HDq; e0 += 16) {
        int r = tid >> 2, c4 = (tid & 3) * 4;
#pragma unroll
        for (int it = 0; it < 2; it++) {
            int rowj = r + it * 64;
            float w = expf((float)(rowj + 1) * lgam);
            float4 q4 = *(const float4*)(Qb + (long)rowj * Hq + e0 + c4);
            S1[(c4 + 0) * 128 + rowj] = q4.x * w; S1[(c4 + 1) * 128 + rowj] = q4.y * w;
            S1[(c4 + 2) * 128 + rowj] = q4.z * w; S1[(c4 + 3) * 128 + rowj] = q4.w * w;
        }
        {
            int r2 = tid >> 4, cc = (tid & 15) * 8;
            float4 s0 = *(const float4*)(Sb + (long)(e0 + r2) * 128 + cc);
            float4 s1 = *(const float4*)(Sb + (long)(e0 + r2) * 128 + cc + 4);
            *(float4*)&S2[r2 * 128 + cc] = s0; *(float4*)&S2[r2 * 128 + cc + 4] = s1;
        }
        __syncthreads();
#pragma unroll
        for (int kk = 0; kk < 16; kk++) {
#pragma unroll
            for (int i = 0; i < 8; i++) af[i] = S1[kk * 128 + ty * 8 + i];
#pragma unroll
            for (int j = 0; j < 8; j++) bf[j] = S2[kk * 128 + tx * 8 + j];
#pragma unroll
            for (int i = 0; i < 8; i++)
#pragma unroll
                for (int j = 0; j < 8; j++) acc[i][j] += af[i] * bf[j];
        }
        __syncthreads();
    }

    float* Yb = Yattn + ((long)bn * Sq + c * CHq) * HDq;
#pragma unroll
    for (int i = 0; i < 8; i++)
#pragma unroll
        for (int j = 0; j < 8; j++)
            Yb[(ty * 8 + i) * HDq + tx * 8 + j] = acc[i][j];
}

// ---------------- group norm over HD per head + swish gate -----------------
__global__ __launch_bounds__(128) void gnorm_gate_kernel(const float* __restrict__ Yattn,
                                                         const float* __restrict__ G,
                                                         const float* __restrict__ gnw,
                                                         const float* __restrict__ gnb,
                                                         float* __restrict__ out) {
    int bid = blockIdx.x;          // (b*S+s)*NH + n
    int n = bid % NHq;
    long bs = bid / NHq;           // b*S + s
    long b = bs / Sq, s = bs % Sq;
    int d = threadIdx.x;
    __shared__ float red[4];
    float y = Yattn[(((long)(b * NHq + n)) * Sq + s) * HDq + d];
    float m = blockReduceSum(y, red) * (1.f / HDq);
    float dd = y - m;
    float var = blockReduceSum(dd * dd, red) * (1.f / HDq);
    float yn = dd * rsqrtf(var + EPSq) * gnw[n * HDq + d] + gnb[n * HDq + d];
    float g = G[bs * Hq + n * HDq + d];
    float sw = g / (1.f + expf(-g));
    out[bs * Hq + n * HDq + d] = sw * yn;
}

// ---------------- plain copy -----------------------------------------------
__global__ void copy_kernel(const float* __restrict__ src, float* __restrict__ dst, long nTot) {
    long i = (long)blockIdx.x * blockDim.x + threadIdx.x;
    if (i < nTot) dst[i] = src[i];
}

// ============================================================================
extern "C" void kernel_launch(void* const* d_in, const int* in_sizes, int n_in,
                              void* d_out, int out_size) {
    const float* Xin  = (const float*)d_in[0];
    const float* WQ   = (const float*)d_in[1];
    const float* WK   = (const float*)d_in[2];
    const float* WV   = (const float*)d_in[3];
    const float* WG   = (const float*)d_in[4];
    const float* WO   = (const float*)d_in[5];
    const float* gn_w = (const float*)d_in[6];
    const float* gn_b = (const float*)d_in[7];
    const float* ln1w = (const float*)d_in[8];
    const float* ln1b = (const float*)d_in[9];
    const float* ln2w = (const float*)d_in[10];
    const float* ln2b = (const float*)d_in[11];
    const float* fw1  = (const float*)d_in[12];
    const float* fb1  = (const float*)d_in[13];
    const float* fw2  = (const float*)d_in[14];
    const float* fb2  = (const float*)d_in[15];
    float* out = (float*)d_out;

    float *pXn, *pQ, *pK, *pV, *pG, *pGated, *pY, *pHn, *pX, *pYa, *pM, *pSt, *pHf;
    cudaGetSymbolAddress((void**)&pXn, g_Xn);
    cudaGetSymbolAddress((void**)&pQ, g_Q);
    cudaGetSymbolAddress((void**)&pK, g_K);
    cudaGetSymbolAddress((void**)&pV, g_V);
    cudaGetSymbolAddress((void**)&pG, g_G);
    cudaGetSymbolAddress((void**)&pGated, g_Gated);
    cudaGetSymbolAddress((void**)&pY, g_Y);
    cudaGetSymbolAddress((void**)&pHn, g_Hn);
    cudaGetSymbolAddress((void**)&pX, g_X);
    cudaGetSymbolAddress((void**)&pYa, g_Yattn);
    cudaGetSymbolAddress((void**)&pM, g_M);
    cudaGetSymbolAddress((void**)&pSt, g_St);
    cudaGetSymbolAddress((void**)&pHf, g_Hf);

    cudaFuncSetAttribute(chunk_out_kernel, cudaFuncAttributeMaxDynamicSharedMemorySize, 84992);
    const int smemCO = (128 * 130 + 2 * 16 * 128) * 4;  // 82944 B

    const float* cur = Xin;  // residual stream input of current layer
    for (int l = 0; l < Lq; l++) {
        // 1. LN1
        ln_kernel<<<BSq, 256>>>(cur, ln1w + (long)l * Hq, ln1b + (long)l * Hq, pXn);
        // 2. Q,K,V per-head GEMMs (grid.z = heads), G GEMM
        mma_gemm_kernel<<<dim3(1, BSq / 128, NHq), 256>>>(pXn, WQ + (long)l * NHq * Hq * HDq, pQ,
            BSq, HDq, Hq, Hq, HDq, Hq, 0, (long)Hq * HDq, HDq, nullptr, nullptr, 0, 0);
        mma_gemm_kernel<<<dim3(1, BSq / 128, NHq), 256>>>(pXn, WK + (long)l * NHq * Hq * HDq, pK,
            BSq, HDq, Hq, Hq, HDq, Hq, 0, (long)Hq * HDq, HDq, nullptr, nullptr, 0, 0);
        mma_gemm_kernel<<<dim3(1, BSq / 128, NHq), 256>>>(pXn, WV + (long)l * NHq * Hq * HDq, pV,
            BSq, HDq, Hq, Hq, HDq, Hq, 0, (long)Hq * HDq, HDq, nullptr, nullptr, 0, 0);
        mma_gemm_kernel<<<dim3(Hq / 128, BSq / 128, 1), 256>>>(pXn, WG + (long)l * Hq * Hq, pG,
            BSq, Hq, Hq, Hq, Hq, Hq, 0, 0, 0, nullptr, nullptr, 0, 0);
        // 3. xpos
        long pairs = (long)BSq * Hq / 2;
        xpos_kernel<<<(int)((pairs + 255) / 256), 256>>>(pQ, 0);
        xpos_kernel<<<(int)((pairs + 255) / 256), 256>>>(pK, 1);
        // 4. retention (exact chunked linear form)
        chunk_kv_kernel<<<Bq * NHq * NCq, 256>>>(pK, pV, pM);
        scan_kernel<<<(Bq * NHq * HDq * HDq) / 256, 256>>>(pM, pSt);
        chunk_out_kernel<<<Bq * NHq * NCq, 256, smemCO>>>(pQ, pK, pV, pSt, pYa);
        // 5. group norm + swish gate
        gnorm_gate_kernel<<<BSq * NHq, 128>>>(pYa, pG, gn_w + (long)l * Hq, gn_b + (long)l * Hq, pGated);
        // 6. O-proj + residual
        mma_gemm_kernel<<<dim3(Hq / 128, BSq / 128, 1), 256>>>(pGated, WO + (long)l * Hq * Hq, pY,
            BSq, Hq, Hq, Hq, Hq, Hq, 0, 0, 0, nullptr, cur, 0, 0);
        // 7. LN2
        ln_kernel<<<BSq, 256>>>(pY, ln2w + (long)l * Hq, ln2b + (long)l * Hq, pHn);
        // 8. FFN1 (+bias, exact gelu)
        mma_gemm_kernel<<<dim3(FFNq / 128, BSq / 128, 1), 256>>>(pHn, fw1 + (long)l * Hq * FFNq, pHf,
            BSq, FFNq, Hq, Hq, FFNq, FFNq, 0, 0, 0, fb1 + (long)l * FFNq, nullptr, 1, 0);
        // 9. FFN2 (+bias, +residual Y)
        mma_gemm_kernel<<<dim3(Hq / 128, BSq / 128, 1), 256>>>(pHf, fw2 + (long)l * FFNq * Hq, pX,
            BSq, Hq, FFNq, FFNq, Hq, Hq, 0, 0, 0, fb2 + (long)l * Hq, pY, 0, 0);
        cur = pX;
    }

    // output 0: X
    long nX = (long)BSq * Hq;
    copy_kernel<<<(int)((nX + 255) / 256), 256>>>(pX, out, nX);
    // output 1: per-batch X @ X^T (NT GEMM)
    mma_gemm_kernel<<<dim3(Sq / 128, Sq / 128, Bq), 256>>>(pX, pX, out + nX,
        Sq, Sq, Hq, Hq, Hq, Sq,
        (long)Sq * Hq, (long)Sq * Hq, (long)Sq * Sq,
        nullptr, nullptr, 0, 1);
}

// round 3
// speedup vs baseline: 2.3850x; 1.2028x over previous
#include <cuda_runtime.h>
#include <math.h>
#include <stdint.h>

// Problem constants
#define Bq   4
#define Sq   2048
#define Hq   512
#define NHq  4
#define HDq  128
#define FFNq 2048
#define Lq   3
#define BSq  (Bq*Sq)        // 8192
#define CHq  128            // retention chunk
#define NCq  (Sq/CHq)       // 16 chunks
#define EPSq 1e-5f

#define PA   20    // pitch for [row][16k] tiles (conflict-free frag LDS)
#define PB   136   // pitch for [16k][128n] tiles
#define PAsm 132   // pitch for 128x128 score matrix

// ---------------- scratch (static __device__, no allocations) ----------------
__device__ float g_Xn[BSq*Hq];
__device__ float g_Q[BSq*Hq];
__device__ float g_K[BSq*Hq];
__device__ float g_V[BSq*Hq];
__device__ float g_G[BSq*Hq];
__device__ float g_Gated[BSq*Hq];
__device__ float g_Y[BSq*Hq];
__device__ float g_Hn[BSq*Hq];
__device__ float g_X[BSq*Hq];
__device__ float g_Yattn[BSq*Hq];          // (b,n,s,d)
__device__ float g_M[Bq*NHq*NCq*HDq*HDq];  // per-chunk decayed KV sums
__device__ float g_St[Bq*NHq*NCq*HDq*HDq]; // per-chunk input states
__device__ float g_Hf[BSq*FFNq];

// gamma_n = 1 - exp(linspace(log(1/32), log(1/512), 4))  (double, matching numpy)
__device__ __forceinline__ float gamma_of(int n) {
    double lg = -3.4657359027997265 + (double)n * (-0.9241962407465937);
    return (float)(1.0 - exp(lg));
}

__device__ __forceinline__ uint32_t f2tf(float x) {
    uint32_t y;
    asm("cvt.rna.tf32.f32 %0, %1;" : "=r"(y) : "f"(x));
    return y;
}

__device__ __forceinline__ void mma_tf32(float* c, const uint32_t* a, const uint32_t* b) {
    asm volatile(
        "mma.sync.aligned.m16n8k8.row.col.f32.tf32.tf32.f32 "
        "{%0,%1,%2,%3}, {%4,%5,%6,%7}, {%8,%9}, {%0,%1,%2,%3};"
        : "+f"(c[0]), "+f"(c[1]), "+f"(c[2]), "+f"(c[3])
        : "r"(a[0]), "r"(a[1]), "r"(a[2]), "r"(a[3]), "r"(b[0]), "r"(b[1]));
}

__device__ __forceinline__ float blockReduceSum(float v, volatile float* red) {
    int tid = threadIdx.x;
#pragma unroll
    for (int o = 16; o > 0; o >>= 1) v += __shfl_xor_sync(0xffffffffu, v, o);
    if ((tid & 31) == 0) red[tid >> 5] = v;
    __syncthreads();
    if (tid == 0) {
        float s = 0.f;
        int nw = blockDim.x >> 5;
        for (int i = 0; i < nw; i++) s += red[i];
        red[0] = s;
    }
    __syncthreads();
    float r = red[0];
    __syncthreads();
    return r;
}

// ---------------- LayerNorm over H=512, one row per block (256 thr) ----------
__global__ __launch_bounds__(256) void ln_kernel(const float* __restrict__ X,
                                                 const float* __restrict__ w,
                                                 const float* __restrict__ b,
                                                 float* __restrict__ out) {
    long row = blockIdx.x;
    const float* x = X + row * Hq;
    __shared__ float red[8];
    int tid = threadIdx.x;
    float v0 = x[tid], v1 = x[tid + 256];
    float m = blockReduceSum(v0 + v1, red) * (1.f / Hq);
    float d0 = v0 - m, d1 = v1 - m;
    float var = blockReduceSum(d0 * d0 + d1 * d1, red) * (1.f / Hq);
    float inv = rsqrtf(var + EPSq);
    out[row * Hq + tid]       = d0 * inv * w[tid]       + b[tid];
    out[row * Hq + tid + 256] = d1 * inv * w[tid + 256] + b[tid + 256];
}

// =============== tf32 tensor-core 128x128x16 GEMM, double-buffered ==========
// C = A(MxK)*B + [bias] -> [gelu | xpos] -> +[res]; NN (bT=0) or NT (bT=1).
// act: 0 none, 1 exact gelu, 2 xpos (Q), 3 xpos downscale (K).
__global__ __launch_bounds__(256, 2) void mma_gemm_kernel(
    const float* __restrict__ A, const float* __restrict__ Bm, float* __restrict__ C,
    int M, int N, int K, int lda, int ldb, int ldc,
    long aStride, long bStride, long cStride,
    const float* __restrict__ bias, const float* __restrict__ res,
    int act, int bT)
{
    __shared__ uint32_t smA[2][128 * PA];
    __shared__ uint32_t smB[2][16 * PB];
    int z = blockIdx.z;
    A  += z * aStride;
    Bm += z * bStride;
    C  += z * cStride;
    if (res) res += z * cStride;
    int bm = blockIdx.y * 128, bn = blockIdx.x * 128;
    int tid = threadIdx.x;
    int lane = tid & 31, warp = tid >> 5;
    int gid = lane >> 2, tig = lane & 3;
    int wy = warp >> 2, wx = warp & 3;

    float acc[4][4][4];
#pragma unroll
    for (int i = 0; i < 4; i++)
#pragma unroll
        for (int j = 0; j < 4; j++)
#pragma unroll
            for (int k = 0; k < 4; k++) acc[i][j][k] = 0.f;

    int ar = tid >> 1, ac = (tid & 1) * 8;     // A: 128 x 16
    int br = tid >> 4, bc = (tid & 15) * 8;    // B NN: 16 x 128

    uint32_t ra[8], rb[8];

#define LOAD_TILE(k0)                                                          \
    {                                                                          \
        const float* ap = A + (long)(bm + ar) * lda + (k0) + ac;               \
        float4 a0 = *(const float4*)(ap);                                      \
        float4 a1 = *(const float4*)(ap + 4);                                  \
        ra[0]=f2tf(a0.x); ra[1]=f2tf(a0.y); ra[2]=f2tf(a0.z); ra[3]=f2tf(a0.w);\
        ra[4]=f2tf(a1.x); ra[5]=f2tf(a1.y); ra[6]=f2tf(a1.z); ra[7]=f2tf(a1.w);\
        if (!bT) {                                                             \
            const float* bp = Bm + (long)((k0) + br) * ldb + bn + bc;          \
            float4 b0 = *(const float4*)(bp);                                  \
            float4 b1 = *(const float4*)(bp + 4);                              \
            rb[0]=f2tf(b0.x); rb[1]=f2tf(b0.y); rb[2]=f2tf(b0.z); rb[3]=f2tf(b0.w);\
            rb[4]=f2tf(b1.x); rb[5]=f2tf(b1.y); rb[6]=f2tf(b1.z); rb[7]=f2tf(b1.w);\
        } else {                                                               \
            const float* bp = Bm + (long)(bn + ar) * ldb + (k0) + ac;          \
            float4 b0 = *(const float4*)(bp);                                  \
            float4 b1 = *(const float4*)(bp + 4);                              \
            rb[0]=f2tf(b0.x); rb[1]=f2tf(b0.y); rb[2]=f2tf(b0.z); rb[3]=f2tf(b0.w);\
            rb[4]=f2tf(b1.x); rb[5]=f2tf(b1.y); rb[6]=f2tf(b1.z); rb[7]=f2tf(b1.w);\
        }                                                                      \
    }

#define STORE_TILE(p)                                                          \
    {                                                                          \
        uint4 v0 = make_uint4(ra[0], ra[1], ra[2], ra[3]);                     \
        uint4 v1 = make_uint4(ra[4], ra[5], ra[6], ra[7]);                     \
        *(uint4*)&smA[p][ar * PA + ac]     = v0;                               \
        *(uint4*)&smA[p][ar * PA + ac + 4] = v1;                               \
        if (!bT) {                                                             \
            uint4 w0 = make_uint4(rb[0], rb[1], rb[2], rb[3]);                 \
            uint4 w1 = make_uint4(rb[4], rb[5], rb[6], rb[7]);                 \
            *(uint4*)&smB[p][br * PB + bc]     = w0;                           \
            *(uint4*)&smB[p][br * PB + bc + 4] = w1;                           \
        } else {                                                               \
            _Pragma("unroll")                                                  \
            for (int i = 0; i < 8; i++) smB[p][(ac + i) * PB + ar] = rb[i];    \
        }                                                                      \
    }

#define COMPUTE(p)                                                             \
    _Pragma("unroll")                                                          \
    for (int kk = 0; kk < 16; kk += 8) {                                       \
        uint32_t af[4][4], bf[4][2];                                           \
        _Pragma("unroll")                                                      \
        for (int mi = 0; mi < 4; mi++) {                                       \
            int mb = (wy * 64 + mi * 16 + gid) * PA + kk + tig;                \
            af[mi][0] = smA[p][mb];                                            \
            af[mi][1] = smA[p][mb + 8 * PA];                                   \
            af[mi][2] = smA[p][mb + 4];                                        \
            af[mi][3] = smA[p][mb + 8 * PA + 4];                               \
        }                                                                      \
        _Pragma("unroll")                                                      \
        for (int ni = 0; ni < 4; ni++) {                                       \
            int nb = wx * 32 + ni * 8 + gid;                                   \
            bf[ni][0] = smB[p][(kk + tig) * PB + nb];                          \
            bf[ni][1] = smB[p][(kk + tig + 4) * PB + nb];                      \
        }                                                                      \
        _Pragma("unroll")                                                      \
        for (int mi = 0; mi < 4; mi++)                                         \
            _Pragma("unroll")                                                  \
            for (int ni = 0; ni < 4; ni++)                                     \
                mma_tf32(acc[mi][ni], af[mi], bf[ni]);                         \
    }

    LOAD_TILE(0)
    STORE_TILE(0)
    __syncthreads();
    int p = 0;
    for (int k0 = 16;; k0 += 16) {
        bool more = (k0 < K);
        if (more) LOAD_TILE(k0)
        COMPUTE(p)
        if (!more) break;
        STORE_TILE(p ^ 1)
        __syncthreads();
        p ^= 1;
    }

    // epilogue
#pragma unroll
    for (int mi = 0; mi < 4; mi++) {
        long r0 = bm + wy * 64 + mi * 16 + gid;
        long r1 = r0 + 8;
#pragma unroll
        for (int ni = 0; ni < 4; ni++) {
            int c0 = bn + wx * 32 + ni * 8 + tig * 2;
            float v00 = acc[mi][ni][0], v01 = acc[mi][ni][1];
            float v10 = acc[mi][ni][2], v11 = acc[mi][ni][3];
            if (bias) {
                float b0 = bias[c0], b1 = bias[c0 + 1];
                v00 += b0; v01 += b1; v10 += b0; v11 += b1;
            }
            if (act == 1) {
                v00 = 0.5f * v00 * (1.f + erff(v00 * 0.70710678118654752f));
                v01 = 0.5f * v01 * (1.f + erff(v01 * 0.70710678118654752f));
                v10 = 0.5f * v10 * (1.f + erff(v10 * 0.70710678118654752f));
                v11 = 0.5f * v11 * (1.f + erff(v11 * 0.70710678118654752f));
            } else if (act >= 2) {
                // xpos rotary on pair (c0, c0+1); i = c0/2 within head (N==128)
                float fi = (float)(c0 >> 1);
                float lsb = log2f((fi + 51.2f) * (1.f / 179.2f));
                if (act == 3) lsb = -lsb;
                float invf = exp2f(fi * (-0.20761871093296528f)); // -log2(1e4)/64
#pragma unroll
                for (int rr = 0; rr < 2; rr++) {
                    float pp = (float)((rr ? r1 : r0) & (Sq - 1));
                    float sc = exp2f(lsb * pp * (1.f / 512.f));
                    float s_, c_;
                    sincosf(pp * invf, &s_, &c_);
                    c_ *= sc; s_ *= sc;
                    if (rr == 0) {
                        float t0 = v00 * c_ - v01 * s_;
                        v01 = v01 * c_ + v00 * s_;
                        v00 = t0;
                    } else {
                        float t0 = v10 * c_ - v11 * s_;
                        v11 = v11 * c_ + v10 * s_;
                        v10 = t0;
                    }
                }
            }
            if (res) {
                v00 += res[r0 * ldc + c0]; v01 += res[r0 * ldc + c0 + 1];
                v10 += res[r1 * ldc + c0]; v11 += res[r1 * ldc + c0 + 1];
            }
            *(float2*)(C + r0 * ldc + c0) = make_float2(v00, v01);
            *(float2*)(C + r1 * ldc + c0) = make_float2(v10, v11);
        }
    }
#undef LOAD_TILE
#undef STORE_TILE
#undef COMPUTE
}

// ---------------- retention pass A: per-chunk decayed KV (tf32 mma) --------
// M[d1][d2] = sum_j gamma^{127-j} K[j][d1] V[j][d2]
__global__ __launch_bounds__(256) void chunk_kv_kernel(const float* __restrict__ Kd,
                                                       const float* __restrict__ Vd,
                                                       float* __restrict__ Mout) {
    __shared__ uint32_t KT[128 * PA];   // [d1][j-tile], swizzled
    __shared__ uint32_t VT[128 * PA];   // [d2][j-tile], swizzled
    int bid = blockIdx.x;
    int bn = bid / NCq, c = bid % NCq;
    int b = bn >> 2, n = bn & 3;
    float lgam = logf(gamma_of(n));
    const float* Kb = Kd + ((long)(b * Sq + c * CHq)) * Hq + n * HDq;
    const float* Vb = Vd + ((long)(b * Sq + c * CHq)) * Hq + n * HDq;
    int tid = threadIdx.x;
    int lane = tid & 31, warp = tid >> 5;
    int gid = lane >> 2, tig = lane & 3;
    int wy = warp >> 2, wx = warp & 3;

    float acc[4][4][4];
#pragma unroll
    for (int i = 0; i < 4; i++)
#pragma unroll
        for (int j = 0; j < 4; j++)
#pragma unroll
            for (int k = 0; k < 4; k++) acc[i][j][k] = 0.f;

    int jj = tid >> 4, dbase = (tid & 15) * 8;
    int swz = tid & 15;                 // (dbase+i)>>3 for i<8
    int jjs = jj ^ swz;

    for (int j0 = 0; j0 < CHq; j0 += 16) {
        int j = j0 + jj;
        float w = expf((float)(127 - j) * lgam);
        const float* kp = Kb + (long)j * Hq + dbase;
        float4 k0 = *(const float4*)(kp), k1 = *(const float4*)(kp + 4);
        const float* vp = Vb + (long)j * Hq + dbase;
        float4 v0 = *(const float4*)(vp), v1 = *(const float4*)(vp + 4);
        __syncthreads();
        KT[(dbase + 0) * PA + jjs] = f2tf(k0.x * w);
        KT[(dbase + 1) * PA + jjs] = f2tf(k0.y * w);
        KT[(dbase + 2) * PA + jjs] = f2tf(k0.z * w);
        KT[(dbase + 3) * PA + jjs] = f2tf(k0.w * w);
        KT[(dbase + 4) * PA + jjs] = f2tf(k1.x * w);
        KT[(dbase + 5) * PA + jjs] = f2tf(k1.y * w);
        KT[(dbase + 6) * PA + jjs] = f2tf(k1.z * w);
        KT[(dbase + 7) * PA + jjs] = f2tf(k1.w * w);
        VT[(dbase + 0) * PA + jjs] = f2tf(v0.x);
        VT[(dbase + 1) * PA + jjs] = f2tf(v0.y);
        VT[(dbase + 2) * PA + jjs] = f2tf(v0.z);
        VT[(dbase + 3) * PA + jjs] = f2tf(v0.w);
        VT[(dbase + 4) * PA + jjs] = f2tf(v1.x);
        VT[(dbase + 5) * PA + jjs] = f2tf(v1.y);
        VT[(dbase + 6) * PA + jjs] = f2tf(v1.z);
        VT[(dbase + 7) * PA + jjs] = f2tf(v1.w);
        __syncthreads();
#pragma unroll
        for (int kk = 0; kk < 16; kk += 8) {
            uint32_t af[4][4], bf[4][2];
#pragma unroll
            for (int mi = 0; mi < 4; mi++) {
                int m = wy * 64 + mi * 16 + gid;
                int sw = m >> 3;
                af[mi][0] = KT[m * PA + ((kk + tig) ^ sw)];
                af[mi][1] = KT[(m + 8) * PA + ((kk + tig) ^ ((m + 8) >> 3))];
                af[mi][2] = KT[m * PA + ((kk + tig + 4) ^ sw)];
                af[mi][3] = KT[(m + 8) * PA + ((kk + tig + 4) ^ ((m + 8) >> 3))];
            }
#pragma unroll
            for (int ni = 0; ni < 4; ni++) {
                int nb = wx * 32 + ni * 8 + gid;
                int sw = nb >> 3;
                bf[ni][0] = VT[nb * PA + ((kk + tig) ^ sw)];
                bf[ni][1] = VT[nb * PA + ((kk + tig + 4) ^ sw)];
            }
#pragma unroll
            for (int mi = 0; mi < 4; mi++)
#pragma unroll
                for (int ni = 0; ni < 4; ni++)
                    mma_tf32(acc[mi][ni], af[mi], bf[ni]);
        }
    }
    float* Mo = Mout + (long)bid * (HDq * HDq);
#pragma unroll
    for (int mi = 0; mi < 4; mi++) {
        int r0 = wy * 64 + mi * 16 + gid, r1 = r0 + 8;
#pragma unroll
        for (int ni = 0; ni < 4; ni++) {
            int c0 = wx * 32 + ni * 8 + tig * 2;
            *(float2*)(Mo + r0 * HDq + c0) = make_float2(acc[mi][ni][0], acc[mi][ni][1]);
            *(float2*)(Mo + r1 * HDq + c0) = make_float2(acc[mi][ni][2], acc[mi][ni][3]);
        }
    }
}

// ---------------- retention pass B: decayed prefix scan over chunks --------
__global__ __launch_bounds__(256) void scan_kernel(const float* __restrict__ M,
                                                   float* __restrict__ St) {
    long idx = (long)blockIdx.x * blockDim.x + threadIdx.x;
    int bn = (int)(idx >> 14);
    int n = bn & 3;
    float gamma = gamma_of(n);
    float gC = expf(128.f * logf(gamma));
    long e = idx & 16383;
    float s = 0.f;
    for (int c = 0; c < NCq; c++) {
        long off = ((long)bn * NCq + c) * 16384 + e;
        St[off] = s;
        s = s * gC + M[off];
    }
}

// ---------------- retention pass C: chunk output (tf32 mma, 3 phases) ------
__global__ __launch_bounds__(256) void chunk_out_kernel(const float* __restrict__ Qd,
                                                        const float* __restrict__ Kd,
                                                        const float* __restrict__ Vd,
                                                        const float* __restrict__ States,
                                                        float* __restrict__ Yattn) {
    extern __shared__ uint32_t dsm[];
    uint32_t* Asm = dsm;                   // 128 x PAsm (tf32 decayed scores)
    uint32_t* T1  = dsm + 128 * PAsm;      // 128 x PA
    uint32_t* T2  = T1 + 128 * PA;         // 128 x PA

    int bid = blockIdx.x;
    int bn = bid / NCq, c = bid % NCq;
    int b = bn >> 2, n = bn & 3;
    float lgam = logf(gamma_of(n));
    const float* Qb = Qd + ((long)(b * Sq + c * CHq)) * Hq + n * HDq;
    const float* Kb = Kd + ((long)(b * Sq + c * CHq)) * Hq + n * HDq;
    const float* Vb = Vd + ((long)(b * Sq + c * CHq)) * Hq + n * HDq;
    const float* Sb = States + ((long)bn * NCq + c) * 16384;

    int tid = threadIdx.x;
    int lane = tid & 31, warp = tid >> 5;
    int gid = lane >> 2, tig = lane & 3;
    int wy = warp >> 2, wx = warp & 3;

    float acc[4][4][4];
#pragma unroll
    for (int i = 0; i < 4; i++)
#pragma unroll
        for (int j = 0; j < 4; j++)
#pragma unroll
            for (int k = 0; k < 4; k++) acc[i][j][k] = 0.f;

    int lr = tid >> 1, lc = (tid & 1) * 8;      // natural tile load coords
    int jj = tid >> 4, dbase = (tid & 15) * 8;  // transposed tile load coords
    int jjs = jj ^ (tid & 15);

    // --- phase 1: scores = Q K^T (contract d) -------------------------------
    for (int d0 = 0; d0 < HDq; d0 += 16) {
        const float* qp = Qb + (long)lr * Hq + d0 + lc;
        float4 q0 = *(const float4*)(qp), q1 = *(const float4*)(qp + 4);
        const float* kp = Kb + (long)lr * Hq + d0 + lc;
        float4 k0 = *(const float4*)(kp), k1 = *(const float4*)(kp + 4);
        __syncthreads();
        *(uint4*)&T1[lr * PA + lc]     = make_uint4(f2tf(q0.x), f2tf(q0.y), f2tf(q0.z), f2tf(q0.w));
        *(uint4*)&T1[lr * PA + lc + 4] = make_uint4(f2tf(q1.x), f2tf(q1.y), f2tf(q1.z), f2tf(q1.w));
        *(uint4*)&T2[lr * PA + lc]     = make_uint4(f2tf(k0.x), f2tf(k0.y), f2tf(k0.z), f2tf(k0.w));
        *(uint4*)&T2[lr * PA + lc + 4] = make_uint4(f2tf(k1.x), f2tf(k1.y), f2tf(k1.z), f2tf(k1.w));
        __syncthreads();
#pragma unroll
        for (int kk = 0; kk < 16; kk += 8) {
            uint32_t af[4][4], bf[4][2];
#pragma unroll
            for (int mi = 0; mi < 4; mi++) {
                int mb = (wy * 64 + mi * 16 + gid) * PA + kk + tig;
                af[mi][0] = T1[mb];
                af[mi][1] = T1[mb + 8 * PA];
                af[mi][2] = T1[mb + 4];
                af[mi][3] = T1[mb + 8 * PA + 4];
            }
#pragma unroll
            for (int ni = 0; ni < 4; ni++) {
                int nb = (wx * 32 + ni * 8 + gid) * PA + kk + tig;
                bf[ni][0] = T2[nb];
                bf[ni][1] = T2[nb + 4];
            }
#pragma unroll
            for (int mi = 0; mi < 4; mi++)
#pragma unroll
                for (int ni = 0; ni < 4; ni++)
                    mma_tf32(acc[mi][ni], af[mi], bf[ni]);
        }
    }
    // decay+mask, write tf32 scores to Asm
    {
        float pj[8], pk[8];
#pragma unroll
        for (int mi = 0; mi < 4; mi++) {
            int r0 = wy * 64 + mi * 16 + gid;
            pj[mi * 2]     = expf((float)r0 * lgam);
            pj[mi * 2 + 1] = expf((float)(r0 + 8) * lgam);
        }
#pragma unroll
        for (int ni = 0; ni < 4; ni++) {
            int c0 = wx * 32 + ni * 8 + tig * 2;
            pk[ni * 2]     = expf((float)(-c0) * lgam);
            pk[ni * 2 + 1] = expf((float)(-(c0 + 1)) * lgam);
        }
        __syncthreads();
#pragma unroll
        for (int mi = 0; mi < 4; mi++) {
            int r0 = wy * 64 + mi * 16 + gid, r1 = r0 + 8;
#pragma unroll
            for (int ni = 0; ni < 4; ni++) {
                int c0 = wx * 32 + ni * 8 + tig * 2;
                float v00 = (r0 >= c0)     ? acc[mi][ni][0] * pj[mi*2]   * pk[ni*2]   : 0.f;
                float v01 = (r0 >= c0 + 1) ? acc[mi][ni][1] * pj[mi*2]   * pk[ni*2+1] : 0.f;
                float v10 = (r1 >= c0)     ? acc[mi][ni][2] * pj[mi*2+1] * pk[ni*2]   : 0.f;
                float v11 = (r1 >= c0 + 1) ? acc[mi][ni][3] * pj[mi*2+1] * pk[ni*2+1] : 0.f;
                Asm[r0 * PAsm + c0]     = f2tf(v00);
                Asm[r0 * PAsm + c0 + 1] = f2tf(v01);
                Asm[r1 * PAsm + c0]     = f2tf(v10);
                Asm[r1 * PAsm + c0 + 1] = f2tf(v11);
                acc[mi][ni][0] = acc[mi][ni][1] = acc[mi][ni][2] = acc[mi][ni][3] = 0.f;
            }
        }
    }
    __syncthreads();

    // --- phase 2: Y = scores * V (contract j) -------------------------------
    for (int j0 = 0; j0 < CHq; j0 += 16) {
        const float* vp = Vb + (long)(j0 + jj) * Hq + dbase;
        float4 v0 = *(const float4*)(vp), v1 = *(const float4*)(vp + 4);
        __syncthreads();
        VTSTORE:
        T2[(dbase + 0) * PA + jjs] = f2tf(v0.x);
        T2[(dbase + 1) * PA + jjs] = f2tf(v0.y);
        T2[(dbase + 2) * PA + jjs] = f2tf(v0.z);
        T2[(dbase + 3) * PA + jjs] = f2tf(v0.w);
        T2[(dbase + 4) * PA + jjs] = f2tf(v1.x);
        T2[(dbase + 5) * PA + jjs] = f2tf(v1.y);
        T2[(dbase + 6) * PA + jjs] = f2tf(v1.z);
        T2[(dbase + 7) * PA + jjs] = f2tf(v1.w);
        __syncthreads();
#pragma unroll
        for (int kk = 0; kk < 16; kk += 8) {
            uint32_t af[4][4], bf[4][2];
#pragma unroll
            for (int mi = 0; mi < 4; mi++) {
                int mb = (wy * 64 + mi * 16 + gid) * PAsm + j0 + kk + tig;
                af[mi][0] = Asm[mb];
                af[mi][1] = Asm[mb + 8 * PAsm];
                af[mi][2] = Asm[mb + 4];
                af[mi][3] = Asm[mb + 8 * PAsm + 4];
            }
#pragma unroll
            for (int ni = 0; ni < 4; ni++) {
                int nb = wx * 32 + ni * 8 + gid;
                int sw = nb >> 3;
                bf[ni][0] = T2[nb * PA + ((kk + tig) ^ sw)];
                bf[ni][1] = T2[nb * PA + ((kk + tig + 4) ^ sw)];
            }
#pragma unroll
            for (int mi = 0; mi < 4; mi++)
#pragma unroll
                for (int ni = 0; ni < 4; ni++)
                    mma_tf32(acc[mi][ni], af[mi], bf[ni]);
        }
    }

    // --- phase 3: Y += diag(gamma^{j+1}) Q * State (contract e) -------------
    {
        float wrow = expf((float)(lr + 1) * lgam);
        for (int e0 = 0; e0 < HDq; e0 += 16) {
            const float* qp = Qb + (long)lr * Hq + e0 + lc;
            float4 q0 = *(const float4*)(qp), q1 = *(const float4*)(qp + 4);
            const float* sp = Sb + (long)(e0 + jj) * HDq + dbase;
            float4 s0 = *(const float4*)(sp), s1 = *(const float4*)(sp + 4);
            __syncthreads();
            *(uint4*)&T1[lr * PA + lc]     = make_uint4(f2tf(q0.x * wrow), f2tf(q0.y * wrow), f2tf(q0.z * wrow), f2tf(q0.w * wrow));
            *(uint4*)&T1[lr * PA + lc + 4] = make_uint4(f2tf(q1.x * wrow), f2tf(q1.y * wrow), f2tf(q1.z * wrow), f2tf(q1.w * wrow));
            T2[(dbase + 0) * PA + jjs] = f2tf(s0.x);
            T2[(dbase + 1) * PA + jjs] = f2tf(s0.y);
            T2[(dbase + 2) * PA + jjs] = f2tf(s0.z);
            T2[(dbase + 3) * PA + jjs] = f2tf(s0.w);
            T2[(dbase + 4) * PA + jjs] = f2tf(s1.x);
            T2[(dbase + 5) * PA + jjs] = f2tf(s1.y);
            T2[(dbase + 6) * PA + jjs] = f2tf(s1.z);
            T2[(dbase + 7) * PA + jjs] = f2tf(s1.w);
            __syncthreads();
#pragma unroll
            for (int kk = 0; kk < 16; kk += 8) {
                uint32_t af[4][4], bf[4][2];
#pragma unroll
                for (int mi = 0; mi < 4; mi++) {
                    int mb = (wy * 64 + mi * 16 + gid) * PA + kk + tig;
                    af[mi][0] = T1[mb];
                    af[mi][1] = T1[mb + 8 * PA];
                    af[mi][2] = T1[mb + 4];
                    af[mi][3] = T1[mb + 8 * PA + 4];
                }
#pragma unroll
                for (int ni = 0; ni < 4; ni++) {
                    int nb = wx * 32 + ni * 8 + gid;
                    int sw = nb >> 3;
                    bf[ni][0] = T2[nb * PA + ((kk + tig) ^ sw)];
                    bf[ni][1] = T2[nb * PA + ((kk + tig + 4) ^ sw)];
                }
#pragma unroll
                for (int mi = 0; mi < 4; mi++)
#pragma unroll
                    for (int ni = 0; ni < 4; ni++)
                        mma_tf32(acc[mi][ni], af[mi], bf[ni]);
            }
        }
    }

    float* Yb = Yattn + ((long)bn * Sq + c * CHq) * HDq;
#pragma unroll
    for (int mi = 0; mi < 4; mi++) {
        int r0 = wy * 64 + mi * 16 + gid, r1 = r0 + 8;
#pragma unroll
        for (int ni = 0; ni < 4; ni++) {
            int c0 = wx * 32 + ni * 8 + tig * 2;
            *(float2*)(Yb + (long)r0 * HDq + c0) = make_float2(acc[mi][ni][0], acc[mi][ni][1]);
            *(float2*)(Yb + (long)r1 * HDq + c0) = make_float2(acc[mi][ni][2], acc[mi][ni][3]);
        }
    }
}

// ---------------- group norm over HD per head + swish gate -----------------
__global__ __launch_bounds__(128) void gnorm_gate_kernel(const float* __restrict__ Yattn,
                                                         const float* __restrict__ G,
                                                         const float* __restrict__ gnw,
                                                         const float* __restrict__ gnb,
                                                         float* __restrict__ out) {
    int bid = blockIdx.x;          // (b*S+s)*NH + n
    int n = bid % NHq;
    long bs = bid / NHq;
    long b = bs / Sq, s = bs % Sq;
    int d = threadIdx.x;
    __shared__ float red[4];
    float y = Yattn[(((long)(b * NHq + n)) * Sq + s) * HDq + d];
    float m = blockReduceSum(y, red) * (1.f / HDq);
    float dd = y - m;
    float var = blockReduceSum(dd * dd, red) * (1.f / HDq);
    float yn = dd * rsqrtf(var + EPSq) * gnw[n * HDq + d] + gnb[n * HDq + d];
    float g = G[bs * Hq + n * HDq + d];
    float sw = g / (1.f + expf(-g));
    out[bs * Hq + n * HDq + d] = sw * yn;
}

// ---------------- plain copy -----------------------------------------------
__global__ void copy_kernel(const float* __restrict__ src, float* __restrict__ dst, long nTot) {
    long i = (long)blockIdx.x * blockDim.x + threadIdx.x;
    if (i < nTot) dst[i] = src[i];
}

// ============================================================================
extern "C" void kernel_launch(void* const* d_in, const int* in_sizes, int n_in,
                              void* d_out, int out_size) {
    const float* Xin  = (const float*)d_in[0];
    const float* WQ   = (const float*)d_in[1];
    const float* WK   = (const float*)d_in[2];
    const float* WV   = (const float*)d_in[3];
    const float* WG   = (const float*)d_in[4];
    const float* WO   = (const float*)d_in[5];
    const float* gn_w = (const float*)d_in[6];
    const float* gn_b = (const float*)d_in[7];
    const float* ln1w = (const float*)d_in[8];
    const float* ln1b = (const float*)d_in[9];
    const float* ln2w = (const float*)d_in[10];
    const float* ln2b = (const float*)d_in[11];
    const float* fw1  = (const float*)d_in[12];
    const float* fb1  = (const float*)d_in[13];
    const float* fw2  = (const float*)d_in[14];
    const float* fb2  = (const float*)d_in[15];
    float* out = (float*)d_out;

    float *pXn, *pQ, *pK, *pV, *pG, *pGated, *pY, *pHn, *pX, *pYa, *pM, *pSt, *pHf;
    cudaGetSymbolAddress((void**)&pXn, g_Xn);
    cudaGetSymbolAddress((void**)&pQ, g_Q);
    cudaGetSymbolAddress((void**)&pK, g_K);
    cudaGetSymbolAddress((void**)&pV, g_V);
    cudaGetSymbolAddress((void**)&pG, g_G);
    cudaGetSymbolAddress((void**)&pGated, g_Gated);
    cudaGetSymbolAddress((void**)&pY, g_Y);
    cudaGetSymbolAddress((void**)&pHn, g_Hn);
    cudaGetSymbolAddress((void**)&pX, g_X);
    cudaGetSymbolAddress((void**)&pYa, g_Yattn);
    cudaGetSymbolAddress((void**)&pM, g_M);
    cudaGetSymbolAddress((void**)&pSt, g_St);
    cudaGetSymbolAddress((void**)&pHf, g_Hf);

    const int smemCO = (128 * PAsm + 2 * 128 * PA) * 4;  // 88064 B
    cudaFuncSetAttribute(chunk_out_kernel, cudaFuncAttributeMaxDynamicSharedMemorySize, smemCO);

    const float* cur = Xin;
    for (int l = 0; l < Lq; l++) {
        // 1. LN1
        ln_kernel<<<BSq, 256>>>(cur, ln1w + (long)l * Hq, ln1b + (long)l * Hq, pXn);
        // 2. Q,K,V per-head GEMMs with fused xpos; G GEMM
        mma_gemm_kernel<<<dim3(1, BSq / 128, NHq), 256>>>(pXn, WQ + (long)l * NHq * Hq * HDq, pQ,
            BSq, HDq, Hq, Hq, HDq, Hq, 0, (long)Hq * HDq, HDq, nullptr, nullptr, 2, 0);
        mma_gemm_kernel<<<dim3(1, BSq / 128, NHq), 256>>>(pXn, WK + (long)l * NHq * Hq * HDq, pK,
            BSq, HDq, Hq, Hq, HDq, Hq, 0, (long)Hq * HDq, HDq, nullptr, nullptr, 3, 0);
        mma_gemm_kernel<<<dim3(1, BSq / 128, NHq), 256>>>(pXn, WV + (long)l * NHq * Hq * HDq, pV,
            BSq, HDq, Hq, Hq, HDq, Hq, 0, (long)Hq * HDq, HDq, nullptr, nullptr, 0, 0);
        mma_gemm_kernel<<<dim3(Hq / 128, BSq / 128, 1), 256>>>(pXn, WG + (long)l * Hq * Hq, pG,
            BSq, Hq, Hq, Hq, Hq, Hq, 0, 0, 0, nullptr, nullptr, 0, 0);
        // 3. retention (exact chunked linear form, tf32 mma)
        chunk_kv_kernel<<<Bq * NHq * NCq, 256>>>(pK, pV, pM);
        scan_kernel<<<(Bq * NHq * HDq * HDq) / 256, 256>>>(pM, pSt);
        chunk_out_kernel<<<Bq * NHq * NCq, 256, smemCO>>>(pQ, pK, pV, pSt, pYa);
        // 4. group norm + swish gate
        gnorm_gate_kernel<<<BSq * NHq, 128>>>(pYa, pG, gn_w + (long)l * Hq, gn_b + (long)l * Hq, pGated);
        // 5. O-proj + residual
        mma_gemm_kernel<<<dim3(Hq / 128, BSq / 128, 1), 256>>>(pGated, WO + (long)l * Hq * Hq, pY,
            BSq, Hq, Hq, Hq, Hq, Hq, 0, 0, 0, nullptr, cur, 0, 0);
        // 6. LN2
        ln_kernel<<<BSq, 256>>>(pY, ln2w + (long)l * Hq, ln2b + (long)l * Hq, pHn);
        // 7. FFN1 (+bias, exact gelu)
        mma_gemm_kernel<<<dim3(FFNq / 128, BSq / 128, 1), 256>>>(pHn, fw1 + (long)l * Hq * FFNq, pHf,
            BSq, FFNq, Hq, Hq, FFNq, FFNq, 0, 0, 0, fb1 + (long)l * FFNq, nullptr, 1, 0);
        // 8. FFN2 (+bias, +residual Y)
        mma_gemm_kernel<<<dim3(Hq / 128, BSq / 128, 1), 256>>>(pHf, fw2 + (long)l * FFNq * Hq, pX,
            BSq, Hq, FFNq, FFNq, Hq, Hq, 0, 0, 0, fb2 + (long)l * Hq, pY, 0, 0);
        cur = pX;
    }

    // output 0: X
    long nX = (long)BSq * Hq;
    copy_kernel<<<(int)((nX + 255) / 256), 256>>>(pX, out, nX);
    // output 1: per-batch X @ X^T (NT GEMM)
    mma_gemm_kernel<<<dim3(Sq / 128, Sq / 128, Bq), 256>>>(pX, pX, out + nX,
        Sq, Sq, Hq, Hq, Hq, Sq,
        (long)Sq * Hq, (long)Sq * Hq, (long)Sq * Sq,
        nullptr, nullptr, 0, 1);
}

// round 4
// speedup vs baseline: 2.3861x; 1.0004x over previous
#include <cuda_runtime.h>
#include <math.h>
#include <stdint.h>

// Problem constants
#define Bq   4
#define Sq   2048
#define Hq   512
#define NHq  4
#define HDq  128
#define FFNq 2048
#define Lq   3
#define BSq  (Bq*Sq)        // 8192
#define CHq  128            // retention chunk
#define NCq  (Sq/CHq)       // 16 chunks
#define EPSq 1e-5f

#define PA   20    // pitch for [row][16k] tiles (conflict-free frag LDS)
#define PB   136   // pitch for [16k][128n] tiles
#define PAsm 132   // pitch for 128x128 score matrix

// ---------------- scratch (static __device__, no allocations) ----------------
__device__ float g_Xn[BSq*Hq];
__device__ float g_Q[BSq*Hq];
__device__ float g_K[BSq*Hq];
__device__ float g_V[BSq*Hq];
__device__ float g_G[BSq*Hq];
__device__ float g_Gated[BSq*Hq];
__device__ float g_Y[BSq*Hq];
__device__ float g_Hn[BSq*Hq];
__device__ float g_X[BSq*Hq];
__device__ float g_Yattn[BSq*Hq];          // (b,n,s,d)
__device__ float g_M[Bq*NHq*NCq*HDq*HDq];  // per-chunk decayed KV sums
__device__ float g_St[Bq*NHq*NCq*HDq*HDq]; // per-chunk input states
__device__ float g_Hf[BSq*FFNq];

// gamma_n = 1 - exp(linspace(log(1/32), log(1/512), 4))  (double, matching numpy)
__device__ __forceinline__ float gamma_of(int n) {
    double lg = -3.4657359027997265 + (double)n * (-0.9241962407465937);
    return (float)(1.0 - exp(lg));
}

__device__ __forceinline__ uint32_t f2tf(float x) {
    uint32_t y;
    asm("cvt.rna.tf32.f32 %0, %1;" : "=r"(y) : "f"(x));
    return y;
}

__device__ __forceinline__ void mma_tf32(float* c, const uint32_t* a, const uint32_t* b) {
    asm volatile(
        "mma.sync.aligned.m16n8k8.row.col.f32.tf32.tf32.f32 "
        "{%0,%1,%2,%3}, {%4,%5,%6,%7}, {%8,%9}, {%0,%1,%2,%3};"
        : "+f"(c[0]), "+f"(c[1]), "+f"(c[2]), "+f"(c[3])
        : "r"(a[0]), "r"(a[1]), "r"(a[2]), "r"(a[3]), "r"(b[0]), "r"(b[1]));
}

__device__ __forceinline__ float blockReduceSum(float v, volatile float* red) {
    int tid = threadIdx.x;
#pragma unroll
    for (int o = 16; o > 0; o >>= 1) v += __shfl_xor_sync(0xffffffffu, v, o);
    if ((tid & 31) == 0) red[tid >> 5] = v;
    __syncthreads();
    if (tid == 0) {
        float s = 0.f;
        int nw = blockDim.x >> 5;
        for (int i = 0; i < nw; i++) s += red[i];
        red[0] = s;
    }
    __syncthreads();
    float r = red[0];
    __syncthreads();
    return r;
}

// ---------------- LayerNorm over H=512, one row per block (256 thr) ----------
__global__ __launch_bounds__(256) void ln_kernel(const float* __restrict__ X,
                                                 const float* __restrict__ w,
                                                 const float* __restrict__ b,
                                                 float* __restrict__ out) {
    long row = blockIdx.x;
    const float* x = X + row * Hq;
    __shared__ float red[8];
    int tid = threadIdx.x;
    float v0 = x[tid], v1 = x[tid + 256];
    float m = blockReduceSum(v0 + v1, red) * (1.f / Hq);
    float d0 = v0 - m, d1 = v1 - m;
    float var = blockReduceSum(d0 * d0 + d1 * d1, red) * (1.f / Hq);
    float inv = rsqrtf(var + EPSq);
    out[row * Hq + tid]       = d0 * inv * w[tid]       + b[tid];
    out[row * Hq + tid + 256] = d1 * inv * w[tid + 256] + b[tid + 256];
}

// =============== tf32 tensor-core 128x128x16 GEMM, double-buffered ==========
// C = A(MxK)*B + [bias] -> [gelu | xpos] -> +[res]; NN (bT=0) or NT (bT=1).
// act: 0 none, 1 exact gelu, 2 xpos (Q), 3 xpos downscale (K).
__global__ __launch_bounds__(256, 2) void mma_gemm_kernel(
    const float* __restrict__ A, const float* __restrict__ Bm, float* __restrict__ C,
    int M, int N, int K, int lda, int ldb, int ldc,
    long aStride, long bStride, long cStride,
    const float* __restrict__ bias, const float* __restrict__ res,
    int act, int bT)
{
    __shared__ uint32_t smA[2][128 * PA];
    __shared__ uint32_t smB[2][16 * PB];
    int z = blockIdx.z;
    A  += z * aStride;
    Bm += z * bStride;
    C  += z * cStride;
    if (res) res += z * cStride;
    int bm = blockIdx.y * 128, bn = blockIdx.x * 128;
    int tid = threadIdx.x;
    int lane = tid & 31, warp = tid >> 5;
    int gid = lane >> 2, tig = lane & 3;
    int wy = warp >> 2, wx = warp & 3;

    float acc[4][4][4];
#pragma unroll
    for (int i = 0; i < 4; i++)
#pragma unroll
        for (int j = 0; j < 4; j++)
#pragma unroll
            for (int k = 0; k < 4; k++) acc[i][j][k] = 0.f;

    int ar = tid >> 1, ac = (tid & 1) * 8;     // A: 128 x 16
    int br = tid >> 4, bc = (tid & 15) * 8;    // B NN: 16 x 128

    uint32_t ra[8], rb[8];

#define LOAD_TILE(k0)                                                          \
    {                                                                          \
        const float* ap = A + (long)(bm + ar) * lda + (k0) + ac;               \
        float4 a0 = *(const float4*)(ap);                                      \
        float4 a1 = *(const float4*)(ap + 4);                                  \
        ra[0]=f2tf(a0.x); ra[1]=f2tf(a0.y); ra[2]=f2tf(a0.z); ra[3]=f2tf(a0.w);\
        ra[4]=f2tf(a1.x); ra[5]=f2tf(a1.y); ra[6]=f2tf(a1.z); ra[7]=f2tf(a1.w);\
        if (!bT) {                                                             \
            const float* bp = Bm + (long)((k0) + br) * ldb + bn + bc;          \
            float4 b0 = *(const float4*)(bp);                                  \
            float4 b1 = *(const float4*)(bp + 4);                              \
            rb[0]=f2tf(b0.x); rb[1]=f2tf(b0.y); rb[2]=f2tf(b0.z); rb[3]=f2tf(b0.w);\
            rb[4]=f2tf(b1.x); rb[5]=f2tf(b1.y); rb[6]=f2tf(b1.z); rb[7]=f2tf(b1.w);\
        } else {                                                               \
            const float* bp = Bm + (long)(bn + ar) * ldb + (k0) + ac;          \
            float4 b0 = *(const float4*)(bp);                                  \
            float4 b1 = *(const float4*)(bp + 4);                              \
            rb[0]=f2tf(b0.x); rb[1]=f2tf(b0.y); rb[2]=f2tf(b0.z); rb[3]=f2tf(b0.w);\
            rb[4]=f2tf(b1.x); rb[5]=f2tf(b1.y); rb[6]=f2tf(b1.z); rb[7]=f2tf(b1.w);\
        }                                                                      \
    }

#define STORE_TILE(p)                                                          \
    {                                                                          \
        uint4 v0 = make_uint4(ra[0], ra[1], ra[2], ra[3]);                     \
        uint4 v1 = make_uint4(ra[4], ra[5], ra[6], ra[7]);                     \
        *(uint4*)&smA[p][ar * PA + ac]     = v0;                               \
        *(uint4*)&smA[p][ar * PA + ac + 4] = v1;                               \
        if (!bT) {                                                             \
            uint4 w0 = make_uint4(rb[0], rb[1], rb[2], rb[3]);                 \
            uint4 w1 = make_uint4(rb[4], rb[5], rb[6], rb[7]);                 \
            *(uint4*)&smB[p][br * PB + bc]     = w0;                           \
            *(uint4*)&smB[p][br * PB + bc + 4] = w1;                           \
        } else {                                                               \
            _Pragma("unroll")                                                  \
            for (int i = 0; i < 8; i++) smB[p][(ac + i) * PB + ar] = rb[i];    \
        }                                                                      \
    }

#define COMPUTE(p)                                                             \
    _Pragma("unroll")                                                          \
    for (int kk = 0; kk < 16; kk += 8) {                                       \
        uint32_t af[4][4], bf[4][2];                                           \
        _Pragma("unroll")                                                      \
        for (int mi = 0; mi < 4; mi++) {                                       \
            int mb = (wy * 64 + mi * 16 + gid) * PA + kk + tig;                \
            af[mi][0] = smA[p][mb];                                            \
            af[mi][1] = smA[p][mb + 8 * PA];                                   \
            af[mi][2] = smA[p][mb + 4];                                        \
            af[mi][3] = smA[p][mb + 8 * PA + 4];                               \
        }                                                                      \
        _Pragma("unroll")                                                      \
        for (int ni = 0; ni < 4; ni++) {                                       \
            int nb = wx * 32 + ni * 8 + gid;                                   \
            bf[ni][0] = smB[p][(kk + tig) * PB + nb];                          \
            bf[ni][1] = smB[p][(kk + tig + 4) * PB + nb];                      \
        }                                                                      \
        _Pragma("unroll")                                                      \
        for (int mi = 0; mi < 4; mi++)                                         \
            _Pragma("unroll")                                                  \
            for (int ni = 0; ni < 4; ni++)                                     \
                mma_tf32(acc[mi][ni], af[mi], bf[ni]);                         \
    }

    LOAD_TILE(0)
    STORE_TILE(0)
    __syncthreads();
    int p = 0;
    for (int k0 = 16;; k0 += 16) {
        bool more = (k0 < K);
        if (more) LOAD_TILE(k0)
        COMPUTE(p)
        if (!more) break;
        STORE_TILE(p ^ 1)
        __syncthreads();
        p ^= 1;
    }

    // epilogue
#pragma unroll
    for (int mi = 0; mi < 4; mi++) {
        long r0 = bm + wy * 64 + mi * 16 + gid;
        long r1 = r0 + 8;
#pragma unroll
        for (int ni = 0; ni < 4; ni++) {
            int c0 = bn + wx * 32 + ni * 8 + tig * 2;
            float v00 = acc[mi][ni][0], v01 = acc[mi][ni][1];
            float v10 = acc[mi][ni][2], v11 = acc[mi][ni][3];
            if (bias) {
                float b0 = bias[c0], b1 = bias[c0 + 1];
                v00 += b0; v01 += b1; v10 += b0; v11 += b1;
            }
            if (act == 1) {
                v00 = 0.5f * v00 * (1.f + erff(v00 * 0.70710678118654752f));
                v01 = 0.5f * v01 * (1.f + erff(v01 * 0.70710678118654752f));
                v10 = 0.5f * v10 * (1.f + erff(v10 * 0.70710678118654752f));
                v11 = 0.5f * v11 * (1.f + erff(v11 * 0.70710678118654752f));
            } else if (act >= 2) {
                // xpos rotary on pair (c0, c0+1); i = c0/2 within head (N==128)
                float fi = (float)(c0 >> 1);
                float lsb = log2f((fi + 51.2f) * (1.f / 179.2f));
                if (act == 3) lsb = -lsb;
                float invf = exp2f(fi * (-0.20761871093296528f)); // -log2(1e4)/64
#pragma unroll
                for (int rr = 0; rr < 2; rr++) {
                    float pp = (float)((rr ? r1 : r0) & (Sq - 1));
                    float sc = exp2f(lsb * pp * (1.f / 512.f));
                    float s_, c_;
                    sincosf(pp * invf, &s_, &c_);
                    c_ *= sc; s_ *= sc;
                    if (rr == 0) {
                        float t0 = v00 * c_ - v01 * s_;
                        v01 = v01 * c_ + v00 * s_;
                        v00 = t0;
                    } else {
                        float t0 = v10 * c_ - v11 * s_;
                        v11 = v11 * c_ + v10 * s_;
                        v10 = t0;
                    }
                }
            }
            if (res) {
                v00 += res[r0 * ldc + c0]; v01 += res[r0 * ldc + c0 + 1];
                v10 += res[r1 * ldc + c0]; v11 += res[r1 * ldc + c0 + 1];
            }
            *(float2*)(C + r0 * ldc + c0) = make_float2(v00, v01);
            *(float2*)(C + r1 * ldc + c0) = make_float2(v10, v11);
        }
    }
#undef LOAD_TILE
#undef STORE_TILE
#undef COMPUTE
}

// ---------------- retention pass A: per-chunk decayed KV (tf32 mma) --------
// M[d1][d2] = sum_j gamma^{127-j} K[j][d1] V[j][d2]
__global__ __launch_bounds__(256) void chunk_kv_kernel(const float* __restrict__ Kd,
                                                       const float* __restrict__ Vd,
                                                       float* __restrict__ Mout) {
    __shared__ uint32_t KT[128 * PA];   // [d1][j-tile], swizzled
    __shared__ uint32_t VT[128 * PA];   // [d2][j-tile], swizzled
    int bid = blockIdx.x;
    int bn = bid / NCq, c = bid % NCq;
    int b = bn >> 2, n = bn & 3;
    float lgam = logf(gamma_of(n));
    const float* Kb = Kd + ((long)(b * Sq + c * CHq)) * Hq + n * HDq;
    const float* Vb = Vd + ((long)(b * Sq + c * CHq)) * Hq + n * HDq;
    int tid = threadIdx.x;
    int lane = tid & 31, warp = tid >> 5;
    int gid = lane >> 2, tig = lane & 3;
    int wy = warp >> 2, wx = warp & 3;

    float acc[4][4][4];
#pragma unroll
    for (int i = 0; i < 4; i++)
#pragma unroll
        for (int j = 0; j < 4; j++)
#pragma unroll
            for (int k = 0; k < 4; k++) acc[i][j][k] = 0.f;

    int jj = tid >> 4, dbase = (tid & 15) * 8;
    int swz = tid & 15;                 // (dbase+i)>>3 for i<8
    int jjs = jj ^ swz;

    for (int j0 = 0; j0 < CHq; j0 += 16) {
        int j = j0 + jj;
        float w = expf((float)(127 - j) * lgam);
        const float* kp = Kb + (long)j * Hq + dbase;
        float4 k0 = *(const float4*)(kp), k1 = *(const float4*)(kp + 4);
        const float* vp = Vb + (long)j * Hq + dbase;
        float4 v0 = *(const float4*)(vp), v1 = *(const float4*)(vp + 4);
        __syncthreads();
        KT[(dbase + 0) * PA + jjs] = f2tf(k0.x * w);
        KT[(dbase + 1) * PA + jjs] = f2tf(k0.y * w);
        KT[(dbase + 2) * PA + jjs] = f2tf(k0.z * w);
        KT[(dbase + 3) * PA + jjs] = f2tf(k0.w * w);
        KT[(dbase + 4) * PA + jjs] = f2tf(k1.x * w);
        KT[(dbase + 5) * PA + jjs] = f2tf(k1.y * w);
        KT[(dbase + 6) * PA + jjs] = f2tf(k1.z * w);
        KT[(dbase + 7) * PA + jjs] = f2tf(k1.w * w);
        VT[(dbase + 0) * PA + jjs] = f2tf(v0.x);
        VT[(dbase + 1) * PA + jjs] = f2tf(v0.y);
        VT[(dbase + 2) * PA + jjs] = f2tf(v0.z);
        VT[(dbase + 3) * PA + jjs] = f2tf(v0.w);
        VT[(dbase + 4) * PA + jjs] = f2tf(v1.x);
        VT[(dbase + 5) * PA + jjs] = f2tf(v1.y);
        VT[(dbase + 6) * PA + jjs] = f2tf(v1.z);
        VT[(dbase + 7) * PA + jjs] = f2tf(v1.w);
        __syncthreads();
#pragma unroll
        for (int kk = 0; kk < 16; kk += 8) {
            uint32_t af[4][4], bf[4][2];
#pragma unroll
            for (int mi = 0; mi < 4; mi++) {
                int m = wy * 64 + mi * 16 + gid;
                int sw = m >> 3;
                af[mi][0] = KT[m * PA + ((kk + tig) ^ sw)];
                af[mi][1] = KT[(m + 8) * PA + ((kk + tig) ^ ((m + 8) >> 3))];
                af[mi][2] = KT[m * PA + ((kk + tig + 4) ^ sw)];
                af[mi][3] = KT[(m + 8) * PA + ((kk + tig + 4) ^ ((m + 8) >> 3))];
            }
#pragma unroll
            for (int ni = 0; ni < 4; ni++) {
                int nb = wx * 32 + ni * 8 + gid;
                int sw = nb >> 3;
                bf[ni][0] = VT[nb * PA + ((kk + tig) ^ sw)];
                bf[ni][1] = VT[nb * PA + ((kk + tig + 4) ^ sw)];
            }
#pragma unroll
            for (int mi = 0; mi < 4; mi++)
#pragma unroll
                for (int ni = 0; ni < 4; ni++)
                    mma_tf32(acc[mi][ni], af[mi], bf[ni]);
        }
    }
    float* Mo = Mout + (long)bid * (HDq * HDq);
#pragma unroll
    for (int mi = 0; mi < 4; mi++) {
        int r0 = wy * 64 + mi * 16 + gid, r1 = r0 + 8;
#pragma unroll
        for (int ni = 0; ni < 4; ni++) {
            int c0 = wx * 32 + ni * 8 + tig * 2;
            *(float2*)(Mo + r0 * HDq + c0) = make_float2(acc[mi][ni][0], acc[mi][ni][1]);
            *(float2*)(Mo + r1 * HDq + c0) = make_float2(acc[mi][ni][2], acc[mi][ni][3]);
        }
    }
}

// ---------------- retention pass B: decayed prefix scan over chunks --------
__global__ __launch_bounds__(256) void scan_kernel(const float* __restrict__ M,
                                                   float* __restrict__ St) {
    long idx = (long)blockIdx.x * blockDim.x + threadIdx.x;
    int bn = (int)(idx >> 14);
    int n = bn & 3;
    float gamma = gamma_of(n);
    float gC = expf(128.f * logf(gamma));
    long e = idx & 16383;
    float s = 0.f;
    for (int c = 0; c < NCq; c++) {
        long off = ((long)bn * NCq + c) * 16384 + e;
        St[off] = s;
        s = s * gC + M[off];
    }
}

// ---------------- retention pass C: chunk output (tf32 mma, 3 phases) ------
__global__ __launch_bounds__(256) void chunk_out_kernel(const float* __restrict__ Qd,
                                                        const float* __restrict__ Kd,
                                                        const float* __restrict__ Vd,
                                                        const float* __restrict__ States,
                                                        float* __restrict__ Yattn) {
    extern __shared__ uint32_t dsm[];
    uint32_t* Asm = dsm;                   // 128 x PAsm (tf32 decayed scores)
    uint32_t* T1  = dsm + 128 * PAsm;      // 128 x PA
    uint32_t* T2  = T1 + 128 * PA;         // 128 x PA

    int bid = blockIdx.x;
    int bn = bid / NCq, c = bid % NCq;
    int b = bn >> 2, n = bn & 3;
    float lgam = logf(gamma_of(n));
    const float* Qb = Qd + ((long)(b * Sq + c * CHq)) * Hq + n * HDq;
    const float* Kb = Kd + ((long)(b * Sq + c * CHq)) * Hq + n * HDq;
    const float* Vb = Vd + ((long)(b * Sq + c * CHq)) * Hq + n * HDq;
    const float* Sb = States + ((long)bn * NCq + c) * 16384;

    int tid = threadIdx.x;
    int lane = tid & 31, warp = tid >> 5;
    int gid = lane >> 2, tig = lane & 3;
    int wy = warp >> 2, wx = warp & 3;

    float acc[4][4][4];
#pragma unroll
    for (int i = 0; i < 4; i++)
#pragma unroll
        for (int j = 0; j < 4; j++)
#pragma unroll
            for (int k = 0; k < 4; k++) acc[i][j][k] = 0.f;

    int lr = tid >> 1, lc = (tid & 1) * 8;      // natural tile load coords
    int jj = tid >> 4, dbase = (tid & 15) * 8;  // transposed tile load coords
    int jjs = jj ^ (tid & 15);

    // --- phase 1: scores = Q K^T (contract d) -------------------------------
    for (int d0 = 0; d0 < HDq; d0 += 16) {
        const float* qp = Qb + (long)lr * Hq + d0 + lc;
        float4 q0 = *(const float4*)(qp), q1 = *(const float4*)(qp + 4);
        const float* kp = Kb + (long)lr * Hq + d0 + lc;
        float4 k0 = *(const float4*)(kp), k1 = *(const float4*)(kp + 4);
        __syncthreads();
        *(uint4*)&T1[lr * PA + lc]     = make_uint4(f2tf(q0.x), f2tf(q0.y), f2tf(q0.z), f2tf(q0.w));
        *(uint4*)&T1[lr * PA + lc + 4] = make_uint4(f2tf(q1.x), f2tf(q1.y), f2tf(q1.z), f2tf(q1.w));
        *(uint4*)&T2[lr * PA + lc]     = make_uint4(f2tf(k0.x), f2tf(k0.y), f2tf(k0.z), f2tf(k0.w));
        *(uint4*)&T2[lr * PA + lc + 4] = make_uint4(f2tf(k1.x), f2tf(k1.y), f2tf(k1.z), f2tf(k1.w));
        __syncthreads();
#pragma unroll
        for (int kk = 0; kk < 16; kk += 8) {
            uint32_t af[4][4], bf[4][2];
#pragma unroll
            for (int mi = 0; mi < 4; mi++) {
                int mb = (wy * 64 + mi * 16 + gid) * PA + kk + tig;
                af[mi][0] = T1[mb];
                af[mi][1] = T1[mb + 8 * PA];
                af[mi][2] = T1[mb + 4];
                af[mi][3] = T1[mb + 8 * PA + 4];
            }
#pragma unroll
            for (int ni = 0; ni < 4; ni++) {
                int nb = (wx * 32 + ni * 8 + gid) * PA + kk + tig;
                bf[ni][0] = T2[nb];
                bf[ni][1] = T2[nb + 4];
            }
#pragma unroll
            for (int mi = 0; mi < 4; mi++)
#pragma unroll
                for (int ni = 0; ni < 4; ni++)
                    mma_tf32(acc[mi][ni], af[mi], bf[ni]);
        }
    }
    // decay+mask, write tf32 scores to Asm
    {
        float pj[8], pk[8];
#pragma unroll
        for (int mi = 0; mi < 4; mi++) {
            int r0 = wy * 64 + mi * 16 + gid;
            pj[mi * 2]     = expf((float)r0 * lgam);
            pj[mi * 2 + 1] = expf((float)(r0 + 8) * lgam);
        }
#pragma unroll
        for (int ni = 0; ni < 4; ni++) {
            int c0 = wx * 32 + ni * 8 + tig * 2;
            pk[ni * 2]     = expf((float)(-c0) * lgam);
            pk[ni * 2 + 1] = expf((float)(-(c0 + 1)) * lgam);
        }
        __syncthreads();
#pragma unroll
        for (int mi = 0; mi < 4; mi++) {
            int r0 = wy * 64 + mi * 16 + gid, r1 = r0 + 8;
#pragma unroll
            for (int ni = 0; ni < 4; ni++) {
                int c0 = wx * 32 + ni * 8 + tig * 2;
                float v00 = (r0 >= c0)     ? acc[mi][ni][0] * pj[mi*2]   * pk[ni*2]   : 0.f;
                float v01 = (r0 >= c0 + 1) ? acc[mi][ni][1] * pj[mi*2]   * pk[ni*2+1] : 0.f;
                float v10 = (r1 >= c0)     ? acc[mi][ni][2] * pj[mi*2+1] * pk[ni*2]   : 0.f;
                float v11 = (r1 >= c0 + 1) ? acc[mi][ni][3] * pj[mi*2+1] * pk[ni*2+1] : 0.f;
                Asm[r0 * PAsm + c0]     = f2tf(v00);
                Asm[r0 * PAsm + c0 + 1] = f2tf(v01);
                Asm[r1 * PAsm + c0]     = f2tf(v10);
                Asm[r1 * PAsm + c0 + 1] = f2tf(v11);
                acc[mi][ni][0] = acc[mi][ni][1] = acc[mi][ni][2] = acc[mi][ni][3] = 0.f;
            }
        }
    }
    __syncthreads();

    // --- phase 2: Y = scores * V (contract j) -------------------------------
    for (int j0 = 0; j0 < CHq; j0 += 16) {
        const float* vp = Vb + (long)(j0 + jj) * Hq + dbase;
        float4 v0 = *(const float4*)(vp), v1 = *(const float4*)(vp + 4);
        __syncthreads();
        VTSTORE:
        T2[(dbase + 0) * PA + jjs] = f2tf(v0.x);
        T2[(dbase + 1) * PA + jjs] = f2tf(v0.y);
        T2[(dbase + 2) * PA + jjs] = f2tf(v0.z);
        T2[(dbase + 3) * PA + jjs] = f2tf(v0.w);
        T2[(dbase + 4) * PA + jjs] = f2tf(v1.x);
        T2[(dbase + 5) * PA + jjs] = f2tf(v1.y);
        T2[(dbase + 6) * PA + jjs] = f2tf(v1.z);
        T2[(dbase + 7) * PA + jjs] = f2tf(v1.w);
        __syncthreads();
#pragma unroll
        for (int kk = 0; kk < 16; kk += 8) {
            uint32_t af[4][4], bf[4][2];
#pragma unroll
            for (int mi = 0; mi < 4; mi++) {
                int mb = (wy * 64 + mi * 16 + gid) * PAsm + j0 + kk + tig;
                af[mi][0] = Asm[mb];
                af[mi][1] = Asm[mb + 8 * PAsm];
                af[mi][2] = Asm[mb + 4];
                af[mi][3] = Asm[mb + 8 * PAsm + 4];
            }
#pragma unroll
            for (int ni = 0; ni < 4; ni++) {
                int nb = wx * 32 + ni * 8 + gid;
                int sw = nb >> 3;
                bf[ni][0] = T2[nb * PA + ((kk + tig) ^ sw)];
                bf[ni][1] = T2[nb * PA + ((kk + tig + 4) ^ sw)];
            }
#pragma unroll
            for (int mi = 0; mi < 4; mi++)
#pragma unroll
                for (int ni = 0; ni < 4; ni++)
                    mma_tf32(acc[mi][ni], af[mi], bf[ni]);
        }
    }

    // --- phase 3: Y += diag(gamma^{j+1}) Q * State (contract e) -------------
    {
        float wrow = expf((float)(lr + 1) * lgam);
        for (int e0 = 0; e0 < HDq; e0 += 16) {
            const float* qp = Qb + (long)lr * Hq + e0 + lc;
            float4 q0 = *(const float4*)(qp), q1 = *(const float4*)(qp + 4);
            const float* sp = Sb + (long)(e0 + jj) * HDq + dbase;
            float4 s0 = *(const float4*)(sp), s1 = *(const float4*)(sp + 4);
            __syncthreads();
            *(uint4*)&T1[lr * PA + lc]     = make_uint4(f2tf(q0.x * wrow), f2tf(q0.y * wrow), f2tf(q0.z * wrow), f2tf(q0.w * wrow));
            *(uint4*)&T1[lr * PA + lc + 4] = make_uint4(f2tf(q1.x * wrow), f2tf(q1.y * wrow), f2tf(q1.z * wrow), f2tf(q1.w * wrow));
            T2[(dbase + 0) * PA + jjs] = f2tf(s0.x);
            T2[(dbase + 1) * PA + jjs] = f2tf(s0.y);
            T2[(dbase + 2) * PA + jjs] = f2tf(s0.z);
            T2[(dbase + 3) * PA + jjs] = f2tf(s0.w);
            T2[(dbase + 4) * PA + jjs] = f2tf(s1.x);
            T2[(dbase + 5) * PA + jjs] = f2tf(s1.y);
            T2[(dbase + 6) * PA + jjs] = f2tf(s1.z);
            T2[(dbase + 7) * PA + jjs] = f2tf(s1.w);
            __syncthreads();
#pragma unroll
            for (int kk = 0; kk < 16; kk += 8) {
                uint32_t af[4][4], bf[4][2];
#pragma unroll
                for (int mi = 0; mi < 4; mi++) {
                    int mb = (wy * 64 + mi * 16 + gid) * PA + kk + tig;
                    af[mi][0] = T1[mb];
                    af[mi][1] = T1[mb + 8 * PA];
                    af[mi][2] = T1[mb + 4];
                    af[mi][3] = T1[mb + 8 * PA + 4];
                }
#pragma unroll
                for (int ni = 0; ni < 4; ni++) {
                    int nb = wx * 32 + ni * 8 + gid;
                    int sw = nb >> 3;
                    bf[ni][0] = T2[nb * PA + ((kk + tig) ^ sw)];
                    bf[ni][1] = T2[nb * PA + ((kk + tig + 4) ^ sw)];
                }
#pragma unroll
                for (int mi = 0; mi < 4; mi++)
#pragma unroll
                    for (int ni = 0; ni < 4; ni++)
                        mma_tf32(acc[mi][ni], af[mi], bf[ni]);
            }
        }
    }

    float* Yb = Yattn + ((long)bn * Sq + c * CHq) * HDq;
#pragma unroll
    for (int mi = 0; mi < 4; mi++) {
        int r0 = wy * 64 + mi * 16 + gid, r1 = r0 + 8;
#pragma unroll
        for (int ni = 0; ni < 4; ni++) {
            int c0 = wx * 32 + ni * 8 + tig * 2;
            *(float2*)(Yb + (long)r0 * HDq + c0) = make_float2(acc[mi][ni][0], acc[mi][ni][1]);
            *(float2*)(Yb + (long)r1 * HDq + c0) = make_float2(acc[mi][ni][2], acc[mi][ni][3]);
        }
    }
}

// ---------------- group norm over HD per head + swish gate -----------------
__global__ __launch_bounds__(128) void gnorm_gate_kernel(const float* __restrict__ Yattn,
                                                         const float* __restrict__ G,
                                                         const float* __restrict__ gnw,
                                                         const float* __restrict__ gnb,
                                                         float* __restrict__ out) {
    int bid = blockIdx.x;          // (b*S+s)*NH + n
    int n = bid % NHq;
    long bs = bid / NHq;
    long b = bs / Sq, s = bs % Sq;
    int d = threadIdx.x;
    __shared__ float red[4];
    float y = Yattn[(((long)(b * NHq + n)) * Sq + s) * HDq + d];
    float m = blockReduceSum(y, red) * (1.f / HDq);
    float dd = y - m;
    float var = blockReduceSum(dd * dd, red) * (1.f / HDq);
    float yn = dd * rsqrtf(var + EPSq) * gnw[n * HDq + d] + gnb[n * HDq + d];
    float g = G[bs * Hq + n * HDq + d];
    float sw = g / (1.f + expf(-g));
    out[bs * Hq + n * HDq + d] = sw * yn;
}

// ---------------- plain copy -----------------------------------------------
__global__ void copy_kernel(const float* __restrict__ src, float* __restrict__ dst, long nTot) {
    long i = (long)blockIdx.x * blockDim.x + threadIdx.x;
    if (i < nTot) dst[i] = src[i];
}

// ============================================================================
extern "C" void kernel_launch(void* const* d_in, const int* in_sizes, int n_in,
                              void* d_out, int out_size) {
    const float* Xin  = (const float*)d_in[0];
    const float* WQ   = (const float*)d_in[1];
    const float* WK   = (const float*)d_in[2];
    const float* WV   = (const float*)d_in[3];
    const float* WG   = (const float*)d_in[4];
    const float* WO   = (const float*)d_in[5];
    const float* gn_w = (const float*)d_in[6];
    const float* gn_b = (const float*)d_in[7];
    const float* ln1w = (const float*)d_in[8];
    const float* ln1b = (const float*)d_in[9];
    const float* ln2w = (const float*)d_in[10];
    const float* ln2b = (const float*)d_in[11];
    const float* fw1  = (const float*)d_in[12];
    const float* fb1  = (const float*)d_in[13];
    const float* fw2  = (const float*)d_in[14];
    const float* fb2  = (const float*)d_in[15];
    float* out = (float*)d_out;

    float *pXn, *pQ, *pK, *pV, *pG, *pGated, *pY, *pHn, *pX, *pYa, *pM, *pSt, *pHf;
    cudaGetSymbolAddress((void**)&pXn, g_Xn);
    cudaGetSymbolAddress((void**)&pQ, g_Q);
    cudaGetSymbolAddress((void**)&pK, g_K);
    cudaGetSymbolAddress((void**)&pV, g_V);
    cudaGetSymbolAddress((void**)&pG, g_G);
    cudaGetSymbolAddress((void**)&pGated, g_Gated);
    cudaGetSymbolAddress((void**)&pY, g_Y);
    cudaGetSymbolAddress((void**)&pHn, g_Hn);
    cudaGetSymbolAddress((void**)&pX, g_X);
    cudaGetSymbolAddress((void**)&pYa, g_Yattn);
    cudaGetSymbolAddress((void**)&pM, g_M);
    cudaGetSymbolAddress((void**)&pSt, g_St);
    cudaGetSymbolAddress((void**)&pHf, g_Hf);

    const int smemCO = (128 * PAsm + 2 * 128 * PA) * 4;  // 88064 B
    cudaFuncSetAttribute(chunk_out_kernel, cudaFuncAttributeMaxDynamicSharedMemorySize, smemCO);

    const float* cur = Xin;
    for (int l = 0; l < Lq; l++) {
        // 1. LN1
        ln_kernel<<<BSq, 256>>>(cur, ln1w + (long)l * Hq, ln1b + (long)l * Hq, pXn);
        // 2. Q,K,V per-head GEMMs with fused xpos; G GEMM
        mma_gemm_kernel<<<dim3(1, BSq / 128, NHq), 256>>>(pXn, WQ + (long)l * NHq * Hq * HDq, pQ,
            BSq, HDq, Hq, Hq, HDq, Hq, 0, (long)Hq * HDq, HDq, nullptr, nullptr, 2, 0);
        mma_gemm_kernel<<<dim3(1, BSq / 128, NHq), 256>>>(pXn, WK + (long)l * NHq * Hq * HDq, pK,
            BSq, HDq, Hq, Hq, HDq, Hq, 0, (long)Hq * HDq, HDq, nullptr, nullptr, 3, 0);
        mma_gemm_kernel<<<dim3(1, BSq / 128, NHq), 256>>>(pXn, WV + (long)l * NHq * Hq * HDq, pV,
            BSq, HDq, Hq, Hq, HDq, Hq, 0, (long)Hq * HDq, HDq, nullptr, nullptr, 0, 0);
        mma_gemm_kernel<<<dim3(Hq / 128, BSq / 128, 1), 256>>>(pXn, WG + (long)l * Hq * Hq, pG,
            BSq, Hq, Hq, Hq, Hq, Hq, 0, 0, 0, nullptr, nullptr, 0, 0);
        // 3. retention (exact chunked linear form, tf32 mma)
        chunk_kv_kernel<<<Bq * NHq * NCq, 256>>>(pK, pV, pM);
        scan_kernel<<<(Bq * NHq * HDq * HDq) / 256, 256>>>(pM, pSt);
        chunk_out_kernel<<<Bq * NHq * NCq, 256, smemCO>>>(pQ, pK, pV, pSt, pYa);
        // 4. group norm + swish gate
        gnorm_gate_kernel<<<BSq * NHq, 128>>>(pYa, pG, gn_w + (long)l * Hq, gn_b + (long)l * Hq, pGated);
        // 5. O-proj + residual
        mma_gemm_kernel<<<dim3(Hq / 128, BSq / 128, 1), 256>>>(pGated, WO + (long)l * Hq * Hq, pY,
            BSq, Hq, Hq, Hq, Hq, Hq, 0, 0, 0, nullptr, cur, 0, 0);
        // 6. LN2
        ln_kernel<<<BSq, 256>>>(pY, ln2w + (long)l * Hq, ln2b + (long)l * Hq, pHn);
        // 7. FFN1 (+bias, exact gelu)
        mma_gemm_kernel<<<dim3(FFNq / 128, BSq / 128, 1), 256>>>(pHn, fw1 + (long)l * Hq * FFNq, pHf,
            BSq, FFNq, Hq, Hq, FFNq, FFNq, 0, 0, 0, fb1 + (long)l * FFNq, nullptr, 1, 0);
        // 8. FFN2 (+bias, +residual Y)
        mma_gemm_kernel<<<dim3(Hq / 128, BSq / 128, 1), 256>>>(pHf, fw2 + (long)l * FFNq * Hq, pX,
            BSq, Hq, FFNq, FFNq, Hq, Hq, 0, 0, 0, fb2 + (long)l * Hq, pY, 0, 0);
        cur = pX;
    }

    // output 0: X
    long nX = (long)BSq * Hq;
    copy_kernel<<<(int)((nX + 255) / 256), 256>>>(pX, out, nX);
    // output 1: per-batch X @ X^T (NT GEMM)
    mma_gemm_kernel<<<dim3(Sq / 128, Sq / 128, Bq), 256>>>(pX, pX, out + nX,
        Sq, Sq, Hq, Hq, Hq, Sq,
        (long)Sq * Hq, (long)Sq * Hq, (long)Sq * Sq,
        nullptr, nullptr, 0, 1);
}

// round 6
// speedup vs baseline: 2.9795x; 1.2487x over previous
#include <cuda_runtime.h>
#include <cuda_fp16.h>
#include <math.h>
#include <stdint.h>

#define Bq   4
#define Sq   2048
#define Hq   512
#define NHq  4
#define HDq  128
#define FFNq 2048
#define Lq   3
#define BSq  (Bq*Sq)
#define CHq  128
#define NCq  (Sq/CHq)
#define EPSq 1e-5f
#define PA   20
#define PAsm 132
#define PH   40    // half-precision smem pitch (conflict-free fragment LDS)

__device__ float g_Xn[BSq*Hq];
__device__ float g_Q[BSq*Hq];
__device__ float g_K[BSq*Hq];
__device__ float g_V[BSq*Hq];
__device__ float g_G[BSq*Hq];
__device__ float g_Gated[BSq*Hq];
__device__ float g_Y[BSq*Hq];
__device__ float g_Hn[BSq*Hq];
__device__ float g_X[BSq*Hq];
__device__ float g_Yattn[BSq*Hq];
__device__ float g_M[Bq*NHq*NCq*HDq*HDq];
__device__ float g_St[Bq*NHq*NCq*HDq*HDq];
__device__ float g_Hf[BSq*FFNq];
__device__ float g_WQT[Lq*NHq*HDq*Hq];
__device__ float g_WKT[Lq*NHq*HDq*Hq];
__device__ float g_WVT[Lq*NHq*HDq*Hq];
__device__ float g_WGT[Lq*Hq*Hq];
__device__ float g_WOT[Lq*Hq*Hq];
__device__ float g_W1T[Lq*FFNq*Hq];
__device__ float g_W2T[Lq*Hq*FFNq];

__device__ __forceinline__ float gamma_of(int n) {
    double lg = -3.4657359027997265 + (double)n * (-0.9241962407465937);
    return (float)(1.0 - exp(lg));
}
__device__ __forceinline__ uint32_t f2tf(float x) {
    uint32_t y;
    asm("cvt.rna.tf32.f32 %0, %1;" : "=r"(y) : "f"(x));
    return y;
}
__device__ __forceinline__ uint32_t pack2(float a, float b) {
    __half2 h = __floats2half2_rn(a, b);
    return *(uint32_t*)&h;
}
__device__ __forceinline__ void mma_tf32(float* c, const uint32_t* a, const uint32_t* b) {
    asm volatile(
        "mma.sync.aligned.m16n8k8.row.col.f32.tf32.tf32.f32 "
        "{%0,%1,%2,%3}, {%4,%5,%6,%7}, {%8,%9}, {%0,%1,%2,%3};"
        : "+f"(c[0]), "+f"(c[1]), "+f"(c[2]), "+f"(c[3])
        : "r"(a[0]), "r"(a[1]), "r"(a[2]), "r"(a[3]), "r"(b[0]), "r"(b[1]));
}
__device__ __forceinline__ void mma_f16(float* c, const uint32_t* a, const uint32_t* b) {
    asm volatile(
        "mma.sync.aligned.m16n8k16.row.col.f32.f16.f16.f32 "
        "{%0,%1,%2,%3}, {%4,%5,%6,%7}, {%8,%9}, {%0,%1,%2,%3};"
        : "+f"(c[0]), "+f"(c[1]), "+f"(c[2]), "+f"(c[3])
        : "r"(a[0]), "r"(a[1]), "r"(a[2]), "r"(a[3]), "r"(b[0]), "r"(b[1]));
}

// =========== fp16 tensor-core NT GEMM: C[M,Ntile]=A[M,K]*Bt[N,K]^T =========
// 128x128x32 tiles, 8 warps (2x4), warp tile 64x32, double-buffered.
// act: 0 none, 1 gelu, 2 xpos Q, 3 xpos K (N==128, bn==0 for xpos).
__global__ __launch_bounds__(256, 2) void h_gemm_kernel(
    const float* __restrict__ A, const float* __restrict__ Bt, float* __restrict__ C,
    int K, int lda, int ldb, int ldc,
    long aStride, long bStride, long cStride,
    const float* __restrict__ bias, const float* __restrict__ res, int act)
{
    __shared__ __align__(16) __half smA[2][128 * PH];
    __shared__ __align__(16) __half smB[2][128 * PH];
    int z = blockIdx.z;
    A  += z * aStride;
    Bt += z * bStride;
    C  += z * cStride;
    if (res) res += z * cStride;
    int bm = blockIdx.y * 128, bn = blockIdx.x * 128;
    int tid = threadIdx.x;
    int lane = tid & 31, warp = tid >> 5;
    int gid = lane >> 2, tig = lane & 3;
    int wy = warp >> 2, wx = warp & 3;

    float acc[4][4][4];
#pragma unroll
    for (int i = 0; i < 4; i++)
#pragma unroll
        for (int j = 0; j < 4; j++)
#pragma unroll
            for (int k = 0; k < 4; k++) acc[i][j][k] = 0.f;

    int lr = tid >> 1, lkh = (tid & 1) * 16;
    uint32_t ra[8], rb[8];

#define HLOAD(k0)                                                              \
    {                                                                          \
        const float* ap = A + (long)(bm + lr) * lda + (k0) + lkh;              \
        float4 a0 = *(const float4*)(ap),     a1 = *(const float4*)(ap + 4);   \
        float4 a2 = *(const float4*)(ap + 8), a3 = *(const float4*)(ap + 12);  \
        ra[0] = pack2(a0.x, a0.y); ra[1] = pack2(a0.z, a0.w);                  \
        ra[2] = pack2(a1.x, a1.y); ra[3] = pack2(a1.z, a1.w);                  \
        ra[4] = pack2(a2.x, a2.y); ra[5] = pack2(a2.z, a2.w);                  \
        ra[6] = pack2(a3.x, a3.y); ra[7] = pack2(a3.z, a3.w);                  \
        const float* bp = Bt + (long)(bn + lr) * ldb + (k0) + lkh;             \
        float4 b0 = *(const float4*)(bp),     b1 = *(const float4*)(bp + 4);   \
        float4 b2 = *(const float4*)(bp + 8), b3 = *(const float4*)(bp + 12);  \
        rb[0] = pack2(b0.x, b0.y); rb[1] = pack2(b0.z, b0.w);                  \
        rb[2] = pack2(b1.x, b1.y); rb[3] = pack2(b1.z, b1.w);                  \
        rb[4] = pack2(b2.x, b2.y); rb[5] = pack2(b2.z, b2.w);                  \
        rb[6] = pack2(b3.x, b3.y); rb[7] = pack2(b3.z, b3.w);                  \
    }

#define HSTORE(p)                                                              \
    {                                                                          \
        *(uint4*)&smA[p][lr * PH + lkh]     = make_uint4(ra[0], ra[1], ra[2], ra[3]); \
        *(uint4*)&smA[p][lr * PH + lkh + 8] = make_uint4(ra[4], ra[5], ra[6], ra[7]); \
        *(uint4*)&smB[p][lr * PH + lkh]     = make_uint4(rb[0], rb[1], rb[2], rb[3]); \
        *(uint4*)&smB[p][lr * PH + lkh + 8] = make_uint4(rb[4], rb[5], rb[6], rb[7]); \
    }

#define HCOMP(p)                                                               \
    _Pragma("unroll")                                                          \
    for (int ks = 0; ks < 2; ks++) {                                           \
        uint32_t af[4][4], bf[4][2];                                           \
        _Pragma("unroll")                                                      \
        for (int mi = 0; mi < 4; mi++) {                                       \
            int base = (wy * 64 + mi * 16 + gid) * PH + ks * 16 + tig * 2;     \
            af[mi][0] = *(uint32_t*)&smA[p][base];                             \
            af[mi][1] = *(uint32_t*)&smA[p][base + 8 * PH];                    \
            af[mi][2] = *(uint32_t*)&smA[p][base + 8];                         \
            af[mi][3] = *(uint32_t*)&smA[p][base + 8 * PH + 8];                \
        }                                                                      \
        _Pragma("unroll")                                                      \
        for (int ni = 0; ni < 4; ni++) {                                       \
            int nb = (wx * 32 + ni * 8 + gid) * PH + ks * 16 + tig * 2;        \
            bf[ni][0] = *(uint32_t*)&smB[p][nb];                               \
            bf[ni][1] = *(uint32_t*)&smB[p][nb + 8];                           \
        }                                                                      \
        _Pragma("unroll")                                                      \
        for (int mi = 0; mi < 4; mi++)                                         \
            _Pragma("unroll")                                                  \
            for (int ni = 0; ni < 4; ni++)                                     \
                mma_f16(acc[mi][ni], af[mi], bf[ni]);                          \
    }

    HLOAD(0)
    HSTORE(0)
    __syncthreads();
    int p = 0;
    for (int k0 = 32;; k0 += 32) {
        bool more = (k0 < K);
        if (more) HLOAD(k0)
        HCOMP(p)
        if (!more) break;
        HSTORE(p ^ 1)
        __syncthreads();
        p ^= 1;
    }

    // epilogue
#pragma unroll
    for (int mi = 0; mi < 4; mi++) {
        long r0 = bm + wy * 64 + mi * 16 + gid;
        long r1 = r0 + 8;
#pragma unroll
        for (int ni = 0; ni < 4; ni++) {
            int c0 = bn + wx * 32 + ni * 8 + tig * 2;
            float v00 = acc[mi][ni][0], v01 = acc[mi][ni][1];
            float v10 = acc[mi][ni][2], v11 = acc[mi][ni][3];
            if (bias) {
                float b0 = bias[c0], b1 = bias[c0 + 1];
                v00 += b0; v01 += b1; v10 += b0; v11 += b1;
            }
            if (act == 1) {
                v00 = 0.5f * v00 * (1.f + erff(v00 * 0.70710678118654752f));
                v01 = 0.5f * v01 * (1.f + erff(v01 * 0.70710678118654752f));
                v10 = 0.5f * v10 * (1.f + erff(v10 * 0.70710678118654752f));
                v11 = 0.5f * v11 * (1.f + erff(v11 * 0.70710678118654752f));
            } else if (act >= 2) {
                float fi = (float)(c0 >> 1);
                float lsb = log2f((fi + 51.2f) * (1.f / 179.2f));
                if (act == 3) lsb = -lsb;
                float invf = exp2f(fi * (-0.20761871093296528f));
#pragma unroll
                for (int rr = 0; rr < 2; rr++) {
                    float pp = (float)((rr ? r1 : r0) & (Sq - 1));
                    float sc = exp2f(lsb * pp * (1.f / 512.f));
                    float s_, c_;
                    sincosf(pp * invf, &s_, &c_);
                    c_ *= sc; s_ *= sc;
                    if (rr == 0) {
                        float t0 = v00 * c_ - v01 * s_;
                        v01 = v01 * c_ + v00 * s_;
                        v00 = t0;
                    } else {
                        float t0 = v10 * c_ - v11 * s_;
                        v11 = v11 * c_ + v10 * s_;
                        v10 = t0;
                    }
                }
            }
            if (res) {
                v00 += res[r0 * ldc + c0]; v01 += res[r0 * ldc + c0 + 1];
                v10 += res[r1 * ldc + c0]; v11 += res[r1 * ldc + c0 + 1];
            }
            *(float2*)(C + r0 * ldc + c0) = make_float2(v00, v01);
            *(float2*)(C + r1 * ldc + c0) = make_float2(v10, v11);
        }
    }
#undef HLOAD
#undef HSTORE
#undef HCOMP
}

// ---------------- transpose out[c][r] = in[r][c], z-batched -----------------
__global__ __launch_bounds__(256) void transpose_kernel(const float* __restrict__ in,
                                                        float* __restrict__ out, int R, int C) {
    __shared__ float t[32][33];
    long z = blockIdx.z;
    in  += z * (long)R * C;
    out += z * (long)R * C;
    int bx = blockIdx.x * 32, by = blockIdx.y * 32;
    int tx = threadIdx.x & 31, ty = threadIdx.x >> 5;
#pragma unroll
    for (int i = 0; i < 32; i += 8)
        t[ty + i][tx] = in[(long)(by + ty + i) * C + bx + tx];
    __syncthreads();
#pragma unroll
    for (int i = 0; i < 32; i += 8)
        out[(long)(bx + ty + i) * R + by + tx] = t[tx][ty + i];
}

__device__ __forceinline__ float blockReduceSum(float v, volatile float* red) {
    int tid = threadIdx.x;
#pragma unroll
    for (int o = 16; o > 0; o >>= 1) v += __shfl_xor_sync(0xffffffffu, v, o);
    if ((tid & 31) == 0) red[tid >> 5] = v;
    __syncthreads();
    if (tid == 0) {
        float s = 0.f;
        int nw = blockDim.x >> 5;
        for (int i = 0; i < nw; i++) s += red[i];
        red[0] = s;
    }
    __syncthreads();
    float r = red[0];
    __syncthreads();
    return r;
}

__global__ __launch_bounds__(256) void ln_kernel(const float* __restrict__ X,
                                                 const float* __restrict__ w,
                                                 const float* __restrict__ b,
                                                 float* __restrict__ out) {
    long row = blockIdx.x;
    const float* x = X + row * Hq;
    __shared__ float red[8];
    int tid = threadIdx.x;
    float v0 = x[tid], v1 = x[tid + 256];
    float m = blockReduceSum(v0 + v1, red) * (1.f / Hq);
    float d0 = v0 - m, d1 = v1 - m;
    float var = blockReduceSum(d0 * d0 + d1 * d1, red) * (1.f / Hq);
    float inv = rsqrtf(var + EPSq);
    out[row * Hq + tid]       = d0 * inv * w[tid]       + b[tid];
    out[row * Hq + tid + 256] = d1 * inv * w[tid + 256] + b[tid + 256];
}

// ---------------- retention pass A: per-chunk decayed KV (tf32 mma) --------
__global__ __launch_bounds__(256) void chunk_kv_kernel(const float* __restrict__ Kd,
                                                       const float* __restrict__ Vd,
                                                       float* __restrict__ Mout) {
    __shared__ uint32_t KT[128 * PA];
    __shared__ uint32_t VT[128 * PA];
    int bid = blockIdx.x;
    int bn = bid / NCq, c = bid % NCq;
    int b = bn >> 2, n = bn & 3;
    float lgam = logf(gamma_of(n));
    const float* Kb = Kd + ((long)(b * Sq + c * CHq)) * Hq + n * HDq;
    const float* Vb = Vd + ((long)(b * Sq + c * CHq)) * Hq + n * HDq;
    int tid = threadIdx.x;
    int lane = tid & 31, warp = tid >> 5;
    int gid = lane >> 2, tig = lane & 3;
    int wy = warp >> 2, wx = warp & 3;
    float acc[4][4][4];
#pragma unroll
    for (int i = 0; i < 4; i++)
#pragma unroll
        for (int j = 0; j < 4; j++)
#pragma unroll
            for (int k = 0; k < 4; k++) acc[i][j][k] = 0.f;
    int jj = tid >> 4, dbase = (tid & 15) * 8;
    int jjs = jj ^ (tid & 15);
    for (int j0 = 0; j0 < CHq; j0 += 16) {
        int j = j0 + jj;
        float w = expf((float)(127 - j) * lgam);
        const float* kp = Kb + (long)j * Hq + dbase;
        float4 k0 = *(const float4*)(kp), k1 = *(const float4*)(kp + 4);
        const float* vp = Vb + (long)j * Hq + dbase;
        float4 v0 = *(const float4*)(vp), v1 = *(const float4*)(vp + 4);
        __syncthreads();
        KT[(dbase + 0) * PA + jjs] = f2tf(k0.x * w);
        KT[(dbase + 1) * PA + jjs] = f2tf(k0.y * w);
        KT[(dbase + 2) * PA + jjs] = f2tf(k0.z * w);
        KT[(dbase + 3) * PA + jjs] = f2tf(k0.w * w);
        KT[(dbase + 4) * PA + jjs] = f2tf(k1.x * w);
        KT[(dbase + 5) * PA + jjs] = f2tf(k1.y * w);
        KT[(dbase + 6) * PA + jjs] = f2tf(k1.z * w);
        KT[(dbase + 7) * PA + jjs] = f2tf(k1.w * w);
        VT[(dbase + 0) * PA + jjs] = f2tf(v0.x);
        VT[(dbase + 1) * PA + jjs] = f2tf(v0.y);
        VT[(dbase + 2) * PA + jjs] = f2tf(v0.z);
        VT[(dbase + 3) * PA + jjs] = f2tf(v0.w);
        VT[(dbase + 4) * PA + jjs] = f2tf(v1.x);
        VT[(dbase + 5) * PA + jjs] = f2tf(v1.y);
        VT[(dbase + 6) * PA + jjs] = f2tf(v1.z);
        VT[(dbase + 7) * PA + jjs] = f2tf(v1.w);
        __syncthreads();
#pragma unroll
        for (int kk = 0; kk < 16; kk += 8) {
            uint32_t af[4][4], bf[4][2];
#pragma unroll
            for (int mi = 0; mi < 4; mi++) {
                int m = wy * 64 + mi * 16 + gid;
                int sw = m >> 3, sw2 = (m + 8) >> 3;
                af[mi][0] = KT[m * PA + ((kk + tig) ^ sw)];
                af[mi][1] = KT[(m + 8) * PA + ((kk + tig) ^ sw2)];
                af[mi][2] = KT[m * PA + ((kk + tig + 4) ^ sw)];
                af[mi][3] = KT[(m + 8) * PA + ((kk + tig + 4) ^ sw2)];
            }
#pragma unroll
            for (int ni = 0; ni < 4; ni++) {
                int nb = wx * 32 + ni * 8 + gid;
                int sw = nb >> 3;
                bf[ni][0] = VT[nb * PA + ((kk + tig) ^ sw)];
                bf[ni][1] = VT[nb * PA + ((kk + tig + 4) ^ sw)];
            }
#pragma unroll
            for (int mi = 0; mi < 4; mi++)
#pragma unroll
                for (int ni = 0; ni < 4; ni++)
                    mma_tf32(acc[mi][ni], af[mi], bf[ni]);
        }
    }
    float* Mo = Mout + (long)bid * (HDq * HDq);
#pragma unroll
    for (int mi = 0; mi < 4; mi++) {
        int r0 = wy * 64 + mi * 16 + gid, r1 = r0 + 8;
#pragma unroll
        for (int ni = 0; ni < 4; ni++) {
            int c0 = wx * 32 + ni * 8 + tig * 2;
            *(float2*)(Mo + r0 * HDq + c0) = make_float2(acc[mi][ni][0], acc[mi][ni][1]);
            *(float2*)(Mo + r1 * HDq + c0) = make_float2(acc[mi][ni][2], acc[mi][ni][3]);
        }
    }
}

__global__ __launch_bounds__(256) void scan_kernel(const float* __restrict__ M,
                                                   float* __restrict__ St) {
    long idx = (long)blockIdx.x * blockDim.x + threadIdx.x;
    int bn = (int)(idx >> 14);
    int n = bn & 3;
    float gamma = gamma_of(n);
    float gC = expf(128.f * logf(gamma));
    long e = idx & 16383;
    float s = 0.f;
    for (int c = 0; c < NCq; c++) {
        long off = ((long)bn * NCq + c) * 16384 + e;
        St[off] = s;
        s = s * gC + M[off];
    }
}

// ---------------- retention pass C: chunk output (tf32 mma, 3 phases) ------
__global__ __launch_bounds__(256) void chunk_out_kernel(const float* __restrict__ Qd,
                                                        const float* __restrict__ Kd,
                                                        const float* __restrict__ Vd,
                                                        const float* __restrict__ States,
                                                        float* __restrict__ Yattn) {
    extern __shared__ uint32_t dsm[];
    uint32_t* Asm = dsm;
    uint32_t* T1  = dsm + 128 * PAsm;
    uint32_t* T2  = T1 + 128 * PA;
    int bid = blockIdx.x;
    int bn = bid / NCq, c = bid % NCq;
    int b = bn >> 2, n = bn & 3;
    float lgam = logf(gamma_of(n));
    const float* Qb = Qd + ((long)(b * Sq + c * CHq)) * Hq + n * HDq;
    const float* Kb = Kd + ((long)(b * Sq + c * CHq)) * Hq + n * HDq;
    const float* Vb = Vd + ((long)(b * Sq + c * CHq)) * Hq + n * HDq;
    const float* Sb = States + ((long)bn * NCq + c) * 16384;
    int tid = threadIdx.x;
    int lane = tid & 31, warp = tid >> 5;
    int gid = lane >> 2, tig = lane & 3;
    int wy = warp >> 2, wx = warp & 3;
    float acc[4][4][4];
#pragma unroll
    for (int i = 0; i < 4; i++)
#pragma unroll
        for (int j = 0; j < 4; j++)
#pragma unroll
            for (int k = 0; k < 4; k++) acc[i][j][k] = 0.f;
    int lr = tid >> 1, lc = (tid & 1) * 8;
    int jj = tid >> 4, dbase = (tid & 15) * 8;
    int jjs = jj ^ (tid & 15);

    // phase 1: scores = Q K^T
    for (int d0 = 0; d0 < HDq; d0 += 16) {
        const float* qp = Qb + (long)lr * Hq + d0 + lc;
        float4 q0 = *(const float4*)(qp), q1 = *(const float4*)(qp + 4);
        const float* kp = Kb + (long)lr * Hq + d0 + lc;
        float4 k0 = *(const float4*)(kp), k1 = *(const float4*)(kp + 4);
        __syncthreads();
        *(uint4*)&T1[lr * PA + lc]     = make_uint4(f2tf(q0.x), f2tf(q0.y), f2tf(q0.z), f2tf(q0.w));
        *(uint4*)&T1[lr * PA + lc + 4] = make_uint4(f2tf(q1.x), f2tf(q1.y), f2tf(q1.z), f2tf(q1.w));
        *(uint4*)&T2[lr * PA + lc]     = make_uint4(f2tf(k0.x), f2tf(k0.y), f2tf(k0.z), f2tf(k0.w));
        *(uint4*)&T2[lr * PA + lc + 4] = make_uint4(f2tf(k1.x), f2tf(k1.y), f2tf(k1.z), f2tf(k1.w));
        __syncthreads();
#pragma unroll
        for (int kk = 0; kk < 16; kk += 8) {
            uint32_t af[4][4], bf[4][2];
#pragma unroll
            for (int mi = 0; mi < 4; mi++) {
                int mb = (wy * 64 + mi * 16 + gid) * PA + kk + tig;
                af[mi][0] = T1[mb]; af[mi][1] = T1[mb + 8 * PA];
                af[mi][2] = T1[mb + 4]; af[mi][3] = T1[mb + 8 * PA + 4];
            }
#pragma unroll
            for (int ni = 0; ni < 4; ni++) {
                int nb = (wx * 32 + ni * 8 + gid) * PA + kk + tig;
                bf[ni][0] = T2[nb]; bf[ni][1] = T2[nb + 4];
            }
#pragma unroll
            for (int mi = 0; mi < 4; mi++)
#pragma unroll
                for (int ni = 0; ni < 4; ni++)
                    mma_tf32(acc[mi][ni], af[mi], bf[ni]);
        }
    }
    {
        float pj[8], pk[8];
#pragma unroll
        for (int mi = 0; mi < 4; mi++) {
            int r0 = wy * 64 + mi * 16 + gid;
            pj[mi * 2]     = expf((float)r0 * lgam);
            pj[mi * 2 + 1] = expf((float)(r0 + 8) * lgam);
        }
#pragma unroll
        for (int ni = 0; ni < 4; ni++) {
            int c0 = wx * 32 + ni * 8 + tig * 2;
            pk[ni * 2]     = expf((float)(-c0) * lgam);
            pk[ni * 2 + 1] = expf((float)(-(c0 + 1)) * lgam);
        }
        __syncthreads();
#pragma unroll
        for (int mi = 0; mi < 4; mi++) {
            int r0 = wy * 64 + mi * 16 + gid, r1 = r0 + 8;
#pragma unroll
            for (int ni = 0; ni < 4; ni++) {
                int c0 = wx * 32 + ni * 8 + tig * 2;
                float v00 = (r0 >= c0)     ? acc[mi][ni][0] * pj[mi*2]   * pk[ni*2]   : 0.f;
                float v01 = (r0 >= c0 + 1) ? acc[mi][ni][1] * pj[mi*2]   * pk[ni*2+1] : 0.f;
                float v10 = (r1 >= c0)     ? acc[mi][ni][2] * pj[mi*2+1] * pk[ni*2]   : 0.f;
                float v11 = (r1 >= c0 + 1) ? acc[mi][ni][3] * pj[mi*2+1] * pk[ni*2+1] : 0.f;
                Asm[r0 * PAsm + c0]     = f2tf(v00);
                Asm[r0 * PAsm + c0 + 1] = f2tf(v01);
                Asm[r1 * PAsm + c0]     = f2tf(v10);
                Asm[r1 * PAsm + c0 + 1] = f2tf(v11);
                acc[mi][ni][0] = acc[mi][ni][1] = acc[mi][ni][2] = acc[mi][ni][3] = 0.f;
            }
        }
    }
    __syncthreads();

    // phase 2: Y = scores * V
    for (int j0 = 0; j0 < CHq; j0 += 16) {
        const float* vp = Vb + (long)(j0 + jj) * Hq + dbase;
        float4 v0 = *(const float4*)(vp), v1 = *(const float4*)(vp + 4);
        __syncthreads();
        T2[(dbase + 0) * PA + jjs] = f2tf(v0.x);
        T2[(dbase + 1) * PA + jjs] = f2tf(v0.y);
        T2[(dbase + 2) * PA + jjs] = f2tf(v0.z);
        T2[(dbase + 3) * PA + jjs] = f2tf(v0.w);
        T2[(dbase + 4) * PA + jjs] = f2tf(v1.x);
        T2[(dbase + 5) * PA + jjs] = f2tf(v1.y);
        T2[(dbase + 6) * PA + jjs] = f2tf(v1.z);
        T2[(dbase + 7) * PA + jjs] = f2tf(v1.w);
        __syncthreads();
#pragma unroll
        for (int kk = 0; kk < 16; kk += 8) {
            uint32_t af[4][4], bf[4][2];
#pragma unroll
            for (int mi = 0; mi < 4; mi++) {
                int mb = (wy * 64 + mi * 16 + gid) * PAsm + j0 + kk + tig;
                af[mi][0] = Asm[mb]; af[mi][1] = Asm[mb + 8 * PAsm];
                af[mi][2] = Asm[mb + 4]; af[mi][3] = Asm[mb + 8 * PAsm + 4];
            }
#pragma unroll
            for (int ni = 0; ni < 4; ni++) {
                int nb = wx * 32 + ni * 8 + gid;
                int sw = nb >> 3;
                bf[ni][0] = T2[nb * PA + ((kk + tig) ^ sw)];
                bf[ni][1] = T2[nb * PA + ((kk + tig + 4) ^ sw)];
            }
#pragma unroll
            for (int mi = 0; mi < 4; mi++)
#pragma unroll
                for (int ni = 0; ni < 4; ni++)
                    mma_tf32(acc[mi][ni], af[mi], bf[ni]);
        }
    }

    // phase 3: Y += diag(gamma^{j+1}) Q * State
    {
        float wrow = expf((float)(lr + 1) * lgam);
        for (int e0 = 0; e0 < HDq; e0 += 16) {
            const float* qp = Qb + (long)lr * Hq + e0 + lc;
            float4 q0 = *(const float4*)(qp), q1 = *(const float4*)(qp + 4);
            const float* sp = Sb + (long)(e0 + jj) * HDq + dbase;
            float4 s0 = *(const float4*)(sp), s1 = *(const float4*)(sp + 4);
            __syncthreads();
            *(uint4*)&T1[lr * PA + lc]     = make_uint4(f2tf(q0.x * wrow), f2tf(q0.y * wrow), f2tf(q0.z * wrow), f2tf(q0.w * wrow));
            *(uint4*)&T1[lr * PA + lc + 4] = make_uint4(f2tf(q1.x * wrow), f2tf(q1.y * wrow), f2tf(q1.z * wrow), f2tf(q1.w * wrow));
            T2[(dbase + 0) * PA + jjs] = f2tf(s0.x);
            T2[(dbase + 1) * PA + jjs] = f2tf(s0.y);
            T2[(dbase + 2) * PA + jjs] = f2tf(s0.z);
            T2[(dbase + 3) * PA + jjs] = f2tf(s0.w);
            T2[(dbase + 4) * PA + jjs] = f2tf(s1.x);
            T2[(dbase + 5) * PA + jjs] = f2tf(s1.y);
            T2[(dbase + 6) * PA + jjs] = f2tf(s1.z);
            T2[(dbase + 7) * PA + jjs] = f2tf(s1.w);
            __syncthreads();
#pragma unroll
            for (int kk = 0; kk < 16; kk += 8) {
                uint32_t af[4][4], bf[4][2];
#pragma unroll
                for (int mi = 0; mi < 4; mi++) {
                    int mb = (wy * 64 + mi * 16 + gid) * PA + kk + tig;
                    af[mi][0] = T1[mb]; af[mi][1] = T1[mb + 8 * PA];
                    af[mi][2] = T1[mb + 4]; af[mi][3] = T1[mb + 8 * PA + 4];
                }
#pragma unroll
                for (int ni = 0; ni < 4; ni++) {
                    int nb = wx * 32 + ni * 8 + gid;
                    int sw = nb >> 3;
                    bf[ni][0] = T2[nb * PA + ((kk + tig) ^ sw)];
                    bf[ni][1] = T2[nb * PA + ((kk + tig + 4) ^ sw)];
                }
#pragma unroll
                for (int mi = 0; mi < 4; mi++)
#pragma unroll
                    for (int ni = 0; ni < 4; ni++)
                        mma_tf32(acc[mi][ni], af[mi], bf[ni]);
            }
        }
    }

    float* Yb = Yattn + ((long)bn * Sq + c * CHq) * HDq;
#pragma unroll
    for (int mi = 0; mi < 4; mi++) {
        int r0 = wy * 64 + mi * 16 + gid, r1 = r0 + 8;
#pragma unroll
        for (int ni = 0; ni < 4; ni++) {
            int c0 = wx * 32 + ni * 8 + tig * 2;
            *(float2*)(Yb + (long)r0 * HDq + c0) = make_float2(acc[mi][ni][0], acc[mi][ni][1]);
            *(float2*)(Yb + (long)r1 * HDq + c0) = make_float2(acc[mi][ni][2], acc[mi][ni][3]);
        }
    }
}

__global__ __launch_bounds__(128) void gnorm_gate_kernel(const float* __restrict__ Yattn,
                                                         const float* __restrict__ G,
                                                         const float* __restrict__ gnw,
                                                         const float* __restrict__ gnb,
                                                         float* __restrict__ out) {
    int bid = blockIdx.x;
    int n = bid % NHq;
    long bs = bid / NHq;
    long b = bs / Sq, s = bs % Sq;
    int d = threadIdx.x;
    __shared__ float red[4];
    float y = Yattn[(((long)(b * NHq + n)) * Sq + s) * HDq + d];
    float m = blockReduceSum(y, red) * (1.f / HDq);
    float dd = y - m;
    float var = blockReduceSum(dd * dd, red) * (1.f / HDq);
    float yn = dd * rsqrtf(var + EPSq) * gnw[n * HDq + d] + gnb[n * HDq + d];
    float g = G[bs * Hq + n * HDq + d];
    out[bs * Hq + n * HDq + d] = (g / (1.f + expf(-g))) * yn;
}

__global__ void copy_kernel(const float* __restrict__ src, float* __restrict__ dst, long nTot) {
    long i = (long)blockIdx.x * blockDim.x + threadIdx.x;
    if (i < nTot) dst[i] = src[i];
}

// ============================================================================
extern "C" void kernel_launch(void* const* d_in, const int* in_sizes, int n_in,
                              void* d_out, int out_size) {
    const float* Xin  = (const float*)d_in[0];
    const float* WQ   = (const float*)d_in[1];
    const float* WK   = (const float*)d_in[2];
    const float* WV   = (const float*)d_in[3];
    const float* WG   = (const float*)d_in[4];
    const float* WO   = (const float*)d_in[5];
    const float* gn_w = (const float*)d_in[6];
    const float* gn_b = (const float*)d_in[7];
    const float* ln1w = (const float*)d_in[8];
    const float* ln1b = (const float*)d_in[9];
    const float* ln2w = (const float*)d_in[10];
    const float* ln2b = (const float*)d_in[11];
    const float* fw1  = (const float*)d_in[12];
    const float* fb1  = (const float*)d_in[13];
    const float* fw2  = (const float*)d_in[14];
    const float* fb2  = (const float*)d_in[15];
    float* out = (float*)d_out;

    float *pXn, *pQ, *pK, *pV, *pG, *pGated, *pY, *pHn, *pX, *pYa, *pM, *pSt, *pHf;
    float *pWQT, *pWKT, *pWVT, *pWGT, *pWOT, *pW1T, *pW2T;
    cudaGetSymbolAddress((void**)&pXn, g_Xn);
    cudaGetSymbolAddress((void**)&pQ, g_Q);
    cudaGetSymbolAddress((void**)&pK, g_K);
    cudaGetSymbolAddress((void**)&pV, g_V);
    cudaGetSymbolAddress((void**)&pG, g_G);
    cudaGetSymbolAddress((void**)&pGated, g_Gated);
    cudaGetSymbolAddress((void**)&pY, g_Y);
    cudaGetSymbolAddress((void**)&pHn, g_Hn);
    cudaGetSymbolAddress((void**)&pX, g_X);
    cudaGetSymbolAddress((void**)&pYa, g_Yattn);
    cudaGetSymbolAddress((void**)&pM, g_M);
    cudaGetSymbolAddress((void**)&pSt, g_St);
    cudaGetSymbolAddress((void**)&pHf, g_Hf);
    cudaGetSymbolAddress((void**)&pWQT, g_WQT);
    cudaGetSymbolAddress((void**)&pWKT, g_WKT);
    cudaGetSymbolAddress((void**)&pWVT, g_WVT);
    cudaGetSymbolAddress((void**)&pWGT, g_WGT);
    cudaGetSymbolAddress((void**)&pWOT, g_WOT);
    cudaGetSymbolAddress((void**)&pW1T, g_W1T);
    cudaGetSymbolAddress((void**)&pW2T, g_W2T);

    const int smemCO = (128 * PAsm + 2 * 128 * PA) * 4;
    cudaFuncSetAttribute(chunk_out_kernel, cudaFuncAttributeMaxDynamicSharedMemorySize, smemCO);

    // weight transposes to NT layout [N][K]
    transpose_kernel<<<dim3(4, 16, 12), 256>>>(WQ, pWQT, Hq, HDq);
    transpose_kernel<<<dim3(4, 16, 12), 256>>>(WK, pWKT, Hq, HDq);
    transpose_kernel<<<dim3(4, 16, 12), 256>>>(WV, pWVT, Hq, HDq);
    transpose_kernel<<<dim3(16, 16, 3), 256>>>(WG, pWGT, Hq, Hq);
    transpose_kernel<<<dim3(16, 16, 3), 256>>>(WO, pWOT, Hq, Hq);
    transpose_kernel<<<dim3(64, 16, 3), 256>>>(fw1, pW1T, Hq, FFNq);
    transpose_kernel<<<dim3(16, 64, 3), 256>>>(fw2, pW2T, FFNq, Hq);

    const float* cur = Xin;
    for (int l = 0; l < Lq; l++) {
        ln_kernel<<<BSq, 256>>>(cur, ln1w + (long)l * Hq, ln1b + (long)l * Hq, pXn);
        h_gemm_kernel<<<dim3(1, BSq / 128, NHq), 256>>>(pXn, pWQT + (long)l * NHq * HDq * Hq, pQ,
            Hq, Hq, Hq, Hq, 0, (long)HDq * Hq, HDq, nullptr, nullptr, 2);
        h_gemm_kernel<<<dim3(1, BSq / 128, NHq), 256>>>(pXn, pWKT + (long)l * NHq * HDq * Hq, pK,
            Hq, Hq, Hq, Hq, 0, (long)HDq * Hq, HDq, nullptr, nullptr, 3);
        h_gemm_kernel<<<dim3(1, BSq / 128, NHq), 256>>>(pXn, pWVT + (long)l * NHq * HDq * Hq, pV,
            Hq, Hq, Hq, Hq, 0, (long)HDq * Hq, HDq, nullptr, nullptr, 0);
        h_gemm_kernel<<<dim3(Hq / 128, BSq / 128, 1), 256>>>(pXn, pWGT + (long)l * Hq * Hq, pG,
            Hq, Hq, Hq, Hq, 0, 0, 0, nullptr, nullptr, 0);
        chunk_kv_kernel<<<Bq * NHq * NCq, 256>>>(pK, pV, pM);
        scan_kernel<<<(Bq * NHq * HDq * HDq) / 256, 256>>>(pM, pSt);
        chunk_out_kernel<<<Bq * NHq * NCq, 256, smemCO>>>(pQ, pK, pV, pSt, pYa);
        gnorm_gate_kernel<<<BSq * NHq, 128>>>(pYa, pG, gn_w + (long)l * Hq, gn_b + (long)l * Hq, pGated);
        h_gemm_kernel<<<dim3(Hq / 128, BSq / 128, 1), 256>>>(pGated, pWOT + (long)l * Hq * Hq, pY,
            Hq, Hq, Hq, Hq, 0, 0, 0, nullptr, cur, 0);
        ln_kernel<<<BSq, 256>>>(pY, ln2w + (long)l * Hq, ln2b + (long)l * Hq, pHn);
        h_gemm_kernel<<<dim3(FFNq / 128, BSq / 128, 1), 256>>>(pHn, pW1T + (long)l * FFNq * Hq, pHf,
            Hq, Hq, Hq, FFNq, 0, 0, 0, fb1 + (long)l * FFNq, nullptr, 1);
        h_gemm_kernel<<<dim3(Hq / 128, BSq / 128, 1), 256>>>(pHf, pW2T + (long)l * Hq * FFNq, pX,
            FFNq, FFNq, FFNq, Hq, 0, 0, 0, fb2 + (long)l * Hq, pY, 0);
        cur = pX;
    }

    long nX = (long)BSq * Hq;
    copy_kernel<<<(int)((nX + 255) / 256), 256>>>(pX, out, nX);
    h_gemm_kernel<<<dim3(Sq / 128, Sq / 128, Bq), 256>>>(pX, pX, out + nX,
        Hq, Hq, Hq, Sq,
        (long)Sq * Hq, (long)Sq * Hq, (long)Sq * Sq,
        nullptr, nullptr, 0);
}

// round 7
// speedup vs baseline: 3.0154x; 1.0120x over previous
#include <cuda_runtime.h>
#include <cuda_fp16.h>
#include <math.h>
#include <stdint.h>

#define Bq   4
#define Sq   2048
#define Hq   512
#define NHq  4
#define HDq  128
#define FFNq 2048
#define Lq   3
#define BSq  (Bq*Sq)
#define CHq  128
#define NCq  (Sq/CHq)
#define EPSq 1e-5f
#define PA   20
#define PAsm 132
#define PH   40

__device__ float g_Xn[BSq*Hq];
__device__ float g_Q[BSq*Hq];
__device__ float g_K[BSq*Hq];
__device__ float g_V[BSq*Hq];
__device__ float g_G[BSq*Hq];
__device__ float g_Gated[BSq*Hq];
__device__ float g_Y[BSq*Hq];
__device__ float g_Hn[BSq*Hq];
__device__ float g_X[BSq*Hq];
__device__ float g_M[Bq*NHq*NCq*HDq*HDq];
__device__ float g_St[Bq*NHq*NCq*HDq*HDq];
__device__ float g_Hf[BSq*FFNq];
__device__ float g_WQT[Lq*NHq*HDq*Hq];
__device__ float g_WKT[Lq*NHq*HDq*Hq];
__device__ float g_WVT[Lq*NHq*HDq*Hq];
__device__ float g_WGT[Lq*Hq*Hq];
__device__ float g_WOT[Lq*Hq*Hq];
__device__ float g_W1T[Lq*FFNq*Hq];
__device__ float g_W2T[Lq*Hq*FFNq];

__device__ __forceinline__ float gamma_of(int n) {
    double lg = -3.4657359027997265 + (double)n * (-0.9241962407465937);
    return (float)(1.0 - exp(lg));
}
__device__ __forceinline__ uint32_t f2tf(float x) {
    uint32_t y;
    asm("cvt.rna.tf32.f32 %0, %1;" : "=r"(y) : "f"(x));
    return y;
}
__device__ __forceinline__ uint32_t pack2(float a, float b) {
    __half2 h = __floats2half2_rn(a, b);
    return *(uint32_t*)&h;
}
__device__ __forceinline__ void mma_tf32(float* c, const uint32_t* a, const uint32_t* b) {
    asm volatile(
        "mma.sync.aligned.m16n8k8.row.col.f32.tf32.tf32.f32 "
        "{%0,%1,%2,%3}, {%4,%5,%6,%7}, {%8,%9}, {%0,%1,%2,%3};"
        : "+f"(c[0]), "+f"(c[1]), "+f"(c[2]), "+f"(c[3])
        : "r"(a[0]), "r"(a[1]), "r"(a[2]), "r"(a[3]), "r"(b[0]), "r"(b[1]));
}
__device__ __forceinline__ void mma_f16(float* c, const uint32_t* a, const uint32_t* b) {
    asm volatile(
        "mma.sync.aligned.m16n8k16.row.col.f32.f16.f16.f32 "
        "{%0,%1,%2,%3}, {%4,%5,%6,%7}, {%8,%9}, {%0,%1,%2,%3};"
        : "+f"(c[0]), "+f"(c[1]), "+f"(c[2]), "+f"(c[3])
        : "r"(a[0]), "r"(a[1]), "r"(a[2]), "r"(a[3]), "r"(b[0]), "r"(b[1]));
}

// =========== fp16 tensor-core NT GEMM: C[M,Ntile]=A[M,K]*Bt[N,K]^T =========
__global__ __launch_bounds__(256, 2) void h_gemm_kernel(
    const float* __restrict__ A, const float* __restrict__ Bt, float* __restrict__ C,
    int K, int lda, int ldb, int ldc,
    long aStride, long bStride, long cStride,
    const float* __restrict__ bias, const float* __restrict__ res, int act)
{
    __shared__ __align__(16) __half smA[2][128 * PH];
    __shared__ __align__(16) __half smB[2][128 * PH];
    int z = blockIdx.z;
    A  += z * aStride;
    Bt += z * bStride;
    C  += z * cStride;
    if (res) res += z * cStride;
    int bm = blockIdx.y * 128, bn = blockIdx.x * 128;
    int tid = threadIdx.x;
    int lane = tid & 31, warp = tid >> 5;
    int gid = lane >> 2, tig = lane & 3;
    int wy = warp >> 2, wx = warp & 3;

    float acc[4][4][4];
#pragma unroll
    for (int i = 0; i < 4; i++)
#pragma unroll
        for (int j = 0; j < 4; j++)
#pragma unroll
            for (int k = 0; k < 4; k++) acc[i][j][k] = 0.f;

    int lr = tid >> 1, lkh = (tid & 1) * 16;
    uint32_t ra[8], rb[8];

#define HLOAD(k0)                                                              \
    {                                                                          \
        const float* ap = A + (long)(bm + lr) * lda + (k0) + lkh;              \
        float4 a0 = *(const float4*)(ap),     a1 = *(const float4*)(ap + 4);   \
        float4 a2 = *(const float4*)(ap + 8), a3 = *(const float4*)(ap + 12);  \
        ra[0] = pack2(a0.x, a0.y); ra[1] = pack2(a0.z, a0.w);                  \
        ra[2] = pack2(a1.x, a1.y); ra[3] = pack2(a1.z, a1.w);                  \
        ra[4] = pack2(a2.x, a2.y); ra[5] = pack2(a2.z, a2.w);                  \
        ra[6] = pack2(a3.x, a3.y); ra[7] = pack2(a3.z, a3.w);                  \
        const float* bp = Bt + (long)(bn + lr) * ldb + (k0) + lkh;             \
        float4 b0 = *(const float4*)(bp),     b1 = *(const float4*)(bp + 4);   \
        float4 b2 = *(const float4*)(bp + 8), b3 = *(const float4*)(bp + 12);  \
        rb[0] = pack2(b0.x, b0.y); rb[1] = pack2(b0.z, b0.w);                  \
        rb[2] = pack2(b1.x, b1.y); rb[3] = pack2(b1.z, b1.w);                  \
        rb[4] = pack2(b2.x, b2.y); rb[5] = pack2(b2.z, b2.w);                  \
        rb[6] = pack2(b3.x, b3.y); rb[7] = pack2(b3.z, b3.w);                  \
    }

#define HSTORE(p)                                                              \
    {                                                                          \
        *(uint4*)&smA[p][lr * PH + lkh]     = make_uint4(ra[0], ra[1], ra[2], ra[3]); \
        *(uint4*)&smA[p][lr * PH + lkh + 8] = make_uint4(ra[4], ra[5], ra[6], ra[7]); \
        *(uint4*)&smB[p][lr * PH + lkh]     = make_uint4(rb[0], rb[1], rb[2], rb[3]); \
        *(uint4*)&smB[p][lr * PH + lkh + 8] = make_uint4(rb[4], rb[5], rb[6], rb[7]); \
    }

#define HCOMP(p)                                                               \
    _Pragma("unroll")                                                          \
    for (int ks = 0; ks < 2; ks++) {                                           \
        uint32_t af[4][4], bf[4][2];                                           \
        _Pragma("unroll")                                                      \
        for (int mi = 0; mi < 4; mi++) {                                       \
            int base = (wy * 64 + mi * 16 + gid) * PH + ks * 16 + tig * 2;     \
            af[mi][0] = *(uint32_t*)&smA[p][base];                             \
            af[mi][1] = *(uint32_t*)&smA[p][base + 8 * PH];                    \
            af[mi][2] = *(uint32_t*)&smA[p][base + 8];                         \
            af[mi][3] = *(uint32_t*)&smA[p][base + 8 * PH + 8];                \
        }                                                                      \
        _Pragma("unroll")                                                      \
        for (int ni = 0; ni < 4; ni++) {                                       \
            int nb = (wx * 32 + ni * 8 + gid) * PH + ks * 16 + tig * 2;        \
            bf[ni][0] = *(uint32_t*)&smB[p][nb];                               \
            bf[ni][1] = *(uint32_t*)&smB[p][nb + 8];                           \
        }                                                                      \
        _Pragma("unroll")                                                      \
        for (int mi = 0; mi < 4; mi++)                                         \
            _Pragma("unroll")                                                  \
            for (int ni = 0; ni < 4; ni++)                                     \
                mma_f16(acc[mi][ni], af[mi], bf[ni]);                          \
    }

    HLOAD(0)
    HSTORE(0)
    __syncthreads();
    int p = 0;
    for (int k0 = 32;; k0 += 32) {
        bool more = (k0 < K);
        if (more) HLOAD(k0)
        HCOMP(p)
        if (!more) break;
        HSTORE(p ^ 1)
        __syncthreads();
        p ^= 1;
    }

    // epilogue
#pragma unroll
    for (int mi = 0; mi < 4; mi++) {
        long r0 = bm + wy * 64 + mi * 16 + gid;
        long r1 = r0 + 8;
#pragma unroll
        for (int ni = 0; ni < 4; ni++) {
            int c0 = bn + wx * 32 + ni * 8 + tig * 2;
            float v00 = acc[mi][ni][0], v01 = acc[mi][ni][1];
            float v10 = acc[mi][ni][2], v11 = acc[mi][ni][3];
            if (bias) {
                float b0 = bias[c0], b1 = bias[c0 + 1];
                v00 += b0; v01 += b1; v10 += b0; v11 += b1;
            }
            if (act == 1) {
                v00 = 0.5f * v00 * (1.f + erff(v00 * 0.70710678118654752f));
                v01 = 0.5f * v01 * (1.f + erff(v01 * 0.70710678118654752f));
                v10 = 0.5f * v10 * (1.f + erff(v10 * 0.70710678118654752f));
                v11 = 0.5f * v11 * (1.f + erff(v11 * 0.70710678118654752f));
            } else if (act >= 2) {
                float fi = (float)(c0 >> 1);
                float lsb = log2f((fi + 51.2f) * (1.f / 179.2f));
                if (act == 3) lsb = -lsb;
                float invf = exp2f(fi * (-0.20761871093296528f));
#pragma unroll
                for (int rr = 0; rr < 2; rr++) {
                    float pp = (float)((rr ? r1 : r0) & (Sq - 1));
                    float sc = exp2f(lsb * pp * (1.f / 512.f));
                    float s_, c_;
                    sincosf(pp * invf, &s_, &c_);
                    c_ *= sc; s_ *= sc;
                    if (rr == 0) {
                        float t0 = v00 * c_ - v01 * s_;
                        v01 = v01 * c_ + v00 * s_;
                        v00 = t0;
                    } else {
                        float t0 = v10 * c_ - v11 * s_;
                        v11 = v11 * c_ + v10 * s_;
                        v10 = t0;
                    }
                }
            }
            if (res) {
                v00 += res[r0 * ldc + c0]; v01 += res[r0 * ldc + c0 + 1];
                v10 += res[r1 * ldc + c0]; v11 += res[r1 * ldc + c0 + 1];
            }
            *(float2*)(C + r0 * ldc + c0) = make_float2(v00, v01);
            *(float2*)(C + r1 * ldc + c0) = make_float2(v10, v11);
        }
    }
#undef HLOAD
#undef HSTORE
#undef HCOMP
}

// ---------------- transpose out[c][r] = in[r][c], z-batched -----------------
__global__ __launch_bounds__(256) void transpose_kernel(const float* __restrict__ in,
                                                        float* __restrict__ out, int R, int C) {
    __shared__ float t[32][33];
    long z = blockIdx.z;
    in  += z * (long)R * C;
    out += z * (long)R * C;
    int bx = blockIdx.x * 32, by = blockIdx.y * 32;
    int tx = threadIdx.x & 31, ty = threadIdx.x >> 5;
#pragma unroll
    for (int i = 0; i < 32; i += 8)
        t[ty + i][tx] = in[(long)(by + ty + i) * C + bx + tx];
    __syncthreads();
#pragma unroll
    for (int i = 0; i < 32; i += 8)
        out[(long)(bx + ty + i) * R + by + tx] = t[tx][ty + i];
}

// ---------------- warp-per-row LayerNorm over H=512 -------------------------
__global__ __launch_bounds__(256) void ln_kernel(const float* __restrict__ X,
                                                 const float* __restrict__ w,
                                                 const float* __restrict__ b,
                                                 float* __restrict__ out) {
    int warp = threadIdx.x >> 5, lane = threadIdx.x & 31;
    long row = (long)blockIdx.x * 8 + warp;
    const float* x = X + row * Hq;
    float4 v[4];
#pragma unroll
    for (int i = 0; i < 4; i++) v[i] = *(const float4*)(x + i * 128 + lane * 4);
    float s = 0.f;
#pragma unroll
    for (int i = 0; i < 4; i++) s += v[i].x + v[i].y + v[i].z + v[i].w;
#pragma unroll
    for (int o = 16; o; o >>= 1) s += __shfl_xor_sync(0xffffffffu, s, o);
    float m = s * (1.f / Hq);
    float s2 = 0.f;
#pragma unroll
    for (int i = 0; i < 4; i++) {
        v[i].x -= m; v[i].y -= m; v[i].z -= m; v[i].w -= m;
        s2 += v[i].x * v[i].x + v[i].y * v[i].y + v[i].z * v[i].z + v[i].w * v[i].w;
    }
#pragma unroll
    for (int o = 16; o; o >>= 1) s2 += __shfl_xor_sync(0xffffffffu, s2, o);
    float inv = rsqrtf(s2 * (1.f / Hq) + EPSq);
#pragma unroll
    for (int i = 0; i < 4; i++) {
        int d = i * 128 + lane * 4;
        float4 ww = *(const float4*)(w + d);
        float4 bb = *(const float4*)(b + d);
        *(float4*)(out + row * Hq + d) = make_float4(
            v[i].x * inv * ww.x + bb.x, v[i].y * inv * ww.y + bb.y,
            v[i].z * inv * ww.z + bb.z, v[i].w * inv * ww.w + bb.w);
    }
}

// ---------------- retention pass A: per-chunk decayed KV (tf32 mma) --------
__global__ __launch_bounds__(256) void chunk_kv_kernel(const float* __restrict__ Kd,
                                                       const float* __restrict__ Vd,
                                                       float* __restrict__ Mout) {
    __shared__ uint32_t KT[128 * PA];
    __shared__ uint32_t VT[128 * PA];
    int bid = blockIdx.x;
    int bn = bid / NCq, c = bid % NCq;
    int b = bn >> 2, n = bn & 3;
    float lgam = logf(gamma_of(n));
    const float* Kb = Kd + ((long)(b * Sq + c * CHq)) * Hq + n * HDq;
    const float* Vb = Vd + ((long)(b * Sq + c * CHq)) * Hq + n * HDq;
    int tid = threadIdx.x;
    int lane = tid & 31, warp = tid >> 5;
    int gid = lane >> 2, tig = lane & 3;
    int wy = warp >> 2, wx = warp & 3;
    float acc[4][4][4];
#pragma unroll
    for (int i = 0; i < 4; i++)
#pragma unroll
        for (int j = 0; j < 4; j++)
#pragma unroll
            for (int k = 0; k < 4; k++) acc[i][j][k] = 0.f;
    int jj = tid >> 4, dbase = (tid & 15) * 8;
    int jjs = jj ^ (tid & 15);
    for (int j0 = 0; j0 < CHq; j0 += 16) {
        int j = j0 + jj;
        float w = expf((float)(127 - j) * lgam);
        const float* kp = Kb + (long)j * Hq + dbase;
        float4 k0 = *(const float4*)(kp), k1 = *(const float4*)(kp + 4);
        const float* vp = Vb + (long)j * Hq + dbase;
        float4 v0 = *(const float4*)(vp), v1 = *(const float4*)(vp + 4);
        __syncthreads();
        KT[(dbase + 0) * PA + jjs] = f2tf(k0.x * w);
        KT[(dbase + 1) * PA + jjs] = f2tf(k0.y * w);
        KT[(dbase + 2) * PA + jjs] = f2tf(k0.z * w);
        KT[(dbase + 3) * PA + jjs] = f2tf(k0.w * w);
        KT[(dbase + 4) * PA + jjs] = f2tf(k1.x * w);
        KT[(dbase + 5) * PA + jjs] = f2tf(k1.y * w);
        KT[(dbase + 6) * PA + jjs] = f2tf(k1.z * w);
        KT[(dbase + 7) * PA + jjs] = f2tf(k1.w * w);
        VT[(dbase + 0) * PA + jjs] = f2tf(v0.x);
        VT[(dbase + 1) * PA + jjs] = f2tf(v0.y);
        VT[(dbase + 2) * PA + jjs] = f2tf(v0.z);
        VT[(dbase + 3) * PA + jjs] = f2tf(v0.w);
        VT[(dbase + 4) * PA + jjs] = f2tf(v1.x);
        VT[(dbase + 5) * PA + jjs] = f2tf(v1.y);
        VT[(dbase + 6) * PA + jjs] = f2tf(v1.z);
        VT[(dbase + 7) * PA + jjs] = f2tf(v1.w);
        __syncthreads();
#pragma unroll
        for (int kk = 0; kk < 16; kk += 8) {
            uint32_t af[4][4], bf[4][2];
#pragma unroll
            for (int mi = 0; mi < 4; mi++) {
                int m = wy * 64 + mi * 16 + gid;
                int sw = m >> 3, sw2 = (m + 8) >> 3;
                af[mi][0] = KT[m * PA + ((kk + tig) ^ sw)];
                af[mi][1] = KT[(m + 8) * PA + ((kk + tig) ^ sw2)];
                af[mi][2] = KT[m * PA + ((kk + tig + 4) ^ sw)];
                af[mi][3] = KT[(m + 8) * PA + ((kk + tig + 4) ^ sw2)];
            }
#pragma unroll
            for (int ni = 0; ni < 4; ni++) {
                int nb = wx * 32 + ni * 8 + gid;
                int sw = nb >> 3;
                bf[ni][0] = VT[nb * PA + ((kk + tig) ^ sw)];
                bf[ni][1] = VT[nb * PA + ((kk + tig + 4) ^ sw)];
            }
#pragma unroll
            for (int mi = 0; mi < 4; mi++)
#pragma unroll
                for (int ni = 0; ni < 4; ni++)
                    mma_tf32(acc[mi][ni], af[mi], bf[ni]);
        }
    }
    float* Mo = Mout + (long)bid * (HDq * HDq);
#pragma unroll
    for (int mi = 0; mi < 4; mi++) {
        int r0 = wy * 64 + mi * 16 + gid, r1 = r0 + 8;
#pragma unroll
        for (int ni = 0; ni < 4; ni++) {
            int c0 = wx * 32 + ni * 8 + tig * 2;
            *(float2*)(Mo + r0 * HDq + c0) = make_float2(acc[mi][ni][0], acc[mi][ni][1]);
            *(float2*)(Mo + r1 * HDq + c0) = make_float2(acc[mi][ni][2], acc[mi][ni][3]);
        }
    }
}

__global__ __launch_bounds__(256) void scan_kernel(const float* __restrict__ M,
                                                   float* __restrict__ St) {
    long idx = (long)blockIdx.x * blockDim.x + threadIdx.x;
    int bn = (int)(idx >> 14);
    int n = bn & 3;
    float gamma = gamma_of(n);
    float gC = expf(128.f * logf(gamma));
    long e = idx & 16383;
    float s = 0.f;
    for (int c = 0; c < NCq; c++) {
        long off = ((long)bn * NCq + c) * 16384 + e;
        St[off] = s;
        s = s * gC + M[off];
    }
}

// ------- retention pass C: chunk output + fused group-norm + swish gate ----
__global__ __launch_bounds__(256) void chunk_out_kernel(const float* __restrict__ Qd,
                                                        const float* __restrict__ Kd,
                                                        const float* __restrict__ Vd,
                                                        const float* __restrict__ States,
                                                        const float* __restrict__ Gm,
                                                        const float* __restrict__ gnw,
                                                        const float* __restrict__ gnb,
                                                        float* __restrict__ outG) {
    extern __shared__ uint32_t dsm[];
    uint32_t* Asm = dsm;
    uint32_t* T1  = dsm + 128 * PAsm;
    uint32_t* T2  = T1 + 128 * PA;
    int bid = blockIdx.x;
    int bn = bid / NCq, c = bid % NCq;
    int b = bn >> 2, n = bn & 3;
    float lgam = logf(gamma_of(n));
    const float* Qb = Qd + ((long)(b * Sq + c * CHq)) * Hq + n * HDq;
    const float* Kb = Kd + ((long)(b * Sq + c * CHq)) * Hq + n * HDq;
    const float* Vb = Vd + ((long)(b * Sq + c * CHq)) * Hq + n * HDq;
    const float* Sb = States + ((long)bn * NCq + c) * 16384;
    int tid = threadIdx.x;
    int lane = tid & 31, warp = tid >> 5;
    int gid = lane >> 2, tig = lane & 3;
    int wy = warp >> 2, wx = warp & 3;
    float acc[4][4][4];
#pragma unroll
    for (int i = 0; i < 4; i++)
#pragma unroll
        for (int j = 0; j < 4; j++)
#pragma unroll
            for (int k = 0; k < 4; k++) acc[i][j][k] = 0.f;
    int lr = tid >> 1, lc = (tid & 1) * 8;
    int jj = tid >> 4, dbase = (tid & 15) * 8;
    int jjs = jj ^ (tid & 15);

    // phase 1: scores = Q K^T
    for (int d0 = 0; d0 < HDq; d0 += 16) {
        const float* qp = Qb + (long)lr * Hq + d0 + lc;
        float4 q0 = *(const float4*)(qp), q1 = *(const float4*)(qp + 4);
        const float* kp = Kb + (long)lr * Hq + d0 + lc;
        float4 k0 = *(const float4*)(kp), k1 = *(const float4*)(kp + 4);
        __syncthreads();
        *(uint4*)&T1[lr * PA + lc]     = make_uint4(f2tf(q0.x), f2tf(q0.y), f2tf(q0.z), f2tf(q0.w));
        *(uint4*)&T1[lr * PA + lc + 4] = make_uint4(f2tf(q1.x), f2tf(q1.y), f2tf(q1.z), f2tf(q1.w));
        *(uint4*)&T2[lr * PA + lc]     = make_uint4(f2tf(k0.x), f2tf(k0.y), f2tf(k0.z), f2tf(k0.w));
        *(uint4*)&T2[lr * PA + lc + 4] = make_uint4(f2tf(k1.x), f2tf(k1.y), f2tf(k1.z), f2tf(k1.w));
        __syncthreads();
#pragma unroll
        for (int kk = 0; kk < 16; kk += 8) {
            uint32_t af[4][4], bf[4][2];
#pragma unroll
            for (int mi = 0; mi < 4; mi++) {
                int mb = (wy * 64 + mi * 16 + gid) * PA + kk + tig;
                af[mi][0] = T1[mb]; af[mi][1] = T1[mb + 8 * PA];
                af[mi][2] = T1[mb + 4]; af[mi][3] = T1[mb + 8 * PA + 4];
            }
#pragma unroll
            for (int ni = 0; ni < 4; ni++) {
                int nb = (wx * 32 + ni * 8 + gid) * PA + kk + tig;
                bf[ni][0] = T2[nb]; bf[ni][1] = T2[nb + 4];
            }
#pragma unroll
            for (int mi = 0; mi < 4; mi++)
#pragma unroll
                for (int ni = 0; ni < 4; ni++)
                    mma_tf32(acc[mi][ni], af[mi], bf[ni]);
        }
    }
    {
        float pj[8], pk[8];
#pragma unroll
        for (int mi = 0; mi < 4; mi++) {
            int r0 = wy * 64 + mi * 16 + gid;
            pj[mi * 2]     = expf((float)r0 * lgam);
            pj[mi * 2 + 1] = expf((float)(r0 + 8) * lgam);
        }
#pragma unroll
        for (int ni = 0; ni < 4; ni++) {
            int c0 = wx * 32 + ni * 8 + tig * 2;
            pk[ni * 2]     = expf((float)(-c0) * lgam);
            pk[ni * 2 + 1] = expf((float)(-(c0 + 1)) * lgam);
        }
        __syncthreads();
#pragma unroll
        for (int mi = 0; mi < 4; mi++) {
            int r0 = wy * 64 + mi * 16 + gid, r1 = r0 + 8;
#pragma unroll
            for (int ni = 0; ni < 4; ni++) {
                int c0 = wx * 32 + ni * 8 + tig * 2;
                float v00 = (r0 >= c0)     ? acc[mi][ni][0] * pj[mi*2]   * pk[ni*2]   : 0.f;
                float v01 = (r0 >= c0 + 1) ? acc[mi][ni][1] * pj[mi*2]   * pk[ni*2+1] : 0.f;
                float v10 = (r1 >= c0)     ? acc[mi][ni][2] * pj[mi*2+1] * pk[ni*2]   : 0.f;
                float v11 = (r1 >= c0 + 1) ? acc[mi][ni][3] * pj[mi*2+1] * pk[ni*2+1] : 0.f;
                Asm[r0 * PAsm + c0]     = f2tf(v00);
                Asm[r0 * PAsm + c0 + 1] = f2tf(v01);
                Asm[r1 * PAsm + c0]     = f2tf(v10);
                Asm[r1 * PAsm + c0 + 1] = f2tf(v11);
                acc[mi][ni][0] = acc[mi][ni][1] = acc[mi][ni][2] = acc[mi][ni][3] = 0.f;
            }
        }
    }
    __syncthreads();

    // phase 2: Y = scores * V
    for (int j0 = 0; j0 < CHq; j0 += 16) {
        const float* vp = Vb + (long)(j0 + jj) * Hq + dbase;
        float4 v0 = *(const float4*)(vp), v1 = *(const float4*)(vp + 4);
        __syncthreads();
        T2[(dbase + 0) * PA + jjs] = f2tf(v0.x);
        T2[(dbase + 1) * PA + jjs] = f2tf(v0.y);
        T2[(dbase + 2) * PA + jjs] = f2tf(v0.z);
        T2[(dbase + 3) * PA + jjs] = f2tf(v0.w);
        T2[(dbase + 4) * PA + jjs] = f2tf(v1.x);
        T2[(dbase + 5) * PA + jjs] = f2tf(v1.y);
        T2[(dbase + 6) * PA + jjs] = f2tf(v1.z);
        T2[(dbase + 7) * PA + jjs] = f2tf(v1.w);
        __syncthreads();
#pragma unroll
        for (int kk = 0; kk < 16; kk += 8) {
            uint32_t af[4][4], bf[4][2];
#pragma unroll
            for (int mi = 0; mi < 4; mi++) {
                int mb = (wy * 64 + mi * 16 + gid) * PAsm + j0 + kk + tig;
                af[mi][0] = Asm[mb]; af[mi][1] = Asm[mb + 8 * PAsm];
                af[mi][2] = Asm[mb + 4]; af[mi][3] = Asm[mb + 8 * PAsm + 4];
            }
#pragma unroll
            for (int ni = 0; ni < 4; ni++) {
                int nb = wx * 32 + ni * 8 + gid;
                int sw = nb >> 3;
                bf[ni][0] = T2[nb * PA + ((kk + tig) ^ sw)];
                bf[ni][1] = T2[nb * PA + ((kk + tig + 4) ^ sw)];
            }
#pragma unroll
            for (int mi = 0; mi < 4; mi++)
#pragma unroll
                for (int ni = 0; ni < 4; ni++)
                    mma_tf32(acc[mi][ni], af[mi], bf[ni]);
        }
    }

    // phase 3: Y += diag(gamma^{j+1}) Q * State
    {
        float wrow = expf((float)(lr + 1) * lgam);
        for (int e0 = 0; e0 < HDq; e0 += 16) {
            const float* qp = Qb + (long)lr * Hq + e0 + lc;
            float4 q0 = *(const float4*)(qp), q1 = *(const float4*)(qp + 4);
            const float* sp = Sb + (long)(e0 + jj) * HDq + dbase;
            float4 s0 = *(const float4*)(sp), s1 = *(const float4*)(sp + 4);
            __syncthreads();
            *(uint4*)&T1[lr * PA + lc]     = make_uint4(f2tf(q0.x * wrow), f2tf(q0.y * wrow), f2tf(q0.z * wrow), f2tf(q0.w * wrow));
            *(uint4*)&T1[lr * PA + lc + 4] = make_uint4(f2tf(q1.x * wrow), f2tf(q1.y * wrow), f2tf(q1.z * wrow), f2tf(q1.w * wrow));
            T2[(dbase + 0) * PA + jjs] = f2tf(s0.x);
            T2[(dbase + 1) * PA + jjs] = f2tf(s0.y);
            T2[(dbase + 2) * PA + jjs] = f2tf(s0.z);
            T2[(dbase + 3) * PA + jjs] = f2tf(s0.w);
            T2[(dbase + 4) * PA + jjs] = f2tf(s1.x);
            T2[(dbase + 5) * PA + jjs] = f2tf(s1.y);
            T2[(dbase + 6) * PA + jjs] = f2tf(s1.z);
            T2[(dbase + 7) * PA + jjs] = f2tf(s1.w);
            __syncthreads();
#pragma unroll
            for (int kk = 0; kk < 16; kk += 8) {
                uint32_t af[4][4], bf[4][2];
#pragma unroll
                for (int mi = 0; mi < 4; mi++) {
                    int mb = (wy * 64 + mi * 16 + gid) * PA + kk + tig;
                    af[mi][0] = T1[mb]; af[mi][1] = T1[mb + 8 * PA];
                    af[mi][2] = T1[mb + 4]; af[mi][3] = T1[mb + 8 * PA + 4];
                }
#pragma unroll
                for (int ni = 0; ni < 4; ni++) {
                    int nb = wx * 32 + ni * 8 + gid;
                    int sw = nb >> 3;
                    bf[ni][0] = T2[nb * PA + ((kk + tig) ^ sw)];
                    bf[ni][1] = T2[nb * PA + ((kk + tig + 4) ^ sw)];
                }
#pragma unroll
                for (int mi = 0; mi < 4; mi++)
#pragma unroll
                    for (int ni = 0; ni < 4; ni++)
                        mma_tf32(acc[mi][ni], af[mi], bf[ni]);
            }
        }
    }

    // ---- fused group-norm + swish gate ----
    float* Ysm = (float*)dsm;   // reuse score region (128 x PAsm floats)
#pragma unroll
    for (int mi = 0; mi < 4; mi++) {
        int r0 = wy * 64 + mi * 16 + gid, r1 = r0 + 8;
#pragma unroll
        for (int ni = 0; ni < 4; ni++) {
            int c0 = wx * 32 + ni * 8 + tig * 2;
            Ysm[r0 * PAsm + c0]     = acc[mi][ni][0];
            Ysm[r0 * PAsm + c0 + 1] = acc[mi][ni][1];
            Ysm[r1 * PAsm + c0]     = acc[mi][ni][2];
            Ysm[r1 * PAsm + c0 + 1] = acc[mi][ni][3];
        }
    }
    __syncthreads();
    const float* gnwh = gnw + n * HDq;
    const float* gnbh = gnb + n * HDq;
#pragma unroll 1
    for (int rr = 0; rr < 16; rr++) {
        int row = warp * 16 + rr;
        float y[4];
#pragma unroll
        for (int i = 0; i < 4; i++) y[i] = Ysm[row * PAsm + lane + 32 * i];
        float s = y[0] + y[1] + y[2] + y[3];
#pragma unroll
        for (int o = 16; o; o >>= 1) s += __shfl_xor_sync(0xffffffffu, s, o);
        float m = s * (1.f / HDq);
        float s2 = 0.f;
#pragma unroll
        for (int i = 0; i < 4; i++) { y[i] -= m; s2 += y[i] * y[i]; }
#pragma unroll
        for (int o = 16; o; o >>= 1) s2 += __shfl_xor_sync(0xffffffffu, s2, o);
        float inv = rsqrtf(s2 * (1.f / HDq) + EPSq);
        long srow = (long)b * Sq + c * CHq + row;
        const float* gp = Gm + srow * Hq + n * HDq;
        float* op = outG + srow * Hq + n * HDq;
#pragma unroll
        for (int i = 0; i < 4; i++) {
            int d = lane + 32 * i;
            float g = gp[d];
            float yn = y[i] * inv * gnwh[d] + gnbh[d];
            op[d] = (g / (1.f + expf(-g))) * yn;
        }
    }
}

// ============================================================================
extern "C" void kernel_launch(void* const* d_in, const int* in_sizes, int n_in,
                              void* d_out, int out_size) {
    const float* Xin  = (const float*)d_in[0];
    const float* WQ   = (const float*)d_in[1];
    const float* WK   = (const float*)d_in[2];
    const float* WV   = (const float*)d_in[3];
    const float* WG   = (const float*)d_in[4];
    const float* WO   = (const float*)d_in[5];
    const float* gn_w = (const float*)d_in[6];
    const float* gn_b = (const float*)d_in[7];
    const float* ln1w = (const float*)d_in[8];
    const float* ln1b = (const float*)d_in[9];
    const float* ln2w = (const float*)d_in[10];
    const float* ln2b = (const float*)d_in[11];
    const float* fw1  = (const float*)d_in[12];
    const float* fb1  = (const float*)d_in[13];
    const float* fw2  = (const float*)d_in[14];
    const float* fb2  = (const float*)d_in[15];
    float* out = (float*)d_out;

    float *pXn, *pQ, *pK, *pV, *pG, *pGated, *pY, *pHn, *pX, *pM, *pSt, *pHf;
    float *pWQT, *pWKT, *pWVT, *pWGT, *pWOT, *pW1T, *pW2T;
    cudaGetSymbolAddress((void**)&pXn, g_Xn);
    cudaGetSymbolAddress((void**)&pQ, g_Q);
    cudaGetSymbolAddress((void**)&pK, g_K);
    cudaGetSymbolAddress((void**)&pV, g_V);
    cudaGetSymbolAddress((void**)&pG, g_G);
    cudaGetSymbolAddress((void**)&pGated, g_Gated);
    cudaGetSymbolAddress((void**)&pY, g_Y);
    cudaGetSymbolAddress((void**)&pHn, g_Hn);
    cudaGetSymbolAddress((void**)&pX, g_X);
    cudaGetSymbolAddress((void**)&pM, g_M);
    cudaGetSymbolAddress((void**)&pSt, g_St);
    cudaGetSymbolAddress((void**)&pHf, g_Hf);
    cudaGetSymbolAddress((void**)&pWQT, g_WQT);
    cudaGetSymbolAddress((void**)&pWKT, g_WKT);
    cudaGetSymbolAddress((void**)&pWVT, g_WVT);
    cudaGetSymbolAddress((void**)&pWGT, g_WGT);
    cudaGetSymbolAddress((void**)&pWOT, g_WOT);
    cudaGetSymbolAddress((void**)&pW1T, g_W1T);
    cudaGetSymbolAddress((void**)&pW2T, g_W2T);

    const int smemCO = (128 * PAsm + 2 * 128 * PA) * 4;
    cudaFuncSetAttribute(chunk_out_kernel, cudaFuncAttributeMaxDynamicSharedMemorySize, smemCO);

    // weight transposes to NT layout [N][K]
    transpose_kernel<<<dim3(4, 16, 12), 256>>>(WQ, pWQT, Hq, HDq);
    transpose_kernel<<<dim3(4, 16, 12), 256>>>(WK, pWKT, Hq, HDq);
    transpose_kernel<<<dim3(4, 16, 12), 256>>>(WV, pWVT, Hq, HDq);
    transpose_kernel<<<dim3(16, 16, 3), 256>>>(WG, pWGT, Hq, Hq);
    transpose_kernel<<<dim3(16, 16, 3), 256>>>(WO, pWOT, Hq, Hq);
    transpose_kernel<<<dim3(64, 16, 3), 256>>>(fw1, pW1T, Hq, FFNq);
    transpose_kernel<<<dim3(16, 64, 3), 256>>>(fw2, pW2T, FFNq, Hq);

    const float* cur = Xin;
    for (int l = 0; l < Lq; l++) {
        ln_kernel<<<BSq / 8, 256>>>(cur, ln1w + (long)l * Hq, ln1b + (long)l * Hq, pXn);
        h_gemm_kernel<<<dim3(1, BSq / 128, NHq), 256>>>(pXn, pWQT + (long)l * NHq * HDq * Hq, pQ,
            Hq, Hq, Hq, Hq, 0, (long)HDq * Hq, HDq, nullptr, nullptr, 2);
        h_gemm_kernel<<<dim3(1, BSq / 128, NHq), 256>>>(pXn, pWKT + (long)l * NHq * HDq * Hq, pK,
            Hq, Hq, Hq, Hq, 0, (long)HDq * Hq, HDq, nullptr, nullptr, 3);
        h_gemm_kernel<<<dim3(1, BSq / 128, NHq), 256>>>(pXn, pWVT + (long)l * NHq * HDq * Hq, pV,
            Hq, Hq, Hq, Hq, 0, (long)HDq * Hq, HDq, nullptr, nullptr, 0);
        h_gemm_kernel<<<dim3(Hq / 128, BSq / 128, 1), 256>>>(pXn, pWGT + (long)l * Hq * Hq, pG,
            Hq, Hq, Hq, Hq, 0, 0, 0, nullptr, nullptr, 0);
        chunk_kv_kernel<<<Bq * NHq * NCq, 256>>>(pK, pV, pM);
        scan_kernel<<<(Bq * NHq * HDq * HDq) / 256, 256>>>(pM, pSt);
        chunk_out_kernel<<<Bq * NHq * NCq, 256, smemCO>>>(pQ, pK, pV, pSt, pG,
            gn_w + (long)l * Hq, gn_b + (long)l * Hq, pGated);
        h_gemm_kernel<<<dim3(Hq / 128, BSq / 128, 1), 256>>>(pGated, pWOT + (long)l * Hq * Hq, pY,
            Hq, Hq, Hq, Hq, 0, 0, 0, nullptr, cur, 0);
        ln_kernel<<<BSq / 8, 256>>>(pY, ln2w + (long)l * Hq, ln2b + (long)l * Hq, pHn);
        h_gemm_kernel<<<dim3(FFNq / 128, BSq / 128, 1), 256>>>(pHn, pW1T + (long)l * FFNq * Hq, pHf,
            Hq, Hq, Hq, FFNq, 0, 0, 0, fb1 + (long)l * FFNq, nullptr, 1);
        float* dst = (l == Lq - 1) ? out : pX;
        h_gemm_kernel<<<dim3(Hq / 128, BSq / 128, 1), 256>>>(pHf, pW2T + (long)l * Hq * FFNq, dst,
            FFNq, FFNq, FFNq, Hq, 0, 0, 0, fb2 + (long)l * Hq, pY, 0);
        cur = dst;
    }

    long nX = (long)BSq * Hq;
    h_gemm_kernel<<<dim3(Sq / 128, Sq / 128, Bq), 256>>>(out, out, out + nX,
        Hq, Hq, Hq, Sq,
        (long)Sq * Hq, (long)Sq * Hq, (long)Sq * Sq,
        nullptr, nullptr, 0);
}

// round 8
// speedup vs baseline: 3.8958x; 1.2919x over previous
#include <cuda_runtime.h>
#include <cuda_fp16.h>
#include <math.h>
#include <stdint.h>

#define Bq   4
#define Sq   2048
#define Hq   512
#define NHq  4
#define HDq  128
#define FFNq 2048
#define Lq   3
#define BSq  (Bq*Sq)
#define CHq  128
#define NCq  (Sq/CHq)
#define EPSq 1e-5f
#define PA   20
#define PAsm 132
#define PH   40

// fp32 buffers (retention path + residual stream)
__device__ float g_Q[BSq*Hq];
__device__ float g_K[BSq*Hq];
__device__ float g_V[BSq*Hq];
__device__ float g_G[BSq*Hq];
__device__ float g_Y[BSq*Hq];
__device__ float g_X[BSq*Hq];
__device__ float g_M[Bq*NHq*NCq*HDq*HDq];
__device__ float g_St[Bq*NHq*NCq*HDq*HDq];
// fp16 GEMM-input buffers
__device__ __half g_XnH[BSq*Hq];
__device__ __half g_GatedH[BSq*Hq];
__device__ __half g_HnH[BSq*Hq];
__device__ __half g_HfH[BSq*FFNq];
__device__ __half g_XH[BSq*Hq];
// fp16 transposed weights [N][K]
__device__ __half g_WQTh[Lq*NHq*HDq*Hq];
__device__ __half g_WKTh[Lq*NHq*HDq*Hq];
__device__ __half g_WVTh[Lq*NHq*HDq*Hq];
__device__ __half g_WGTh[Lq*Hq*Hq];
__device__ __half g_WOTh[Lq*Hq*Hq];
__device__ __half g_W1Th[Lq*FFNq*Hq];
__device__ __half g_W2Th[Lq*Hq*FFNq];

__device__ __forceinline__ float gamma_of(int n) {
    double lg = -3.4657359027997265 + (double)n * (-0.9241962407465937);
    return (float)(1.0 - exp(lg));
}
__device__ __forceinline__ uint32_t f2tf(float x) {
    uint32_t y;
    asm("cvt.rna.tf32.f32 %0, %1;" : "=r"(y) : "f"(x));
    return y;
}
__device__ __forceinline__ void mma_tf32(float* c, const uint32_t* a, const uint32_t* b) {
    asm volatile(
        "mma.sync.aligned.m16n8k8.row.col.f32.tf32.tf32.f32 "
        "{%0,%1,%2,%3}, {%4,%5,%6,%7}, {%8,%9}, {%0,%1,%2,%3};"
        : "+f"(c[0]), "+f"(c[1]), "+f"(c[2]), "+f"(c[3])
        : "r"(a[0]), "r"(a[1]), "r"(a[2]), "r"(a[3]), "r"(b[0]), "r"(b[1]));
}
__device__ __forceinline__ void mma_f16(float* c, const uint32_t* a, const uint32_t* b) {
    asm volatile(
        "mma.sync.aligned.m16n8k16.row.col.f32.f16.f16.f32 "
        "{%0,%1,%2,%3}, {%4,%5,%6,%7}, {%8,%9}, {%0,%1,%2,%3};"
        : "+f"(c[0]), "+f"(c[1]), "+f"(c[2]), "+f"(c[3])
        : "r"(a[0]), "r"(a[1]), "r"(a[2]), "r"(a[3]), "r"(b[0]), "r"(b[1]));
}

// ====== fp16-in fp32-acc NT GEMM: C/Ch[M,Ntile] = A[M,K] * Bt[N,K]^T =======
// A, Bt are __half row-major. C (fp32) and/or Ch (fp16) outputs, same ldc.
// act: 0 none, 1 gelu, 2 xpos Q, 3 xpos K (xpos requires bn==0, N==128).
__global__ __launch_bounds__(256, 2) void h_gemm_kernel(
    const __half* __restrict__ A, const __half* __restrict__ Bt,
    float* __restrict__ C, __half* __restrict__ Ch,
    int K, int lda, int ldb, int ldc,
    long aStride, long bStride, long cStride,
    const float* __restrict__ bias, const float* __restrict__ res, int act)
{
    __shared__ __align__(16) __half smA[2][128 * PH];
    __shared__ __align__(16) __half smB[2][128 * PH];
    int z = blockIdx.z;
    A  += z * aStride;
    Bt += z * bStride;
    if (C)  C  += z * cStride;
    if (Ch) Ch += z * cStride;
    if (res) res += z * cStride;
    int bm = blockIdx.y * 128, bn = blockIdx.x * 128;
    int tid = threadIdx.x;
    int lane = tid & 31, warp = tid >> 5;
    int gid = lane >> 2, tig = lane & 3;
    int wy = warp >> 2, wx = warp & 3;

    float acc[4][4][4];
#pragma unroll
    for (int i = 0; i < 4; i++)
#pragma unroll
        for (int j = 0; j < 4; j++)
#pragma unroll
            for (int k = 0; k < 4; k++) acc[i][j][k] = 0.f;

    int lr = tid >> 1, lkh = (tid & 1) * 16;
    uint4 ra0, ra1, rb0, rb1;

#define HLOAD(k0)                                                              \
    {                                                                          \
        const __half* ap = A + (long)(bm + lr) * lda + (k0) + lkh;             \
        ra0 = *(const uint4*)(ap);                                             \
        ra1 = *(const uint4*)(ap + 8);                                         \
        const __half* bp = Bt + (long)(bn + lr) * ldb + (k0) + lkh;            \
        rb0 = *(const uint4*)(bp);                                             \
        rb1 = *(const uint4*)(bp + 8);                                         \
    }

#define HSTORE(p)                                                              \
    {                                                                          \
        *(uint4*)&smA[p][lr * PH + lkh]     = ra0;                             \
        *(uint4*)&smA[p][lr * PH + lkh + 8] = ra1;                             \
        *(uint4*)&smB[p][lr * PH + lkh]     = rb0;                             \
        *(uint4*)&smB[p][lr * PH + lkh + 8] = rb1;                             \
    }

#define HCOMP(p)                                                               \
    _Pragma("unroll")                                                          \
    for (int ks = 0; ks < 2; ks++) {                                           \
        uint32_t af[4][4], bf[4][2];                                           \
        _Pragma("unroll")                                                      \
        for (int mi = 0; mi < 4; mi++) {                                       \
            int base = (wy * 64 + mi * 16 + gid) * PH + ks * 16 + tig * 2;     \
            af[mi][0] = *(uint32_t*)&smA[p][base];                             \
            af[mi][1] = *(uint32_t*)&smA[p][base + 8 * PH];                    \
            af[mi][2] = *(uint32_t*)&smA[p][base + 8];                         \
            af[mi][3] = *(uint32_t*)&smA[p][base + 8 * PH + 8];                \
        }                                                                      \
        _Pragma("unroll")                                                      \
        for (int ni = 0; ni < 4; ni++) {                                       \
            int nb = (wx * 32 + ni * 8 + gid) * PH + ks * 16 + tig * 2;        \
            bf[ni][0] = *(uint32_t*)&smB[p][nb];                               \
            bf[ni][1] = *(uint32_t*)&smB[p][nb + 8];                           \
        }                                                                      \
        _Pragma("unroll")                                                      \
        for (int mi = 0; mi < 4; mi++)                                         \
            _Pragma("unroll")                                                  \
            for (int ni = 0; ni < 4; ni++)                                     \
                mma_f16(acc[mi][ni], af[mi], bf[ni]);                          \
    }

    HLOAD(0)
    HSTORE(0)
    __syncthreads();
    int p = 0;
    for (int k0 = 32;; k0 += 32) {
        bool more = (k0 < K);
        if (more) HLOAD(k0)
        HCOMP(p)
        if (!more) break;
        HSTORE(p ^ 1)
        __syncthreads();
        p ^= 1;
    }

    // epilogue
#pragma unroll
    for (int mi = 0; mi < 4; mi++) {
        long r0 = bm + wy * 64 + mi * 16 + gid;
        long r1 = r0 + 8;
#pragma unroll
        for (int ni = 0; ni < 4; ni++) {
            int c0 = bn + wx * 32 + ni * 8 + tig * 2;
            float v00 = acc[mi][ni][0], v01 = acc[mi][ni][1];
            float v10 = acc[mi][ni][2], v11 = acc[mi][ni][3];
            if (bias) {
                float b0 = bias[c0], b1 = bias[c0 + 1];
                v00 += b0; v01 += b1; v10 += b0; v11 += b1;
            }
            if (act == 1) {
                v00 = 0.5f * v00 * (1.f + erff(v00 * 0.70710678118654752f));
                v01 = 0.5f * v01 * (1.f + erff(v01 * 0.70710678118654752f));
                v10 = 0.5f * v10 * (1.f + erff(v10 * 0.70710678118654752f));
                v11 = 0.5f * v11 * (1.f + erff(v11 * 0.70710678118654752f));
            } else if (act >= 2) {
                float fi = (float)(c0 >> 1);
                float lsb = log2f((fi + 51.2f) * (1.f / 179.2f));
                if (act == 3) lsb = -lsb;
                float invf = exp2f(fi * (-0.20761871093296528f));
#pragma unroll
                for (int rr = 0; rr < 2; rr++) {
                    float pp = (float)((rr ? r1 : r0) & (Sq - 1));
                    float sc = exp2f(lsb * pp * (1.f / 512.f));
                    float s_, c_;
                    sincosf(pp * invf, &s_, &c_);
                    c_ *= sc; s_ *= sc;
                    if (rr == 0) {
                        float t0 = v00 * c_ - v01 * s_;
                        v01 = v01 * c_ + v00 * s_;
                        v00 = t0;
                    } else {
                        float t0 = v10 * c_ - v11 * s_;
                        v11 = v11 * c_ + v10 * s_;
                        v10 = t0;
                    }
                }
            }
            if (res) {
                v00 += res[r0 * ldc + c0]; v01 += res[r0 * ldc + c0 + 1];
                v10 += res[r1 * ldc + c0]; v11 += res[r1 * ldc + c0 + 1];
            }
            if (C) {
                *(float2*)(C + r0 * ldc + c0) = make_float2(v00, v01);
                *(float2*)(C + r1 * ldc + c0) = make_float2(v10, v11);
            }
            if (Ch) {
                *(__half2*)(Ch + r0 * ldc + c0) = __floats2half2_rn(v00, v01);
                *(__half2*)(Ch + r1 * ldc + c0) = __floats2half2_rn(v10, v11);
            }
        }
    }
#undef HLOAD
#undef HSTORE
#undef HCOMP
}

// ------------- transpose to fp16: out[c][r] = (half)in[r][c], z-batched -----
__global__ __launch_bounds__(256) void transposeh_kernel(const float* __restrict__ in,
                                                         __half* __restrict__ out, int R, int C) {
    __shared__ float t[32][33];
    long z = blockIdx.z;
    in  += z * (long)R * C;
    out += z * (long)R * C;
    int bx = blockIdx.x * 32, by = blockIdx.y * 32;
    int tx = threadIdx.x & 31, ty = threadIdx.x >> 5;
#pragma unroll
    for (int i = 0; i < 32; i += 8)
        t[ty + i][tx] = in[(long)(by + ty + i) * C + bx + tx];
    __syncthreads();
#pragma unroll
    for (int i = 0; i < 32; i += 8)
        out[(long)(bx + ty + i) * R + by + tx] = __float2half(t[tx][ty + i]);
}

// ---------------- warp-per-row LayerNorm over H=512, fp16 out ---------------
__global__ __launch_bounds__(256) void ln_kernel(const float* __restrict__ X,
                                                 const float* __restrict__ w,
                                                 const float* __restrict__ b,
                                                 __half* __restrict__ out) {
    int warp = threadIdx.x >> 5, lane = threadIdx.x & 31;
    long row = (long)blockIdx.x * 8 + warp;
    const float* x = X + row * Hq;
    float4 v[4];
#pragma unroll
    for (int i = 0; i < 4; i++) v[i] = *(const float4*)(x + i * 128 + lane * 4);
    float s = 0.f;
#pragma unroll
    for (int i = 0; i < 4; i++) s += v[i].x + v[i].y + v[i].z + v[i].w;
#pragma unroll
    for (int o = 16; o; o >>= 1) s += __shfl_xor_sync(0xffffffffu, s, o);
    float m = s * (1.f / Hq);
    float s2 = 0.f;
#pragma unroll
    for (int i = 0; i < 4; i++) {
        v[i].x -= m; v[i].y -= m; v[i].z -= m; v[i].w -= m;
        s2 += v[i].x * v[i].x + v[i].y * v[i].y + v[i].z * v[i].z + v[i].w * v[i].w;
    }
#pragma unroll
    for (int o = 16; o; o >>= 1) s2 += __shfl_xor_sync(0xffffffffu, s2, o);
    float inv = rsqrtf(s2 * (1.f / Hq) + EPSq);
#pragma unroll
    for (int i = 0; i < 4; i++) {
        int d = i * 128 + lane * 4;
        float4 ww = *(const float4*)(w + d);
        float4 bb = *(const float4*)(b + d);
        __half2 h0 = __floats2half2_rn(v[i].x * inv * ww.x + bb.x, v[i].y * inv * ww.y + bb.y);
        __half2 h1 = __floats2half2_rn(v[i].z * inv * ww.z + bb.z, v[i].w * inv * ww.w + bb.w);
        *(__half2*)(out + row * Hq + d)     = h0;
        *(__half2*)(out + row * Hq + d + 2) = h1;
    }
}

// ---------------- retention pass A: per-chunk decayed KV (tf32 mma) --------
__global__ __launch_bounds__(256) void chunk_kv_kernel(const float* __restrict__ Kd,
                                                       const float* __restrict__ Vd,
                                                       float* __restrict__ Mout) {
    __shared__ uint32_t KT[128 * PA];
    __shared__ uint32_t VT[128 * PA];
    int bid = blockIdx.x;
    int bn = bid / NCq, c = bid % NCq;
    int b = bn >> 2, n = bn & 3;
    float lgam = logf(gamma_of(n));
    const float* Kb = Kd + ((long)(b * Sq + c * CHq)) * Hq + n * HDq;
    const float* Vb = Vd + ((long)(b * Sq + c * CHq)) * Hq + n * HDq;
    int tid = threadIdx.x;
    int lane = tid & 31, warp = tid >> 5;
    int gid = lane >> 2, tig = lane & 3;
    int wy = warp >> 2, wx = warp & 3;
    float acc[4][4][4];
#pragma unroll
    for (int i = 0; i < 4; i++)
#pragma unroll
        for (int j = 0; j < 4; j++)
#pragma unroll
            for (int k = 0; k < 4; k++) acc[i][j][k] = 0.f;
    int jj = tid >> 4, dbase = (tid & 15) * 8;
    int jjs = jj ^ (tid & 15);
    for (int j0 = 0; j0 < CHq; j0 += 16) {
        int j = j0 + jj;
        float w = expf((float)(127 - j) * lgam);
        const float* kp = Kb + (long)j * Hq + dbase;
        float4 k0 = *(const float4*)(kp), k1 = *(const float4*)(kp + 4);
        const float* vp = Vb + (long)j * Hq + dbase;
        float4 v0 = *(const float4*)(vp), v1 = *(const float4*)(vp + 4);
        __syncthreads();
        KT[(dbase + 0) * PA + jjs] = f2tf(k0.x * w);
        KT[(dbase + 1) * PA + jjs] = f2tf(k0.y * w);
        KT[(dbase + 2) * PA + jjs] = f2tf(k0.z * w);
        KT[(dbase + 3) * PA + jjs] = f2tf(k0.w * w);
        KT[(dbase + 4) * PA + jjs] = f2tf(k1.x * w);
        KT[(dbase + 5) * PA + jjs] = f2tf(k1.y * w);
        KT[(dbase + 6) * PA + jjs] = f2tf(k1.z * w);
        KT[(dbase + 7) * PA + jjs] = f2tf(k1.w * w);
        VT[(dbase + 0) * PA + jjs] = f2tf(v0.x);
        VT[(dbase + 1) * PA + jjs] = f2tf(v0.y);
        VT[(dbase + 2) * PA + jjs] = f2tf(v0.z);
        VT[(dbase + 3) * PA + jjs] = f2tf(v0.w);
        VT[(dbase + 4) * PA + jjs] = f2tf(v1.x);
        VT[(dbase + 5) * PA + jjs] = f2tf(v1.y);
        VT[(dbase + 6) * PA + jjs] = f2tf(v1.z);
        VT[(dbase + 7) * PA + jjs] = f2tf(v1.w);
        __syncthreads();
#pragma unroll
        for (int kk = 0; kk < 16; kk += 8) {
            uint32_t af[4][4], bf[4][2];
#pragma unroll
            for (int mi = 0; mi < 4; mi++) {
                int m = wy * 64 + mi * 16 + gid;
                int sw = m >> 3, sw2 = (m + 8) >> 3;
                af[mi][0] = KT[m * PA + ((kk + tig) ^ sw)];
                af[mi][1] = KT[(m + 8) * PA + ((kk + tig) ^ sw2)];
                af[mi][2] = KT[m * PA + ((kk + tig + 4) ^ sw)];
                af[mi][3] = KT[(m + 8) * PA + ((kk + tig + 4) ^ sw2)];
            }
#pragma unroll
            for (int ni = 0; ni < 4; ni++) {
                int nb = wx * 32 + ni * 8 + gid;
                int sw = nb >> 3;
                bf[ni][0] = VT[nb * PA + ((kk + tig) ^ sw)];
                bf[ni][1] = VT[nb * PA + ((kk + tig + 4) ^ sw)];
            }
#pragma unroll
            for (int mi = 0; mi < 4; mi++)
#pragma unroll
                for (int ni = 0; ni < 4; ni++)
                    mma_tf32(acc[mi][ni], af[mi], bf[ni]);
        }
    }
    float* Mo = Mout + (long)bid * (HDq * HDq);
#pragma unroll
    for (int mi = 0; mi < 4; mi++) {
        int r0 = wy * 64 + mi * 16 + gid, r1 = r0 + 8;
#pragma unroll
        for (int ni = 0; ni < 4; ni++) {
            int c0 = wx * 32 + ni * 8 + tig * 2;
            *(float2*)(Mo + r0 * HDq + c0) = make_float2(acc[mi][ni][0], acc[mi][ni][1]);
            *(float2*)(Mo + r1 * HDq + c0) = make_float2(acc[mi][ni][2], acc[mi][ni][3]);
        }
    }
}

__global__ __launch_bounds__(256) void scan_kernel(const float* __restrict__ M,
                                                   float* __restrict__ St) {
    long idx = (long)blockIdx.x * blockDim.x + threadIdx.x;
    int bn = (int)(idx >> 14);
    int n = bn & 3;
    float gamma = gamma_of(n);
    float gC = expf(128.f * logf(gamma));
    long e = idx & 16383;
    float s = 0.f;
    for (int c = 0; c < NCq; c++) {
        long off = ((long)bn * NCq + c) * 16384 + e;
        St[off] = s;
        s = s * gC + M[off];
    }
}

// ------- retention pass C: chunk output + fused group-norm + swish gate ----
__global__ __launch_bounds__(256) void chunk_out_kernel(const float* __restrict__ Qd,
                                                        const float* __restrict__ Kd,
                                                        const float* __restrict__ Vd,
                                                        const float* __restrict__ States,
                                                        const float* __restrict__ Gm,
                                                        const float* __restrict__ gnw,
                                                        const float* __restrict__ gnb,
                                                        __half* __restrict__ outG) {
    extern __shared__ uint32_t dsm[];
    uint32_t* Asm = dsm;
    uint32_t* T1  = dsm + 128 * PAsm;
    uint32_t* T2  = T1 + 128 * PA;
    int bid = blockIdx.x;
    int bn = bid / NCq, c = bid % NCq;
    int b = bn >> 2, n = bn & 3;
    float lgam = logf(gamma_of(n));
    const float* Qb = Qd + ((long)(b * Sq + c * CHq)) * Hq + n * HDq;
    const float* Kb = Kd + ((long)(b * Sq + c * CHq)) * Hq + n * HDq;
    const float* Vb = Vd + ((long)(b * Sq + c * CHq)) * Hq + n * HDq;
    const float* Sb = States + ((long)bn * NCq + c) * 16384;
    int tid = threadIdx.x;
    int lane = tid & 31, warp = tid >> 5;
    int gid = lane >> 2, tig = lane & 3;
    int wy = warp >> 2, wx = warp & 3;
    float acc[4][4][4];
#pragma unroll
    for (int i = 0; i < 4; i++)
#pragma unroll
        for (int j = 0; j < 4; j++)
#pragma unroll
            for (int k = 0; k < 4; k++) acc[i][j][k] = 0.f;
    int lr = tid >> 1, lc = (tid & 1) * 8;
    int jj = tid >> 4, dbase = (tid & 15) * 8;
    int jjs = jj ^ (tid & 15);

    // phase 1: scores = Q K^T
    for (int d0 = 0; d0 < HDq; d0 += 16) {
        const float* qp = Qb + (long)lr * Hq + d0 + lc;
        float4 q0 = *(const float4*)(qp), q1 = *(const float4*)(qp + 4);
        const float* kp = Kb + (long)lr * Hq + d0 + lc;
        float4 k0 = *(const float4*)(kp), k1 = *(const float4*)(kp + 4);
        __syncthreads();
        *(uint4*)&T1[lr * PA + lc]     = make_uint4(f2tf(q0.x), f2tf(q0.y), f2tf(q0.z), f2tf(q0.w));
        *(uint4*)&T1[lr * PA + lc + 4] = make_uint4(f2tf(q1.x), f2tf(q1.y), f2tf(q1.z), f2tf(q1.w));
        *(uint4*)&T2[lr * PA + lc]     = make_uint4(f2tf(k0.x), f2tf(k0.y), f2tf(k0.z), f2tf(k0.w));
        *(uint4*)&T2[lr * PA + lc + 4] = make_uint4(f2tf(k1.x), f2tf(k1.y), f2tf(k1.z), f2tf(k1.w));
        __syncthreads();
#pragma unroll
        for (int kk = 0; kk < 16; kk += 8) {
            uint32_t af[4][4], bf[4][2];
#pragma unroll
            for (int mi = 0; mi < 4; mi++) {
                int mb = (wy * 64 + mi * 16 + gid) * PA + kk + tig;
                af[mi][0] = T1[mb]; af[mi][1] = T1[mb + 8 * PA];
                af[mi][2] = T1[mb + 4]; af[mi][3] = T1[mb + 8 * PA + 4];
            }
#pragma unroll
            for (int ni = 0; ni < 4; ni++) {
                int nb = (wx * 32 + ni * 8 + gid) * PA + kk + tig;
                bf[ni][0] = T2[nb]; bf[ni][1] = T2[nb + 4];
            }
#pragma unroll
            for (int mi = 0; mi < 4; mi++)
#pragma unroll
                for (int ni = 0; ni < 4; ni++)
                    mma_tf32(acc[mi][ni], af[mi], bf[ni]);
        }
    }
    {
        float pj[8], pk[8];
#pragma unroll
        for (int mi = 0; mi < 4; mi++) {
            int r0 = wy * 64 + mi * 16 + gid;
            pj[mi * 2]     = expf((float)r0 * lgam);
            pj[mi * 2 + 1] = expf((float)(r0 + 8) * lgam);
        }
#pragma unroll
        for (int ni = 0; ni < 4; ni++) {
            int c0 = wx * 32 + ni * 8 + tig * 2;
            pk[ni * 2]     = expf((float)(-c0) * lgam);
            pk[ni * 2 + 1] = expf((float)(-(c0 + 1)) * lgam);
        }
        __syncthreads();
#pragma unroll
        for (int mi = 0; mi < 4; mi++) {
            int r0 = wy * 64 + mi * 16 + gid, r1 = r0 + 8;
#pragma unroll
            for (int ni = 0; ni < 4; ni++) {
                int c0 = wx * 32 + ni * 8 + tig * 2;
                float v00 = (r0 >= c0)     ? acc[mi][ni][0] * pj[mi*2]   * pk[ni*2]   : 0.f;
                float v01 = (r0 >= c0 + 1) ? acc[mi][ni][1] * pj[mi*2]   * pk[ni*2+1] : 0.f;
                float v10 = (r1 >= c0)     ? acc[mi][ni][2] * pj[mi*2+1] * pk[ni*2]   : 0.f;
                float v11 = (r1 >= c0 + 1) ? acc[mi][ni][3] * pj[mi*2+1] * pk[ni*2+1] : 0.f;
                Asm[r0 * PAsm + c0]     = f2tf(v00);
                Asm[r0 * PAsm + c0 + 1] = f2tf(v01);
                Asm[r1 * PAsm + c0]     = f2tf(v10);
                Asm[r1 * PAsm + c0 + 1] = f2tf(v11);
                acc[mi][ni][0] = acc[mi][ni][1] = acc[mi][ni][2] = acc[mi][ni][3] = 0.f;
            }
        }
    }
    __syncthreads();

    // phase 2: Y = scores * V
    for (int j0 = 0; j0 < CHq; j0 += 16) {
        const float* vp = Vb + (long)(j0 + jj) * Hq + dbase;
        float4 v0 = *(const float4*)(vp), v1 = *(const float4*)(vp + 4);
        __syncthreads();
        T2[(dbase + 0) * PA + jjs] = f2tf(v0.x);
        T2[(dbase + 1) * PA + jjs] = f2tf(v0.y);
        T2[(dbase + 2) * PA + jjs] = f2tf(v0.z);
        T2[(dbase + 3) * PA + jjs] = f2tf(v0.w);
        T2[(dbase + 4) * PA + jjs] = f2tf(v1.x);
        T2[(dbase + 5) * PA + jjs] = f2tf(v1.y);
        T2[(dbase + 6) * PA + jjs] = f2tf(v1.z);
        T2[(dbase + 7) * PA + jjs] = f2tf(v1.w);
        __syncthreads();
#pragma unroll
        for (int kk = 0; kk < 16; kk += 8) {
            uint32_t af[4][4], bf[4][2];
#pragma unroll
            for (int mi = 0; mi < 4; mi++) {
                int mb = (wy * 64 + mi * 16 + gid) * PAsm + j0 + kk + tig;
                af[mi][0] = Asm[mb]; af[mi][1] = Asm[mb + 8 * PAsm];
                af[mi][2] = Asm[mb + 4]; af[mi][3] = Asm[mb + 8 * PAsm + 4];
            }
#pragma unroll
            for (int ni = 0; ni < 4; ni++) {
                int nb = wx * 32 + ni * 8 + gid;
                int sw = nb >> 3;
                bf[ni][0] = T2[nb * PA + ((kk + tig) ^ sw)];
                bf[ni][1] = T2[nb * PA + ((kk + tig + 4) ^ sw)];
            }
#pragma unroll
            for (int mi = 0; mi < 4; mi++)
#pragma unroll
                for (int ni = 0; ni < 4; ni++)
                    mma_tf32(acc[mi][ni], af[mi], bf[ni]);
        }
    }

    // phase 3: Y += diag(gamma^{j+1}) Q * State
    {
        float wrow = expf((float)(lr + 1) * lgam);
        for (int e0 = 0; e0 < HDq; e0 += 16) {
            const float* qp = Qb + (long)lr * Hq + e0 + lc;
            float4 q0 = *(const float4*)(qp), q1 = *(const float4*)(qp + 4);
            const float* sp = Sb + (long)(e0 + jj) * HDq + dbase;
            float4 s0 = *(const float4*)(sp), s1 = *(const float4*)(sp + 4);
            __syncthreads();
            *(uint4*)&T1[lr * PA + lc]     = make_uint4(f2tf(q0.x * wrow), f2tf(q0.y * wrow), f2tf(q0.z * wrow), f2tf(q0.w * wrow));
            *(uint4*)&T1[lr * PA + lc + 4] = make_uint4(f2tf(q1.x * wrow), f2tf(q1.y * wrow), f2tf(q1.z * wrow), f2tf(q1.w * wrow));
            T2[(dbase + 0) * PA + jjs] = f2tf(s0.x);
            T2[(dbase + 1) * PA + jjs] = f2tf(s0.y);
            T2[(dbase + 2) * PA + jjs] = f2tf(s0.z);
            T2[(dbase + 3) * PA + jjs] = f2tf(s0.w);
            T2[(dbase + 4) * PA + jjs] = f2tf(s1.x);
            T2[(dbase + 5) * PA + jjs] = f2tf(s1.y);
            T2[(dbase + 6) * PA + jjs] = f2tf(s1.z);
            T2[(dbase + 7) * PA + jjs] = f2tf(s1.w);
            __syncthreads();
#pragma unroll
            for (int kk = 0; kk < 16; kk += 8) {
                uint32_t af[4][4], bf[4][2];
#pragma unroll
                for (int mi = 0; mi < 4; mi++) {
                    int mb = (wy * 64 + mi * 16 + gid) * PA + kk + tig;
                    af[mi][0] = T1[mb]; af[mi][1] = T1[mb + 8 * PA];
                    af[mi][2] = T1[mb + 4]; af[mi][3] = T1[mb + 8 * PA + 4];
                }
#pragma unroll
                for (int ni = 0; ni < 4; ni++) {
                    int nb = wx * 32 + ni * 8 + gid;
                    int sw = nb >> 3;
                    bf[ni][0] = T2[nb * PA + ((kk + tig) ^ sw)];
                    bf[ni][1] = T2[nb * PA + ((kk + tig + 4) ^ sw)];
                }
#pragma unroll
                for (int mi = 0; mi < 4; mi++)
#pragma unroll
                    for (int ni = 0; ni < 4; ni++)
                        mma_tf32(acc[mi][ni], af[mi], bf[ni]);
            }
        }
    }

    // ---- fused group-norm + swish gate (fp16 out for O-proj GEMM) ----
    float* Ysm = (float*)dsm;
#pragma unroll
    for (int mi = 0; mi < 4; mi++) {
        int r0 = wy * 64 + mi * 16 + gid, r1 = r0 + 8;
#pragma unroll
        for (int ni = 0; ni < 4; ni++) {
            int c0 = wx * 32 + ni * 8 + tig * 2;
            Ysm[r0 * PAsm + c0]     = acc[mi][ni][0];
            Ysm[r0 * PAsm + c0 + 1] = acc[mi][ni][1];
            Ysm[r1 * PAsm + c0]     = acc[mi][ni][2];
            Ysm[r1 * PAsm + c0 + 1] = acc[mi][ni][3];
        }
    }
    __syncthreads();
    const float* gnwh = gnw + n * HDq;
    const float* gnbh = gnb + n * HDq;
#pragma unroll 1
    for (int rr = 0; rr < 16; rr++) {
        int row = warp * 16 + rr;
        float y[4];
#pragma unroll
        for (int i = 0; i < 4; i++) y[i] = Ysm[row * PAsm + lane + 32 * i];
        float s = y[0] + y[1] + y[2] + y[3];
#pragma unroll
        for (int o = 16; o; o >>= 1) s += __shfl_xor_sync(0xffffffffu, s, o);
        float m = s * (1.f / HDq);
        float s2 = 0.f;
#pragma unroll
        for (int i = 0; i < 4; i++) { y[i] -= m; s2 += y[i] * y[i]; }
#pragma unroll
        for (int o = 16; o; o >>= 1) s2 += __shfl_xor_sync(0xffffffffu, s2, o);
        float inv = rsqrtf(s2 * (1.f / HDq) + EPSq);
        long srow = (long)b * Sq + c * CHq + row;
        const float* gp = Gm + srow * Hq + n * HDq;
        __half* op = outG + srow * Hq + n * HDq;
#pragma unroll
        for (int i = 0; i < 4; i++) {
            int d = lane + 32 * i;
            float g = gp[d];
            float yn = y[i] * inv * gnwh[d] + gnbh[d];
            op[d] = __float2half((g / (1.f + expf(-g))) * yn);
        }
    }
}

// ============================================================================
extern "C" void kernel_launch(void* const* d_in, const int* in_sizes, int n_in,
                              void* d_out, int out_size) {
    const float* Xin  = (const float*)d_in[0];
    const float* WQ   = (const float*)d_in[1];
    const float* WK   = (const float*)d_in[2];
    const float* WV   = (const float*)d_in[3];
    const float* WG   = (const float*)d_in[4];
    const float* WO   = (const float*)d_in[5];
    const float* gn_w = (const float*)d_in[6];
    const float* gn_b = (const float*)d_in[7];
    const float* ln1w = (const float*)d_in[8];
    const float* ln1b = (const float*)d_in[9];
    const float* ln2w = (const float*)d_in[10];
    const float* ln2b = (const float*)d_in[11];
    const float* fw1  = (const float*)d_in[12];
    const float* fb1  = (const float*)d_in[13];
    const float* fw2  = (const float*)d_in[14];
    const float* fb2  = (const float*)d_in[15];
    float* out = (float*)d_out;

    float *pQ, *pK, *pV, *pG, *pY, *pX, *pM, *pSt;
    __half *pXnH, *pGatedH, *pHnH, *pHfH, *pXH;
    __half *pWQTh, *pWKTh, *pWVTh, *pWGTh, *pWOTh, *pW1Th, *pW2Th;
    cudaGetSymbolAddress((void**)&pQ, g_Q);
    cudaGetSymbolAddress((void**)&pK, g_K);
    cudaGetSymbolAddress((void**)&pV, g_V);
    cudaGetSymbolAddress((void**)&pG, g_G);
    cudaGetSymbolAddress((void**)&pY, g_Y);
    cudaGetSymbolAddress((void**)&pX, g_X);
    cudaGetSymbolAddress((void**)&pM, g_M);
    cudaGetSymbolAddress((void**)&pSt, g_St);
    cudaGetSymbolAddress((void**)&pXnH, g_XnH);
    cudaGetSymbolAddress((void**)&pGatedH, g_GatedH);
    cudaGetSymbolAddress((void**)&pHnH, g_HnH);
    cudaGetSymbolAddress((void**)&pHfH, g_HfH);
    cudaGetSymbolAddress((void**)&pXH, g_XH);
    cudaGetSymbolAddress((void**)&pWQTh, g_WQTh);
    cudaGetSymbolAddress((void**)&pWKTh, g_WKTh);
    cudaGetSymbolAddress((void**)&pWVTh, g_WVTh);
    cudaGetSymbolAddress((void**)&pWGTh, g_WGTh);
    cudaGetSymbolAddress((void**)&pWOTh, g_WOTh);
    cudaGetSymbolAddress((void**)&pW1Th, g_W1Th);
    cudaGetSymbolAddress((void**)&pW2Th, g_W2Th);

    const int smemCO = (128 * PAsm + 2 * 128 * PA) * 4;
    cudaFuncSetAttribute(chunk_out_kernel, cudaFuncAttributeMaxDynamicSharedMemorySize, smemCO);

    // weight transposes to fp16 NT layout [N][K]
    transposeh_kernel<<<dim3(4, 16, 12), 256>>>(WQ, pWQTh, Hq, HDq);
    transposeh_kernel<<<dim3(4, 16, 12), 256>>>(WK, pWKTh, Hq, HDq);
    transposeh_kernel<<<dim3(4, 16, 12), 256>>>(WV, pWVTh, Hq, HDq);
    transposeh_kernel<<<dim3(16, 16, 3), 256>>>(WG, pWGTh, Hq, Hq);
    transposeh_kernel<<<dim3(16, 16, 3), 256>>>(WO, pWOTh, Hq, Hq);
    transposeh_kernel<<<dim3(64, 16, 3), 256>>>(fw1, pW1Th, Hq, FFNq);
    transposeh_kernel<<<dim3(16, 64, 3), 256>>>(fw2, pW2Th, FFNq, Hq);

    const float* cur = Xin;
    for (int l = 0; l < Lq; l++) {
        ln_kernel<<<BSq / 8, 256>>>(cur, ln1w + (long)l * Hq, ln1b + (long)l * Hq, pXnH);
        h_gemm_kernel<<<dim3(1, BSq / 128, NHq), 256>>>(pXnH, pWQTh + (long)l * NHq * HDq * Hq,
            pQ, nullptr, Hq, Hq, Hq, Hq, 0, (long)HDq * Hq, HDq, nullptr, nullptr, 2);
        h_gemm_kernel<<<dim3(1, BSq / 128, NHq), 256>>>(pXnH, pWKTh + (long)l * NHq * HDq * Hq,
            pK, nullptr, Hq, Hq, Hq, Hq, 0, (long)HDq * Hq, HDq, nullptr, nullptr, 3);
        h_gemm_kernel<<<dim3(1, BSq / 128, NHq), 256>>>(pXnH, pWVTh + (long)l * NHq * HDq * Hq,
            pV, nullptr, Hq, Hq, Hq, Hq, 0, (long)HDq * Hq, HDq, nullptr, nullptr, 0);
        h_gemm_kernel<<<dim3(Hq / 128, BSq / 128, 1), 256>>>(pXnH, pWGTh + (long)l * Hq * Hq,
            pG, nullptr, Hq, Hq, Hq, Hq, 0, 0, 0, nullptr, nullptr, 0);
        chunk_kv_kernel<<<Bq * NHq * NCq, 256>>>(pK, pV, pM);
        scan_kernel<<<(Bq * NHq * HDq * HDq) / 256, 256>>>(pM, pSt);
        chunk_out_kernel<<<Bq * NHq * NCq, 256, smemCO>>>(pQ, pK, pV, pSt, pG,
            gn_w + (long)l * Hq, gn_b + (long)l * Hq, pGatedH);
        h_gemm_kernel<<<dim3(Hq / 128, BSq / 128, 1), 256>>>(pGatedH, pWOTh + (long)l * Hq * Hq,
            pY, nullptr, Hq, Hq, Hq, Hq, 0, 0, 0, nullptr, cur, 0);
        ln_kernel<<<BSq / 8, 256>>>(pY, ln2w + (long)l * Hq, ln2b + (long)l * Hq, pHnH);
        h_gemm_kernel<<<dim3(FFNq / 128, BSq / 128, 1), 256>>>(pHnH, pW1Th + (long)l * FFNq * Hq,
            nullptr, pHfH, Hq, Hq, Hq, FFNq, 0, 0, 0, fb1 + (long)l * FFNq, nullptr, 1);
        float* dst = (l == Lq - 1) ? out : pX;
        __half* dstH = (l == Lq - 1) ? pXH : nullptr;
        h_gemm_kernel<<<dim3(Hq / 128, BSq / 128, 1), 256>>>(pHfH, pW2Th + (long)l * Hq * FFNq,
            dst, dstH, FFNq, FFNq, FFNq, Hq, 0, 0, 0, fb2 + (long)l * Hq, pY, 0);
        cur = dst;
    }

    long nX = (long)BSq * Hq;
    h_gemm_kernel<<<dim3(Sq / 128, Sq / 128, Bq), 256>>>(pXH, pXH, out + nX, nullptr,
        Hq, Hq, Hq, Sq,
        (long)Sq * Hq, (long)Sq * Hq, (long)Sq * Sq,
        nullptr, nullptr, 0);
}

// round 9
// speedup vs baseline: 4.2634x; 1.0944x over previous
#include <cuda_runtime.h>
#include <cuda_fp16.h>
#include <math.h>
#include <stdint.h>

#define Bq   4
#define Sq   2048
#define Hq   512
#define NHq  4
#define HDq  128
#define FFNq 2048
#define Lq   3
#define BSq  (Bq*Sq)
#define CHq  128
#define NCq  (Sq/CHq)
#define EPSq 1e-5f
#define PA   20
#define PAsm 132
#define PH   40
#define QS   2048     // QKVG row stride
#define KOFF 512
#define VOFF 1024
#define GOFF 1536

// fp32 buffers
__device__ float g_QKVG[BSq*QS];           // fused Q|K|V|G
__device__ float g_Y[BSq*Hq];
__device__ float g_X[BSq*Hq];
__device__ float g_M[Bq*NHq*NCq*HDq*HDq];
__device__ float g_St[Bq*NHq*NCq*HDq*HDq];
// fp16 GEMM-input buffers
__device__ __half g_XnH[BSq*Hq];
__device__ __half g_GatedH[BSq*Hq];
__device__ __half g_HnH[BSq*Hq];
__device__ __half g_HfH[BSq*FFNq];
__device__ __half g_XH[BSq*Hq];
// fp16 weights [N][K]
__device__ __half g_Wcat[Lq*QS*Hq];        // per layer: rows 0-511 Q, 512 K, 1024 V, 1536 G
__device__ __half g_WOTh[Lq*Hq*Hq];
__device__ __half g_W1Th[Lq*FFNq*Hq];
__device__ __half g_W2Th[Lq*Hq*FFNq];

__device__ __forceinline__ float gamma_of(int n) {
    double lg = -3.4657359027997265 + (double)n * (-0.9241962407465937);
    return (float)(1.0 - exp(lg));
}
__device__ __forceinline__ uint32_t f2tf(float x) {
    uint32_t y;
    asm("cvt.rna.tf32.f32 %0, %1;" : "=r"(y) : "f"(x));
    return y;
}
__device__ __forceinline__ uint32_t smem_u32(const void* p) {
    uint32_t a;
    asm("{ .reg .u64 t; cvta.to.shared.u64 t, %1; cvt.u32.u64 %0, t; }" : "=r"(a) : "l"(p));
    return a;
}
__device__ __forceinline__ void cp16(uint32_t saddr, const void* g) {
    asm volatile("cp.async.ca.shared.global [%0], [%1], 16;" :: "r"(saddr), "l"(g));
}
#define CP_COMMIT() asm volatile("cp.async.commit_group;" ::: "memory")
#define CP_WAIT1()  asm volatile("cp.async.wait_group 1;" ::: "memory")
__device__ __forceinline__ void mma_tf32(float* c, const uint32_t* a, const uint32_t* b) {
    asm volatile(
        "mma.sync.aligned.m16n8k8.row.col.f32.tf32.tf32.f32 "
        "{%0,%1,%2,%3}, {%4,%5,%6,%7}, {%8,%9}, {%0,%1,%2,%3};"
        : "+f"(c[0]), "+f"(c[1]), "+f"(c[2]), "+f"(c[3])
        : "r"(a[0]), "r"(a[1]), "r"(a[2]), "r"(a[3]), "r"(b[0]), "r"(b[1]));
}
__device__ __forceinline__ void mma_f16(float* c, const uint32_t* a, const uint32_t* b) {
    asm volatile(
        "mma.sync.aligned.m16n8k16.row.col.f32.f16.f16.f32 "
        "{%0,%1,%2,%3}, {%4,%5,%6,%7}, {%8,%9}, {%0,%1,%2,%3};"
        : "+f"(c[0]), "+f"(c[1]), "+f"(c[2]), "+f"(c[3])
        : "r"(a[0]), "r"(a[1]), "r"(a[2]), "r"(a[3]), "r"(b[0]), "r"(b[1]));
}

// ====== fp16 NT GEMM with cp.async 3-stage pipeline =======================
// act: 0 none, 1 gelu, 4 fused-QKVG epilogue (xpos on Q/K column regions)
#define STG 10240          // bytes per stage per matrix (128*PH*2)
#define GEMM_SMEM (6*STG)  // 61440
__global__ __launch_bounds__(256, 2) void h_gemm_kernel(
    const __half* __restrict__ A, const __half* __restrict__ Bt,
    float* __restrict__ C, __half* __restrict__ Ch,
    int K, int lda, int ldb, int ldc,
    long aStride, long bStride, long cStride,
    const float* __restrict__ bias, const float* __restrict__ res, int act)
{
    extern __shared__ char hsm[];
    const __half* hbase = (const __half*)hsm;
    uint32_t sA = smem_u32(hsm);
    int z = blockIdx.z;
    A  += z * aStride;
    Bt += z * bStride;
    if (C)  C  += z * cStride;
    if (Ch) Ch += z * cStride;
    if (res) res += z * cStride;
    int bm = blockIdx.y * 128, bn = blockIdx.x * 128;
    int tid = threadIdx.x;
    int lane = tid & 31, warp = tid >> 5;
    int gid = lane >> 2, tig = lane & 3;
    int wy = warp >> 2, wx = warp & 3;

    float acc[4][4][4];
#pragma unroll
    for (int i = 0; i < 4; i++)
#pragma unroll
        for (int j = 0; j < 4; j++)
#pragma unroll
            for (int k = 0; k < 4; k++) acc[i][j][k] = 0.f;

    int lr = tid >> 1, lkh = (tid & 1) * 16;
    uint32_t dBase = sA + (lr * PH + lkh) * 2;

#define COPY(s, k0)                                                            \
    {                                                                          \
        uint32_t d = dBase + (s) * STG;                                        \
        const __half* ap = A + (long)(bm + lr) * lda + (k0) + lkh;             \
        cp16(d, ap); cp16(d + 16, ap + 8);                                     \
        const __half* bp = Bt + (long)(bn + lr) * ldb + (k0) + lkh;            \
        cp16(d + 3 * STG, bp); cp16(d + 3 * STG + 16, bp + 8);                 \
    }

#define HCOMP(p)                                                               \
    {                                                                          \
        const __half* pAs = hbase + (p) * (STG / 2);                           \
        const __half* pBs = hbase + (3 + (p)) * (STG / 2);                     \
        _Pragma("unroll")                                                      \
        for (int ks = 0; ks < 2; ks++) {                                       \
            uint32_t af[4][4], bf[4][2];                                       \
            _Pragma("unroll")                                                  \
            for (int mi = 0; mi < 4; mi++) {                                   \
                int base = (wy * 64 + mi * 16 + gid) * PH + ks * 16 + tig * 2; \
                af[mi][0] = *(uint32_t*)&pAs[base];                            \
                af[mi][1] = *(uint32_t*)&pAs[base + 8 * PH];                   \
                af[mi][2] = *(uint32_t*)&pAs[base + 8];                        \
                af[mi][3] = *(uint32_t*)&pAs[base + 8 * PH + 8];               \
            }                                                                  \
            _Pragma("unroll")                                                  \
            for (int ni = 0; ni < 4; ni++) {                                   \
                int nb = (wx * 32 + ni * 8 + gid) * PH + ks * 16 + tig * 2;    \
                bf[ni][0] = *(uint32_t*)&pBs[nb];                              \
                bf[ni][1] = *(uint32_t*)&pBs[nb + 8];                          \
            }                                                                  \
            _Pragma("unroll")                                                  \
            for (int mi = 0; mi < 4; mi++)                                     \
                _Pragma("unroll")                                              \
                for (int ni = 0; ni < 4; ni++)                                 \
                    mma_f16(acc[mi][ni], af[mi], bf[ni]);                      \
        }                                                                      \
    }

    int nch = K / 32;
    COPY(0, 0)
    CP_COMMIT();
    if (nch > 1) COPY(1, 32)
    CP_COMMIT();
    int st = 0;
    for (int i = 0; i < nch; i++) {
        CP_WAIT1();
        __syncthreads();
        HCOMP(st)
        if (i + 2 < nch) {
            int s2 = st + 2;
            if (s2 >= 3) s2 -= 3;
            COPY(s2, (i + 2) * 32)
        }
        CP_COMMIT();
        if (++st == 3) st = 0;
    }

    // epilogue
#pragma unroll
    for (int mi = 0; mi < 4; mi++) {
        long r0 = bm + wy * 64 + mi * 16 + gid;
        long r1 = r0 + 8;
#pragma unroll
        for (int ni = 0; ni < 4; ni++) {
            int c0 = bn + wx * 32 + ni * 8 + tig * 2;
            float v00 = acc[mi][ni][0], v01 = acc[mi][ni][1];
            float v10 = acc[mi][ni][2], v11 = acc[mi][ni][3];
            if (bias) {
                float b0 = bias[c0], b1 = bias[c0 + 1];
                v00 += b0; v01 += b1; v10 += b0; v11 += b1;
            }
            if (act == 1) {
                v00 = 0.5f * v00 * (1.f + erff(v00 * 0.70710678118654752f));
                v01 = 0.5f * v01 * (1.f + erff(v01 * 0.70710678118654752f));
                v10 = 0.5f * v10 * (1.f + erff(v10 * 0.70710678118654752f));
                v11 = 0.5f * v11 * (1.f + erff(v11 * 0.70710678118654752f));
            } else if (act == 4) {
                int region = c0 >> 9;   // 0 Q, 1 K, 2 V, 3 G
                if (region < 2) {
                    float fi = (float)((c0 & 127) >> 1);
                    float lsb = log2f((fi + 51.2f) * (1.f / 179.2f));
                    if (region == 1) lsb = -lsb;
                    float invf = exp2f(fi * (-0.20761871093296528f));
#pragma unroll
                    for (int rr = 0; rr < 2; rr++) {
                        float pp = (float)((rr ? r1 : r0) & (Sq - 1));
                        float sc = exp2f(lsb * pp * (1.f / 512.f));
                        float s_, c_;
                        sincosf(pp * invf, &s_, &c_);
                        c_ *= sc; s_ *= sc;
                        if (rr == 0) {
                            float t0 = v00 * c_ - v01 * s_;
                            v01 = v01 * c_ + v00 * s_;
                            v00 = t0;
                        } else {
                            float t0 = v10 * c_ - v11 * s_;
                            v11 = v11 * c_ + v10 * s_;
                            v10 = t0;
                        }
                    }
                }
            }
            if (res) {
                v00 += res[r0 * ldc + c0]; v01 += res[r0 * ldc + c0 + 1];
                v10 += res[r1 * ldc + c0]; v11 += res[r1 * ldc + c0 + 1];
            }
            if (C) {
                *(float2*)(C + r0 * ldc + c0) = make_float2(v00, v01);
                *(float2*)(C + r1 * ldc + c0) = make_float2(v10, v11);
            }
            if (Ch) {
                *(__half2*)(Ch + r0 * ldc + c0) = __floats2half2_rn(v00, v01);
                *(__half2*)(Ch + r1 * ldc + c0) = __floats2half2_rn(v10, v11);
            }
        }
    }
#undef COPY
#undef HCOMP
}

// ---------- pack WQ/WK/WV heads into Wcat rows (transposed, fp16) ----------
__global__ __launch_bounds__(256) void packqkv_kernel(const float* __restrict__ WQ,
                                                      const float* __restrict__ WK,
                                                      const float* __restrict__ WV,
                                                      __half* __restrict__ Wcat) {
    __shared__ float t[32][33];
    int z = blockIdx.z;                 // l*4 + n
    int l = z >> 2, n = z & 3;
    long inOff = (long)z * Hq * HDq;    // [L][NH][H][HD]
    int bx = blockIdx.x * 32, by = blockIdx.y * 32;   // bx over HD (C=128), by over H (R=512)
    int tx = threadIdx.x & 31, ty = threadIdx.x >> 5;
    const float* srcs[3] = {WQ + inOff, WK + inOff, WV + inOff};
    int rowBases[3] = {n * HDq, KOFF + n * HDq, VOFF + n * HDq};
#pragma unroll 1
    for (int m = 0; m < 3; m++) {
        const float* in = srcs[m];
        __syncthreads();
#pragma unroll
        for (int i = 0; i < 32; i += 8)
            t[ty + i][tx] = in[(long)(by + ty + i) * HDq + bx + tx];
        __syncthreads();
        __half* out = Wcat + ((long)l * QS + rowBases[m] + bx) * Hq + by;
#pragma unroll
        for (int i = 0; i < 32; i += 8)
            out[(long)(ty + i) * Hq + tx] = __float2half(t[tx][ty + i]);
    }
}

// ------------- transpose to fp16 with explicit z strides --------------------
__global__ __launch_bounds__(256) void transposeh_kernel(const float* __restrict__ in,
                                                         __half* __restrict__ out, int R, int C,
                                                         long inZ, long outZ) {
    __shared__ float t[32][33];
    long z = blockIdx.z;
    in  += z * inZ;
    out += z * outZ;
    int bx = blockIdx.x * 32, by = blockIdx.y * 32;
    int tx = threadIdx.x & 31, ty = threadIdx.x >> 5;
#pragma unroll
    for (int i = 0; i < 32; i += 8)
        t[ty + i][tx] = in[(long)(by + ty + i) * C + bx + tx];
    __syncthreads();
#pragma unroll
    for (int i = 0; i < 32; i += 8)
        out[(long)(bx + ty + i) * R + by + tx] = __float2half(t[tx][ty + i]);
}

// ---------------- warp-per-row LayerNorm over H=512, fp16 out ---------------
__global__ __launch_bounds__(256) void ln_kernel(const float* __restrict__ X,
                                                 const float* __restrict__ w,
                                                 const float* __restrict__ b,
                                                 __half* __restrict__ out) {
    int warp = threadIdx.x >> 5, lane = threadIdx.x & 31;
    long row = (long)blockIdx.x * 8 + warp;
    const float* x = X + row * Hq;
    float4 v[4];
#pragma unroll
    for (int i = 0; i < 4; i++) v[i] = *(const float4*)(x + i * 128 + lane * 4);
    float s = 0.f;
#pragma unroll
    for (int i = 0; i < 4; i++) s += v[i].x + v[i].y + v[i].z + v[i].w;
#pragma unroll
    for (int o = 16; o; o >>= 1) s += __shfl_xor_sync(0xffffffffu, s, o);
    float m = s * (1.f / Hq);
    float s2 = 0.f;
#pragma unroll
    for (int i = 0; i < 4; i++) {
        v[i].x -= m; v[i].y -= m; v[i].z -= m; v[i].w -= m;
        s2 += v[i].x * v[i].x + v[i].y * v[i].y + v[i].z * v[i].z + v[i].w * v[i].w;
    }
#pragma unroll
    for (int o = 16; o; o >>= 1) s2 += __shfl_xor_sync(0xffffffffu, s2, o);
    float inv = rsqrtf(s2 * (1.f / Hq) + EPSq);
#pragma unroll
    for (int i = 0; i < 4; i++) {
        int d = i * 128 + lane * 4;
        float4 ww = *(const float4*)(w + d);
        float4 bb = *(const float4*)(b + d);
        *(__half2*)(out + row * Hq + d)     = __floats2half2_rn(v[i].x * inv * ww.x + bb.x, v[i].y * inv * ww.y + bb.y);
        *(__half2*)(out + row * Hq + d + 2) = __floats2half2_rn(v[i].z * inv * ww.z + bb.z, v[i].w * inv * ww.w + bb.w);
    }
}

// ---------------- retention pass A: per-chunk decayed KV (tf32 mma) --------
__global__ __launch_bounds__(256) void chunk_kv_kernel(const float* __restrict__ QKVG,
                                                       float* __restrict__ Mout) {
    __shared__ uint32_t KT[128 * PA];
    __shared__ uint32_t VT[128 * PA];
    int bid = blockIdx.x;
    int bn = bid / NCq, c = bid % NCq;
    int b = bn >> 2, n = bn & 3;
    float lgam = logf(gamma_of(n));
    const float* base = QKVG + ((long)(b * Sq + c * CHq)) * QS;
    const float* Kb = base + KOFF + n * HDq;
    const float* Vb = base + VOFF + n * HDq;
    int tid = threadIdx.x;
    int lane = tid & 31, warp = tid >> 5;
    int gid = lane >> 2, tig = lane & 3;
    int wy = warp >> 2, wx = warp & 3;
    float acc[4][4][4];
#pragma unroll
    for (int i = 0; i < 4; i++)
#pragma unroll
        for (int j = 0; j < 4; j++)
#pragma unroll
            for (int k = 0; k < 4; k++) acc[i][j][k] = 0.f;
    int jj = tid >> 4, dbase = (tid & 15) * 8;
    int jjs = jj ^ (tid & 15);
    for (int j0 = 0; j0 < CHq; j0 += 16) {
        int j = j0 + jj;
        float w = expf((float)(127 - j) * lgam);
        const float* kp = Kb + (long)j * QS + dbase;
        float4 k0 = *(const float4*)(kp), k1 = *(const float4*)(kp + 4);
        const float* vp = Vb + (long)j * QS + dbase;
        float4 v0 = *(const float4*)(vp), v1 = *(const float4*)(vp + 4);
        __syncthreads();
        KT[(dbase + 0) * PA + jjs] = f2tf(k0.x * w);
        KT[(dbase + 1) * PA + jjs] = f2tf(k0.y * w);
        KT[(dbase + 2) * PA + jjs] = f2tf(k0.z * w);
        KT[(dbase + 3) * PA + jjs] = f2tf(k0.w * w);
        KT[(dbase + 4) * PA + jjs] = f2tf(k1.x * w);
        KT[(dbase + 5) * PA + jjs] = f2tf(k1.y * w);
        KT[(dbase + 6) * PA + jjs] = f2tf(k1.z * w);
        KT[(dbase + 7) * PA + jjs] = f2tf(k1.w * w);
        VT[(dbase + 0) * PA + jjs] = f2tf(v0.x);
        VT[(dbase + 1) * PA + jjs] = f2tf(v0.y);
        VT[(dbase + 2) * PA + jjs] = f2tf(v0.z);
        VT[(dbase + 3) * PA + jjs] = f2tf(v0.w);
        VT[(dbase + 4) * PA + jjs] = f2tf(v1.x);
        VT[(dbase + 5) * PA + jjs] = f2tf(v1.y);
        VT[(dbase + 6) * PA + jjs] = f2tf(v1.z);
        VT[(dbase + 7) * PA + jjs] = f2tf(v1.w);
        __syncthreads();
#pragma unroll
        for (int kk = 0; kk < 16; kk += 8) {
            uint32_t af[4][4], bf[4][2];
#pragma unroll
            for (int mi = 0; mi < 4; mi++) {
                int m = wy * 64 + mi * 16 + gid;
                int sw = m >> 3, sw2 = (m + 8) >> 3;
                af[mi][0] = KT[m * PA + ((kk + tig) ^ sw)];
                af[mi][1] = KT[(m + 8) * PA + ((kk + tig) ^ sw2)];
                af[mi][2] = KT[m * PA + ((kk + tig + 4) ^ sw)];
                af[mi][3] = KT[(m + 8) * PA + ((kk + tig + 4) ^ sw2)];
            }
#pragma unroll
            for (int ni = 0; ni < 4; ni++) {
                int nb = wx * 32 + ni * 8 + gid;
                int sw = nb >> 3;
                bf[ni][0] = VT[nb * PA + ((kk + tig) ^ sw)];
                bf[ni][1] = VT[nb * PA + ((kk + tig + 4) ^ sw)];
            }
#pragma unroll
            for (int mi = 0; mi < 4; mi++)
#pragma unroll
                for (int ni = 0; ni < 4; ni++)
                    mma_tf32(acc[mi][ni], af[mi], bf[ni]);
        }
    }
    float* Mo = Mout + (long)bid * (HDq * HDq);
#pragma unroll
    for (int mi = 0; mi < 4; mi++) {
        int r0 = wy * 64 + mi * 16 + gid, r1 = r0 + 8;
#pragma unroll
        for (int ni = 0; ni < 4; ni++) {
            int c0 = wx * 32 + ni * 8 + tig * 2;
            *(float2*)(Mo + r0 * HDq + c0) = make_float2(acc[mi][ni][0], acc[mi][ni][1]);
            *(float2*)(Mo + r1 * HDq + c0) = make_float2(acc[mi][ni][2], acc[mi][ni][3]);
        }
    }
}

__global__ __launch_bounds__(256) void scan_kernel(const float* __restrict__ M,
                                                   float* __restrict__ St) {
    long idx = (long)blockIdx.x * blockDim.x + threadIdx.x;
    int bn = (int)(idx >> 14);
    int n = bn & 3;
    float gamma = gamma_of(n);
    float gC = expf(128.f * logf(gamma));
    long e = idx & 16383;
    float s = 0.f;
    for (int c = 0; c < NCq; c++) {
        long off = ((long)bn * NCq + c) * 16384 + e;
        St[off] = s;
        s = s * gC + M[off];
    }
}

// ------- retention pass C: chunk output + fused group-norm + swish gate ----
__global__ __launch_bounds__(256) void chunk_out_kernel(const float* __restrict__ QKVG,
                                                        const float* __restrict__ States,
                                                        const float* __restrict__ gnw,
                                                        const float* __restrict__ gnb,
                                                        __half* __restrict__ outG) {
    extern __shared__ uint32_t dsm[];
    uint32_t* Asm = dsm;
    uint32_t* T1  = dsm + 128 * PAsm;
    uint32_t* T2  = T1 + 128 * PA;
    int bid = blockIdx.x;
    int bn = bid / NCq, c = bid % NCq;
    int b = bn >> 2, n = bn & 3;
    float lgam = logf(gamma_of(n));
    const float* base = QKVG + ((long)(b * Sq + c * CHq)) * QS;
    const float* Qb = base + n * HDq;
    const float* Kb = base + KOFF + n * HDq;
    const float* Vb = base + VOFF + n * HDq;
    const float* Sb = States + ((long)bn * NCq + c) * 16384;
    int tid = threadIdx.x;
    int lane = tid & 31, warp = tid >> 5;
    int gid = lane >> 2, tig = lane & 3;
    int wy = warp >> 2, wx = warp & 3;
    float acc[4][4][4];
#pragma unroll
    for (int i = 0; i < 4; i++)
#pragma unroll
        for (int j = 0; j < 4; j++)
#pragma unroll
            for (int k = 0; k < 4; k++) acc[i][j][k] = 0.f;
    int lr = tid >> 1, lc = (tid & 1) * 8;
    int jj = tid >> 4, dbase = (tid & 15) * 8;
    int jjs = jj ^ (tid & 15);

    // phase 1: scores = Q K^T
    for (int d0 = 0; d0 < HDq; d0 += 16) {
        const float* qp = Qb + (long)lr * QS + d0 + lc;
        float4 q0 = *(const float4*)(qp), q1 = *(const float4*)(qp + 4);
        const float* kp = Kb + (long)lr * QS + d0 + lc;
        float4 k0 = *(const float4*)(kp), k1 = *(const float4*)(kp + 4);
        __syncthreads();
        *(uint4*)&T1[lr * PA + lc]     = make_uint4(f2tf(q0.x), f2tf(q0.y), f2tf(q0.z), f2tf(q0.w));
        *(uint4*)&T1[lr * PA + lc + 4] = make_uint4(f2tf(q1.x), f2tf(q1.y), f2tf(q1.z), f2tf(q1.w));
        *(uint4*)&T2[lr * PA + lc]     = make_uint4(f2tf(k0.x), f2tf(k0.y), f2tf(k0.z), f2tf(k0.w));
        *(uint4*)&T2[lr * PA + lc + 4] = make_uint4(f2tf(k1.x), f2tf(k1.y), f2tf(k1.z), f2tf(k1.w));
        __syncthreads();
#pragma unroll
        for (int kk = 0; kk < 16; kk += 8) {
            uint32_t af[4][4], bf[4][2];
#pragma unroll
            for (int mi = 0; mi < 4; mi++) {
                int mb = (wy * 64 + mi * 16 + gid) * PA + kk + tig;
                af[mi][0] = T1[mb]; af[mi][1] = T1[mb + 8 * PA];
                af[mi][2] = T1[mb + 4]; af[mi][3] = T1[mb + 8 * PA + 4];
            }
#pragma unroll
            for (int ni = 0; ni < 4; ni++) {
                int nb = (wx * 32 + ni * 8 + gid) * PA + kk + tig;
                bf[ni][0] = T2[nb]; bf[ni][1] = T2[nb + 4];
            }
#pragma unroll
            for (int mi = 0; mi < 4; mi++)
#pragma unroll
                for (int ni = 0; ni < 4; ni++)
                    mma_tf32(acc[mi][ni], af[mi], bf[ni]);
        }
    }
    {
        float pj[8], pk[8];
#pragma unroll
        for (int mi = 0; mi < 4; mi++) {
            int r0 = wy * 64 + mi * 16 + gid;
            pj[mi * 2]     = expf((float)r0 * lgam);
            pj[mi * 2 + 1] = expf((float)(r0 + 8) * lgam);
        }
#pragma unroll
        for (int ni = 0; ni < 4; ni++) {
            int c0 = wx * 32 + ni * 8 + tig * 2;
            pk[ni * 2]     = expf((float)(-c0) * lgam);
            pk[ni * 2 + 1] = expf((float)(-(c0 + 1)) * lgam);
        }
        __syncthreads();
#pragma unroll
        for (int mi = 0; mi < 4; mi++) {
            int r0 = wy * 64 + mi * 16 + gid, r1 = r0 + 8;
#pragma unroll
            for (int ni = 0; ni < 4; ni++) {
                int c0 = wx * 32 + ni * 8 + tig * 2;
                float v00 = (r0 >= c0)     ? acc[mi][ni][0] * pj[mi*2]   * pk[ni*2]   : 0.f;
                float v01 = (r0 >= c0 + 1) ? acc[mi][ni][1] * pj[mi*2]   * pk[ni*2+1] : 0.f;
                float v10 = (r1 >= c0)     ? acc[mi][ni][2] * pj[mi*2+1] * pk[ni*2]   : 0.f;
                float v11 = (r1 >= c0 + 1) ? acc[mi][ni][3] * pj[mi*2+1] * pk[ni*2+1] : 0.f;
                Asm[r0 * PAsm + c0]     = f2tf(v00);
                Asm[r0 * PAsm + c0 + 1] = f2tf(v01);
                Asm[r1 * PAsm + c0]     = f2tf(v10);
                Asm[r1 * PAsm + c0 + 1] = f2tf(v11);
                acc[mi][ni][0] = acc[mi][ni][1] = acc[mi][ni][2] = acc[mi][ni][3] = 0.f;
            }
        }
    }
    __syncthreads();

    // phase 2: Y = scores * V
    for (int j0 = 0; j0 < CHq; j0 += 16) {
        const float* vp = Vb + (long)(j0 + jj) * QS + dbase;
        float4 v0 = *(const float4*)(vp), v1 = *(const float4*)(vp + 4);
        __syncthreads();
        T2[(dbase + 0) * PA + jjs] = f2tf(v0.x);
        T2[(dbase + 1) * PA + jjs] = f2tf(v0.y);
        T2[(dbase + 2) * PA + jjs] = f2tf(v0.z);
        T2[(dbase + 3) * PA + jjs] = f2tf(v0.w);
        T2[(dbase + 4) * PA + jjs] = f2tf(v1.x);
        T2[(dbase + 5) * PA + jjs] = f2tf(v1.y);
        T2[(dbase + 6) * PA + jjs] = f2tf(v1.z);
        T2[(dbase + 7) * PA + jjs] = f2tf(v1.w);
        __syncthreads();
#pragma unroll
        for (int kk = 0; kk < 16; kk += 8) {
            uint32_t af[4][4], bf[4][2];
#pragma unroll
            for (int mi = 0; mi < 4; mi++) {
                int mb = (wy * 64 + mi * 16 + gid) * PAsm + j0 + kk + tig;
                af[mi][0] = Asm[mb]; af[mi][1] = Asm[mb + 8 * PAsm];
                af[mi][2] = Asm[mb + 4]; af[mi][3] = Asm[mb + 8 * PAsm + 4];
            }
#pragma unroll
            for (int ni = 0; ni < 4; ni++) {
                int nb = wx * 32 + ni * 8 + gid;
                int sw = nb >> 3;
                bf[ni][0] = T2[nb * PA + ((kk + tig) ^ sw)];
                bf[ni][1] = T2[nb * PA + ((kk + tig + 4) ^ sw)];
            }
#pragma unroll
            for (int mi = 0; mi < 4; mi++)
#pragma unroll
                for (int ni = 0; ni < 4; ni++)
                    mma_tf32(acc[mi][ni], af[mi], bf[ni]);
        }
    }

    // phase 3: Y += diag(gamma^{j+1}) Q * State
    {
        float wrow = expf((float)(lr + 1) * lgam);
        for (int e0 = 0; e0 < HDq; e0 += 16) {
            const float* qp = Qb + (long)lr * QS + e0 + lc;
            float4 q0 = *(const float4*)(qp), q1 = *(const float4*)(qp + 4);
            const float* sp = Sb + (long)(e0 + jj) * HDq + dbase;
            float4 s0 = *(const float4*)(sp), s1 = *(const float4*)(sp + 4);
            __syncthreads();
            *(uint4*)&T1[lr * PA + lc]     = make_uint4(f2tf(q0.x * wrow), f2tf(q0.y * wrow), f2tf(q0.z * wrow), f2tf(q0.w * wrow));
            *(uint4*)&T1[lr * PA + lc + 4] = make_uint4(f2tf(q1.x * wrow), f2tf(q1.y * wrow), f2tf(q1.z * wrow), f2tf(q1.w * wrow));
            T2[(dbase + 0) * PA + jjs] = f2tf(s0.x);
            T2[(dbase + 1) * PA + jjs] = f2tf(s0.y);
            T2[(dbase + 2) * PA + jjs] = f2tf(s0.z);
            T2[(dbase + 3) * PA + jjs] = f2tf(s0.w);
            T2[(dbase + 4) * PA + jjs] = f2tf(s1.x);
            T2[(dbase + 5) * PA + jjs] = f2tf(s1.y);
            T2[(dbase + 6) * PA + jjs] = f2tf(s1.z);
            T2[(dbase + 7) * PA + jjs] = f2tf(s1.w);
            __syncthreads();
#pragma unroll
            for (int kk = 0; kk < 16; kk += 8) {
                uint32_t af[4][4], bf[4][2];
#pragma unroll
                for (int mi = 0; mi < 4; mi++) {
                    int mb = (wy * 64 + mi * 16 + gid) * PA + kk + tig;
                    af[mi][0] = T1[mb]; af[mi][1] = T1[mb + 8 * PA];
                    af[mi][2] = T1[mb + 4]; af[mi][3] = T1[mb + 8 * PA + 4];
                }
#pragma unroll
                for (int ni = 0; ni < 4; ni++) {
                    int nb = wx * 32 + ni * 8 + gid;
                    int sw = nb >> 3;
                    bf[ni][0] = T2[nb * PA + ((kk + tig) ^ sw)];
                    bf[ni][1] = T2[nb * PA + ((kk + tig + 4) ^ sw)];
                }
#pragma unroll
                for (int mi = 0; mi < 4; mi++)
#pragma unroll
                    for (int ni = 0; ni < 4; ni++)
                        mma_tf32(acc[mi][ni], af[mi], bf[ni]);
            }
        }
    }

    // ---- fused group-norm + swish gate (fp16 out) ----
    float* Ysm = (float*)dsm;
#pragma unroll
    for (int mi = 0; mi < 4; mi++) {
        int r0 = wy * 64 + mi * 16 + gid, r1 = r0 + 8;
#pragma unroll
        for (int ni = 0; ni < 4; ni++) {
            int c0 = wx * 32 + ni * 8 + tig * 2;
            Ysm[r0 * PAsm + c0]     = acc[mi][ni][0];
            Ysm[r0 * PAsm + c0 + 1] = acc[mi][ni][1];
            Ysm[r1 * PAsm + c0]     = acc[mi][ni][2];
            Ysm[r1 * PAsm + c0 + 1] = acc[mi][ni][3];
        }
    }
    __syncthreads();
    const float* gnwh = gnw + n * HDq;
    const float* gnbh = gnb + n * HDq;
#pragma unroll 1
    for (int rr = 0; rr < 16; rr++) {
        int row = warp * 16 + rr;
        float y[4];
#pragma unroll
        for (int i = 0; i < 4; i++) y[i] = Ysm[row * PAsm + lane + 32 * i];
        float s = y[0] + y[1] + y[2] + y[3];
#pragma unroll
        for (int o = 16; o; o >>= 1) s += __shfl_xor_sync(0xffffffffu, s, o);
        float m = s * (1.f / HDq);
        float s2 = 0.f;
#pragma unroll
        for (int i = 0; i < 4; i++) { y[i] -= m; s2 += y[i] * y[i]; }
#pragma unroll
        for (int o = 16; o; o >>= 1) s2 += __shfl_xor_sync(0xffffffffu, s2, o);
        float inv = rsqrtf(s2 * (1.f / HDq) + EPSq);
        long srow = (long)b * Sq + c * CHq + row;
        const float* gp = QKVG + srow * QS + GOFF + n * HDq;
        __half* op = outG + srow * Hq + n * HDq;
#pragma unroll
        for (int i = 0; i < 4; i++) {
            int d = lane + 32 * i;
            float g = gp[d];
            float yn = y[i] * inv * gnwh[d] + gnbh[d];
            op[d] = __float2half((g / (1.f + expf(-g))) * yn);
        }
    }
}

// ============================================================================
extern "C" void kernel_launch(void* const* d_in, const int* in_sizes, int n_in,
                              void* d_out, int out_size) {
    const float* Xin  = (const float*)d_in[0];
    const float* WQ   = (const float*)d_in[1];
    const float* WK   = (const float*)d_in[2];
    const float* WV   = (const float*)d_in[3];
    const float* WG   = (const float*)d_in[4];
    const float* WO   = (const float*)d_in[5];
    const float* gn_w = (const float*)d_in[6];
    const float* gn_b = (const float*)d_in[7];
    const float* ln1w = (const float*)d_in[8];
    const float* ln1b = (const float*)d_in[9];
    const float* ln2w = (const float*)d_in[10];
    const float* ln2b = (const float*)d_in[11];
    const float* fw1  = (const float*)d_in[12];
    const float* fb1  = (const float*)d_in[13];
    const float* fw2  = (const float*)d_in[14];
    const float* fb2  = (const float*)d_in[15];
    float* out = (float*)d_out;

    float *pQKVG, *pY, *pX, *pM, *pSt;
    __half *pXnH, *pGatedH, *pHnH, *pHfH, *pXH;
    __half *pWcat, *pWOTh, *pW1Th, *pW2Th;
    cudaGetSymbolAddress((void**)&pQKVG, g_QKVG);
    cudaGetSymbolAddress((void**)&pY, g_Y);
    cudaGetSymbolAddress((void**)&pX, g_X);
    cudaGetSymbolAddress((void**)&pM, g_M);
    cudaGetSymbolAddress((void**)&pSt, g_St);
    cudaGetSymbolAddress((void**)&pXnH, g_XnH);
    cudaGetSymbolAddress((void**)&pGatedH, g_GatedH);
    cudaGetSymbolAddress((void**)&pHnH, g_HnH);
    cudaGetSymbolAddress((void**)&pHfH, g_HfH);
    cudaGetSymbolAddress((void**)&pXH, g_XH);
    cudaGetSymbolAddress((void**)&pWcat, g_Wcat);
    cudaGetSymbolAddress((void**)&pWOTh, g_WOTh);
    cudaGetSymbolAddress((void**)&pW1Th, g_W1Th);
    cudaGetSymbolAddress((void**)&pW2Th, g_W2Th);

    const int smemCO = (128 * PAsm + 2 * 128 * PA) * 4;
    cudaFuncSetAttribute(chunk_out_kernel, cudaFuncAttributeMaxDynamicSharedMemorySize, smemCO);
    cudaFuncSetAttribute(h_gemm_kernel, cudaFuncAttributeMaxDynamicSharedMemorySize, GEMM_SMEM);

    // pack weights (fp16, transposed)
    packqkv_kernel<<<dim3(4, 16, 12), 256>>>(WQ, WK, WV, pWcat);
    transposeh_kernel<<<dim3(16, 16, 3), 256>>>(WG, pWcat + (long)GOFF * Hq, Hq, Hq,
        (long)Hq * Hq, (long)QS * Hq);
    transposeh_kernel<<<dim3(16, 16, 3), 256>>>(WO, pWOTh, Hq, Hq, (long)Hq * Hq, (long)Hq * Hq);
    transposeh_kernel<<<dim3(64, 16, 3), 256>>>(fw1, pW1Th, Hq, FFNq, (long)Hq * FFNq, (long)Hq * FFNq);
    transposeh_kernel<<<dim3(16, 64, 3), 256>>>(fw2, pW2Th, FFNq, Hq, (long)Hq * FFNq, (long)Hq * FFNq);

    const float* cur = Xin;
    for (int l = 0; l < Lq; l++) {
        ln_kernel<<<BSq / 8, 256>>>(cur, ln1w + (long)l * Hq, ln1b + (long)l * Hq, pXnH);
        // fused Q|K|V|G projection with per-region xpos
        h_gemm_kernel<<<dim3(QS / 128, BSq / 128, 1), 256, GEMM_SMEM>>>(
            pXnH, pWcat + (long)l * QS * Hq, pQKVG, nullptr,
            Hq, Hq, Hq, QS, 0, 0, 0, nullptr, nullptr, 4);
        chunk_kv_kernel<<<Bq * NHq * NCq, 256>>>(pQKVG, pM);
        scan_kernel<<<(Bq * NHq * HDq * HDq) / 256, 256>>>(pM, pSt);
        chunk_out_kernel<<<Bq * NHq * NCq, 256, smemCO>>>(pQKVG, pSt,
            gn_w + (long)l * Hq, gn_b + (long)l * Hq, pGatedH);
        h_gemm_kernel<<<dim3(Hq / 128, BSq / 128, 1), 256, GEMM_SMEM>>>(
            pGatedH, pWOTh + (long)l * Hq * Hq, pY, nullptr,
            Hq, Hq, Hq, Hq, 0, 0, 0, nullptr, cur, 0);
        ln_kernel<<<BSq / 8, 256>>>(pY, ln2w + (long)l * Hq, ln2b + (long)l * Hq, pHnH);
        h_gemm_kernel<<<dim3(FFNq / 128, BSq / 128, 1), 256, GEMM_SMEM>>>(
            pHnH, pW1Th + (long)l * Hq * FFNq, nullptr, pHfH,
            Hq, Hq, Hq, FFNq, 0, 0, 0, fb1 + (long)l * FFNq, nullptr, 1);
        float* dst = (l == Lq - 1) ? out : pX;
        __half* dstH = (l == Lq - 1) ? pXH : nullptr;
        h_gemm_kernel<<<dim3(Hq / 128, BSq / 128, 1), 256, GEMM_SMEM>>>(
            pHfH, pW2Th + (long)l * Hq * FFNq, dst, dstH,
            FFNq, FFNq, FFNq, Hq, 0, 0, 0, fb2 + (long)l * Hq, pY, 0);
        cur = dst;
    }

    long nX = (long)BSq * Hq;
    h_gemm_kernel<<<dim3(Sq / 128, Sq / 128, Bq), 256, GEMM_SMEM>>>(
        pXH, pXH, out + nX, nullptr,
        Hq, Hq, Hq, Sq,
        (long)Sq * Hq, (long)Sq * Hq, (long)Sq * Sq,
        nullptr, nullptr, 0);
}